// round 7
// baseline (speedup 1.0000x reference)
#include <cuda_runtime.h>
#include <cuda_bf16.h>
#include <cstdint>

#define B_ 4
#define T_ 2048
#define V_ 8192
#define D_ 256
#define M_ (B_*T_)   // 8192 rows of (b,t)

// ---------------- scratch (device globals; no allocs allowed) ----------------
__device__ __nv_bfloat16 g_wh[3*(size_t)D_*V_];
__device__ __nv_bfloat16 g_wl[3*(size_t)D_*V_];
__device__ __nv_bfloat16 g_woh[(size_t)V_*D_];
__device__ __nv_bfloat16 g_wol[(size_t)V_*D_];
__device__ __nv_bfloat16 g_rh[(size_t)M_*D_];
__device__ __nv_bfloat16 g_rl[(size_t)M_*D_];

// bf16 hi/lo q,k,v (written directly by qkv GEMM epilogue)
__device__ __nv_bfloat16 g_qbh[(size_t)M_*D_];
__device__ __nv_bfloat16 g_qbl[(size_t)M_*D_];
__device__ __nv_bfloat16 g_kbh[(size_t)M_*D_];
__device__ __nv_bfloat16 g_kbl[(size_t)M_*D_];
__device__ __nv_bfloat16 g_vbh[(size_t)M_*D_];
__device__ __nv_bfloat16 g_vbl[(size_t)M_*D_];

// ---------------- helpers ----------------
__device__ __forceinline__ uint32_t smem_u32(const void* p){
    uint32_t a;
    asm("{ .reg .u64 t; cvta.to.shared.u64 t, %1; cvt.u32.u64 %0, t; }" : "=r"(a) : "l"(p));
    return a;
}
#define CP16(smem, gptr) \
    asm volatile("cp.async.cg.shared.global [%0], [%1], 16;" :: "r"(smem), "l"(gptr))
#define CP_COMMIT() asm volatile("cp.async.commit_group;" ::: "memory")
#define CP_WAIT1()  asm volatile("cp.async.wait_group 1;" ::: "memory")
#define CP_WAIT0()  asm volatile("cp.async.wait_group 0;" ::: "memory")

__device__ __forceinline__ void ldsm_x4(uint32_t (&r)[4], uint32_t addr){
    asm volatile("ldmatrix.sync.aligned.m8n8.x4.shared.b16 {%0,%1,%2,%3}, [%4];"
        : "=r"(r[0]), "=r"(r[1]), "=r"(r[2]), "=r"(r[3]) : "r"(addr));
}
__device__ __forceinline__ void ldsm_x4_t(uint32_t (&r)[4], uint32_t addr){
    asm volatile("ldmatrix.sync.aligned.m8n8.x4.trans.shared.b16 {%0,%1,%2,%3}, [%4];"
        : "=r"(r[0]), "=r"(r[1]), "=r"(r[2]), "=r"(r[3]) : "r"(addr));
}
__device__ __forceinline__ void mma16816(float (&d)[4], const uint32_t (&a)[4],
                                         uint32_t b0, uint32_t b1){
    asm volatile("mma.sync.aligned.m16n8k16.row.col.f32.bf16.bf16.f32 "
        "{%0,%1,%2,%3}, {%4,%5,%6,%7}, {%8,%9}, {%0,%1,%2,%3};"
        : "+f"(d[0]), "+f"(d[1]), "+f"(d[2]), "+f"(d[3])
        : "r"(a[0]), "r"(a[1]), "r"(a[2]), "r"(a[3]), "r"(b0), "r"(b1));
}
__device__ __forceinline__ uint32_t pack_hilo(float a, float c,
                                              __nv_bfloat16& ra, __nv_bfloat16& rc){
    ra = __float2bfloat16(a);
    rc = __float2bfloat16(c);
    return (uint32_t)*(uint16_t*)&ra | ((uint32_t)*(uint16_t*)&rc << 16);
}

// ================= conversion kernel: weights fp32 -> bf16 hi/lo =================
// One launch covers all four weights: grid = 4*512 blocks, 512 blocks each.
__global__ void __launch_bounds__(256)
cvt_w_kernel(const float* __restrict__ wq, const float* __restrict__ wk,
             const float* __restrict__ wv, const float* __restrict__ wo)
{
    const int sel = blockIdx.x >> 9;
    const int blk = blockIdx.x & 511;
    const float* in;
    __nv_bfloat16 *hi, *lo;
    switch (sel) {
        case 0: in = wq; hi = g_wh;                 lo = g_wl;                 break;
        case 1: in = wk; hi = g_wh + (size_t)D_*V_;   lo = g_wl + (size_t)D_*V_;   break;
        case 2: in = wv; hi = g_wh + 2*(size_t)D_*V_; lo = g_wl + 2*(size_t)D_*V_; break;
        default: in = wo; hi = g_woh;               lo = g_wol;                break;
    }
    const int base = blk * 4096 + threadIdx.x * 4;
    float4 v[4];
    #pragma unroll
    for (int j = 0; j < 4; ++j) v[j] = *(const float4*)(in + base + j * 1024);
    #pragma unroll
    for (int j = 0; j < 4; ++j) {
        const int i = base + j * 1024;
        float f[4] = {v[j].x, v[j].y, v[j].z, v[j].w};
        union { __nv_bfloat16 b[4]; uint2 u; } H, L;
        #pragma unroll
        for (int e = 0; e < 4; ++e) {
            __nv_bfloat16 h = __float2bfloat16(f[e]);
            float r = f[e] - __bfloat162float(h);
            H.b[e] = h;
            L.b[e] = __float2bfloat16(r);
        }
        *(uint2*)(hi + i) = H.u;
        *(uint2*)(lo + i) = L.u;
    }
}

// ================= HMMA split-precision NT GEMM =================
// C = (Ah+Al)(Bh+Bl)^T * scale via Ah*Bh + Ah*Bl + Al*Bh
// CTA tile 128x128, BK=32, 256 threads, warp tile 64x32.
// BOUT=0: fp32 output Cf;  BOUT=1: bf16 hi/lo output Ch/Cl.
// AFP32=1: A is fp32 in gmem; loaded via LDG, converted in-register, STS'd.
#define STG 40960
#define T_AH 0
#define T_AL 10240
#define T_BH 20480
#define T_BL 30720
#define LDS_B 80

template<int BOUT, int AFP32>
__device__ __forceinline__ void hmma_gemm_body(
    const float* __restrict__ Af,
    const __nv_bfloat16* __restrict__ Agh, const __nv_bfloat16* __restrict__ Agl,
    const __nv_bfloat16* __restrict__ Bgh, const __nv_bfloat16* __restrict__ Bgl,
    float* __restrict__ Cf, __nv_bfloat16* __restrict__ Ch, __nv_bfloat16* __restrict__ Cl,
    int K, int ldC, float scale, int row0, int col0)
{
    extern __shared__ __align__(128) char sm[];
    const int tid  = threadIdx.x;
    const int lane = tid & 31;
    const int wid  = tid >> 5;
    const int wm   = wid >> 2;
    const int wn   = wid & 3;
    const uint32_t sbase = smem_u32(sm);

    float acc[4][4][4];
    #pragma unroll
    for (int a = 0; a < 4; ++a)
        #pragma unroll
        for (int b = 0; b < 4; ++b)
            #pragma unroll
            for (int c = 0; c < 4; ++c) acc[a][b][c] = 0.f;

    const int lrow = tid >> 2, lseg = tid & 3;

    // B (and A when !AFP32) staged via cp.async
    auto load_stage = [&](int c, int s){
        const size_t k0 = (size_t)c * 32 + lseg * 8;
        const uint32_t sb = sbase + s * STG;
        #pragma unroll
        for (int h = 0; h < 2; ++h) {
            const int r = lrow + h * 64;
            const uint32_t soff = r * LDS_B + lseg * 16;
            if (!AFP32) {
                CP16(sb + T_AH + soff, Agh + (size_t)(row0 + r) * K + k0);
                CP16(sb + T_AL + soff, Agl + (size_t)(row0 + r) * K + k0);
            }
            CP16(sb + T_BH + soff, Bgh + (size_t)(col0 + r) * K + k0);
            CP16(sb + T_BL + soff, Bgl + (size_t)(col0 + r) * K + k0);
        }
    };

    // A fp32 path: LDG -> in-register hi/lo convert -> STS
    uint32_t ahp[8], alp[8];
    auto ldgA = [&](int c){
        #pragma unroll
        for (int q = 0; q < 4; ++q) {
            const int idx = tid + q * 256;
            const int r = idx >> 3, seg = idx & 7;
            float4 v = *(const float4*)(Af + (size_t)(row0 + r) * K + (size_t)c * 32 + seg * 4);
            __nv_bfloat16 h0, h1, h2, h3, t0, t1;
            uint32_t ph01 = pack_hilo(v.x, v.y, h0, h1);
            uint32_t ph23 = pack_hilo(v.z, v.w, h2, h3);
            float l0 = v.x - __bfloat162float(h0), l1 = v.y - __bfloat162float(h1);
            float l2 = v.z - __bfloat162float(h2), l3 = v.w - __bfloat162float(h3);
            uint32_t pl01 = pack_hilo(l0, l1, t0, t1);
            uint32_t pl23 = pack_hilo(l2, l3, t0, t1);
            ahp[q*2] = ph01; ahp[q*2+1] = ph23;
            alp[q*2] = pl01; alp[q*2+1] = pl23;
        }
    };
    auto stsA = [&](int s){
        char* base = sm + s * STG;
        #pragma unroll
        for (int q = 0; q < 4; ++q) {
            const int idx = tid + q * 256;
            const int r = idx >> 3, seg = idx & 7;
            const uint32_t off = r * LDS_B + seg * 8;
            *(uint2*)(base + T_AH + off) = make_uint2(ahp[q*2], ahp[q*2+1]);
            *(uint2*)(base + T_AL + off) = make_uint2(alp[q*2], alp[q*2+1]);
        }
    };

    const uint32_t offA = (lane & 15) * LDS_B + (lane >> 4) * 16;
    const uint32_t offB = ((lane & 7) + ((lane >> 4) & 1) * 8) * LDS_B
                        + ((lane >> 3) & 1) * 16;

    const int NC = K / 32;

    if (AFP32) { ldgA(0); stsA(0); }
    load_stage(0, 0);
    CP_COMMIT();

    for (int c = 0; c < NC; ++c) {
        const int nxt = (c + 1) & 1;
        if (c + 1 < NC) {
            if (AFP32) ldgA(c + 1);
            load_stage(c + 1, nxt);
            CP_COMMIT();
            CP_WAIT1();
        } else {
            CP_WAIT0();
        }
        __syncthreads();

        const uint32_t sb = sbase + (c & 1) * STG;
        #pragma unroll
        for (int kk = 0; kk < 2; ++kk) {
            const uint32_t kb = kk * 32;
            uint32_t ah[4][4], al[4][4], bh[2][4], bl[2][4];
            #pragma unroll
            for (int mf = 0; mf < 4; ++mf)
                ldsm_x4(ah[mf], sb + T_AH + (wm*64 + mf*16) * LDS_B + kb + offA);
            #pragma unroll
            for (int g = 0; g < 2; ++g)
                ldsm_x4(bh[g], sb + T_BH + (wn*32 + g*16) * LDS_B + kb + offB);
            #pragma unroll
            for (int mf = 0; mf < 4; ++mf)
                #pragma unroll
                for (int nf = 0; nf < 4; ++nf)
                    mma16816(acc[mf][nf], ah[mf], bh[nf>>1][(nf&1)*2], bh[nf>>1][(nf&1)*2+1]);
            #pragma unroll
            for (int g = 0; g < 2; ++g)
                ldsm_x4(bl[g], sb + T_BL + (wn*32 + g*16) * LDS_B + kb + offB);
            #pragma unroll
            for (int mf = 0; mf < 4; ++mf)
                #pragma unroll
                for (int nf = 0; nf < 4; ++nf)
                    mma16816(acc[mf][nf], ah[mf], bl[nf>>1][(nf&1)*2], bl[nf>>1][(nf&1)*2+1]);
            #pragma unroll
            for (int mf = 0; mf < 4; ++mf)
                ldsm_x4(al[mf], sb + T_AL + (wm*64 + mf*16) * LDS_B + kb + offA);
            #pragma unroll
            for (int mf = 0; mf < 4; ++mf)
                #pragma unroll
                for (int nf = 0; nf < 4; ++nf)
                    mma16816(acc[mf][nf], al[mf], bh[nf>>1][(nf&1)*2], bh[nf>>1][(nf&1)*2+1]);
        }
        if (AFP32 && c + 1 < NC) stsA(nxt);
        __syncthreads();
    }

    #pragma unroll
    for (int mf = 0; mf < 4; ++mf) {
        const int r0 = row0 + wm*64 + mf*16 + (lane >> 2);
        #pragma unroll
        for (int nf = 0; nf < 4; ++nf) {
            const int cc = col0 + wn*32 + nf*8 + (lane & 3) * 2;
            if (BOUT == 0) {
                float2 v0 = { acc[mf][nf][0] * scale, acc[mf][nf][1] * scale };
                float2 v1 = { acc[mf][nf][2] * scale, acc[mf][nf][3] * scale };
                *(float2*)(Cf + (size_t)r0 * ldC + cc)       = v0;
                *(float2*)(Cf + (size_t)(r0 + 8) * ldC + cc) = v1;
            } else {
                #pragma unroll
                for (int h = 0; h < 2; ++h) {
                    float a = acc[mf][nf][h*2], c = acc[mf][nf][h*2+1];
                    __nv_bfloat16 ha, hc;
                    uint32_t ph = pack_hilo(a, c, ha, hc);
                    float la = a - __bfloat162float(ha), lc = c - __bfloat162float(hc);
                    __nv_bfloat16 t0, t1;
                    uint32_t pl = pack_hilo(la, lc, t0, t1);
                    *(uint32_t*)(Ch + (size_t)(r0 + h*8) * ldC + cc) = ph;
                    *(uint32_t*)(Cl + (size_t)(r0 + h*8) * ldC + cc) = pl;
                }
            }
        }
    }
}

__global__ void __launch_bounds__(256, 2)
hmma_qkv_kernel(const float* __restrict__ x)
{
    const int w = blockIdx.z;
    const __nv_bfloat16* Bh = g_wh + (size_t)w * D_ * V_;
    const __nv_bfloat16* Bl = g_wl + (size_t)w * D_ * V_;
    __nv_bfloat16* Ch = (w == 0) ? g_qbh : (w == 1) ? g_kbh : g_vbh;
    __nv_bfloat16* Cl = (w == 0) ? g_qbl : (w == 1) ? g_kbl : g_vbl;
    hmma_gemm_body<1, 1>(x, nullptr, nullptr, Bh, Bl, nullptr, Ch, Cl,
                         V_, D_, 1.0f, blockIdx.y * 128, blockIdx.x * 128);
}

__global__ void __launch_bounds__(256, 2)
hmma_out_kernel(const float* __restrict__ out_scale, float* __restrict__ out)
{
    hmma_gemm_body<0, 0>(nullptr, g_rh, g_rl, g_woh, g_wol, out, nullptr, nullptr,
                         D_, V_, out_scale[0], blockIdx.y * 128, blockIdx.x * 128);
}

// ================= HMMA attention =================
#define AT_STRIDE 528
#define SW_STRIDE 144
#define SM_QH 0
#define SM_QL 33792
#define SM_KH 67584
#define SM_KL 101376
#define SM_VH 135168
#define SM_VL 168960
#define SM_SWH 202752
#define SM_SWL 211968
#define ATT_SMEM 221184

__global__ void __launch_bounds__(256, 1)
attn_hmma_kernel(const float* __restrict__ dlp)
{
    extern __shared__ __align__(128) char shm[];
    const int tid = threadIdx.x, lane = tid & 31, wid = tid >> 5;
    const int wm = wid >> 1, wn = wid & 1;
    const int ib = blockIdx.x, b = blockIdx.y;
    const uint32_t sb = smem_u32(shm);

    const float logit = dlp[0];
    const float decay = 1.f / (1.f + expf(-logit));
    const float l2d   = log2f(decay);

    const int qrow0 = b * T_ + ib * 64;

    #pragma unroll
    for (int it = 0; it < 8; ++it) {
        int idx = it * 256 + tid;
        int r = idx >> 5, s = idx & 31;
        uint32_t soff = r * AT_STRIDE + s * 16;
        size_t gb = ((size_t)(qrow0 + r) * D_) * 2 + s * 16;
        CP16(sb + SM_QH + soff, (const char*)g_qbh + gb);
        CP16(sb + SM_QL + soff, (const char*)g_qbl + gb);
    }
    CP_COMMIT();

    float oacc[8][2][4];
    #pragma unroll
    for (int a = 0; a < 8; ++a)
        #pragma unroll
        for (int g = 0; g < 2; ++g)
            #pragma unroll
            for (int e = 0; e < 4; ++e) oacc[a][g][e] = 0.f;

    const uint32_t offA  = (lane & 15) * AT_STRIDE + (lane >> 4) * 16;
    const uint32_t offB  = ((lane & 7) + ((lane >> 4) & 1) * 8) * AT_STRIDE
                         + ((lane >> 3) & 1) * 16;
    const uint32_t offAs = (lane & 15) * SW_STRIDE + (lane >> 4) * 16;
    const uint32_t offV  = ((lane & 7) + ((lane >> 3) & 1) * 8) * AT_STRIDE
                         + (lane >> 4) * 16;

    const int rl0 = wm * 16 + (lane >> 2);
    const float er0 = exp2f(-l2d * (float)rl0);
    const float er1 = er0 * exp2f(-l2d * 8.f);

    CP_WAIT0();
    __syncthreads();

    for (int jb = ib; jb < T_/64; ++jb) {
        int emin = (jb - ib) * 64 - 64;
        if (emin > 0 && l2d * (float)emin < -35.f) break;
        const int krow0 = b * T_ + jb * 64;

        #pragma unroll
        for (int it = 0; it < 8; ++it) {
            int idx = it * 256 + tid;
            int r = idx >> 5, s = idx & 31;
            uint32_t soff = r * AT_STRIDE + s * 16;
            size_t gb = ((size_t)(krow0 + r) * D_) * 2 + s * 16;
            CP16(sb + SM_KH + soff, (const char*)g_kbh + gb);
            CP16(sb + SM_KL + soff, (const char*)g_kbl + gb);
        }
        CP_COMMIT();
        #pragma unroll
        for (int it = 0; it < 8; ++it) {
            int idx = it * 256 + tid;
            int r = idx >> 5, s = idx & 31;
            uint32_t soff = r * AT_STRIDE + s * 16;
            size_t gb = ((size_t)(krow0 + r) * D_) * 2 + s * 16;
            CP16(sb + SM_VH + soff, (const char*)g_vbh + gb);
            CP16(sb + SM_VL + soff, (const char*)g_vbl + gb);
        }
        CP_COMMIT();
        CP_WAIT1();
        __syncthreads();

        float sacc[4][4];
        #pragma unroll
        for (int nf = 0; nf < 4; ++nf)
            #pragma unroll
            for (int e = 0; e < 4; ++e) sacc[nf][e] = 0.f;

        #pragma unroll 4
        for (int kf = 0; kf < 16; ++kf) {
            const uint32_t kb = kf * 32;
            uint32_t qh[4], ql[4], kh[2][4], kl[2][4];
            ldsm_x4(qh, sb + SM_QH + (wm*16) * AT_STRIDE + kb + offA);
            ldsm_x4(ql, sb + SM_QL + (wm*16) * AT_STRIDE + kb + offA);
            ldsm_x4(kh[0], sb + SM_KH + (wn*32)      * AT_STRIDE + kb + offB);
            ldsm_x4(kh[1], sb + SM_KH + (wn*32 + 16) * AT_STRIDE + kb + offB);
            ldsm_x4(kl[0], sb + SM_KL + (wn*32)      * AT_STRIDE + kb + offB);
            ldsm_x4(kl[1], sb + SM_KL + (wn*32 + 16) * AT_STRIDE + kb + offB);
            #pragma unroll
            for (int nf = 0; nf < 4; ++nf) {
                mma16816(sacc[nf], qh, kh[nf>>1][(nf&1)*2], kh[nf>>1][(nf&1)*2+1]);
                mma16816(sacc[nf], qh, kl[nf>>1][(nf&1)*2], kl[nf>>1][(nf&1)*2+1]);
                mma16816(sacc[nf], ql, kh[nf>>1][(nf&1)*2], kh[nf>>1][(nf&1)*2+1]);
            }
        }

        const float wbase = exp2f(l2d * (float)((jb - ib) * 64 - 1));
        const bool diag = (jb == ib);
        #pragma unroll
        for (int nf = 0; nf < 4; ++nf) {
            const int cl = wn*32 + nf*8 + (lane & 3)*2;
            float ec0 = exp2f(l2d * (float)cl);
            float ec1 = ec0 * decay;
            float w00 = wbase*ec0*er0, w01 = wbase*ec1*er0;
            float w10 = wbase*ec0*er1, w11 = wbase*ec1*er1;
            if (diag) {
                if (cl     <= rl0)     w00 = 0.f;
                if (cl + 1 <= rl0)     w01 = 0.f;
                if (cl     <= rl0 + 8) w10 = 0.f;
                if (cl + 1 <= rl0 + 8) w11 = 0.f;
            }
            float v00 = sacc[nf][0]*w00, v01 = sacc[nf][1]*w01;
            float v10 = sacc[nf][2]*w10, v11 = sacc[nf][3]*w11;

            #pragma unroll
            for (int h = 0; h < 2; ++h) {
                float a = h ? v10 : v00, c = h ? v11 : v01;
                __nv_bfloat16 ha, hc;
                uint32_t ph = pack_hilo(a, c, ha, hc);
                float ra = a - __bfloat162float(ha), rc = c - __bfloat162float(hc);
                __nv_bfloat16 t0, t1;
                uint32_t pl = pack_hilo(ra, rc, t0, t1);
                uint32_t off = (rl0 + h*8) * SW_STRIDE + cl * 2;
                *(uint32_t*)(shm + SM_SWH + off) = ph;
                *(uint32_t*)(shm + SM_SWL + off) = pl;
            }
        }

        CP_WAIT0();
        __syncthreads();

        uint32_t sh4[4][4], sl4[4][4];
        #pragma unroll
        for (int kf = 0; kf < 4; ++kf) {
            ldsm_x4(sh4[kf], sb + SM_SWH + (wm*16) * SW_STRIDE + kf*32 + offAs);
            ldsm_x4(sl4[kf], sb + SM_SWL + (wm*16) * SW_STRIDE + kf*32 + offAs);
        }
        #pragma unroll
        for (int nb = 0; nb < 8; ++nb) {
            const uint32_t d0b = (uint32_t)(wn*128 + nb*16) * 2;
            #pragma unroll
            for (int kf = 0; kf < 4; ++kf) {
                uint32_t vh[4], vl[4];
                const uint32_t va = sb + (kf*16) * AT_STRIDE + d0b + offV;
                ldsm_x4_t(vh, va + SM_VH);
                ldsm_x4_t(vl, va + SM_VL);
                mma16816(oacc[nb][0], sh4[kf], vh[0], vh[1]);
                mma16816(oacc[nb][1], sh4[kf], vh[2], vh[3]);
                mma16816(oacc[nb][0], sh4[kf], vl[0], vl[1]);
                mma16816(oacc[nb][1], sh4[kf], vl[2], vl[3]);
                mma16816(oacc[nb][0], sl4[kf], vh[0], vh[1]);
                mma16816(oacc[nb][1], sl4[kf], vh[2], vh[3]);
            }
        }
        __syncthreads();
    }

    // ---- fused epilogue: write r directly as bf16 hi/lo ----
    const size_t rrow = (size_t)(qrow0 + wm*16 + (lane >> 2)) * D_;
    #pragma unroll
    for (int nb = 0; nb < 8; ++nb) {
        #pragma unroll
        for (int g = 0; g < 2; ++g) {
            const int c = wn*128 + nb*16 + g*8 + (lane & 3) * 2;
            #pragma unroll
            for (int h = 0; h < 2; ++h) {
                float a = oacc[nb][g][h*2], cc = oacc[nb][g][h*2+1];
                __nv_bfloat16 ha, hc;
                uint32_t ph = pack_hilo(a, cc, ha, hc);
                float la = a - __bfloat162float(ha), lc = cc - __bfloat162float(hc);
                __nv_bfloat16 t0, t1;
                uint32_t pl = pack_hilo(la, lc, t0, t1);
                *(uint32_t*)(g_rh + rrow + (size_t)h * 8 * D_ + c) = ph;
                *(uint32_t*)(g_rl + rrow + (size_t)h * 8 * D_ + c) = pl;
            }
        }
    }
}

// ================= launch =================
#define DSMEM_BYTES (2*STG)

extern "C" void kernel_launch(void* const* d_in, const int* in_sizes, int n_in,
                              void* d_out, int out_size)
{
    const float* x  = (const float*)d_in[0];
    const float* wq = (const float*)d_in[1];
    const float* wk = (const float*)d_in[2];
    const float* wv = (const float*)d_in[3];
    const float* wo = (const float*)d_in[4];
    const float* dl = (const float*)d_in[5];
    const float* os = (const float*)d_in[6];
    float* out = (float*)d_out;

    cudaFuncSetAttribute(hmma_qkv_kernel, cudaFuncAttributeMaxDynamicSharedMemorySize, DSMEM_BYTES);
    cudaFuncSetAttribute(hmma_out_kernel, cudaFuncAttributeMaxDynamicSharedMemorySize, DSMEM_BYTES);
    cudaFuncSetAttribute(attn_hmma_kernel, cudaFuncAttributeMaxDynamicSharedMemorySize, ATT_SMEM);

    cvt_w_kernel<<<4*512, 256>>>(wq, wk, wv, wo);

    hmma_qkv_kernel<<<dim3(2, 64, 3), 256, DSMEM_BYTES>>>(x);

    attn_hmma_kernel<<<dim3(T_/64, B_), 256, ATT_SMEM>>>(dl);

    hmma_out_kernel<<<dim3(64, 64), 256, DSMEM_BYTES>>>(os, out);
}

// round 8
// speedup vs baseline: 1.1832x; 1.1832x over previous
#include <cuda_runtime.h>
#include <cuda_bf16.h>
#include <cstdint>

#define B_ 4
#define T_ 2048
#define V_ 8192
#define D_ 256
#define M_ (B_*T_)   // 8192 rows of (b,t)

// ---------------- scratch (device globals; no allocs allowed) ----------------
__device__ __nv_bfloat16 g_xh[(size_t)M_*V_];
__device__ __nv_bfloat16 g_xl[(size_t)M_*V_];
__device__ __nv_bfloat16 g_wh[3*(size_t)D_*V_];
__device__ __nv_bfloat16 g_wl[3*(size_t)D_*V_];
__device__ __nv_bfloat16 g_woh[(size_t)V_*D_];
__device__ __nv_bfloat16 g_wol[(size_t)V_*D_];
__device__ __nv_bfloat16 g_rh[(size_t)M_*D_];
__device__ __nv_bfloat16 g_rl[(size_t)M_*D_];

// split-K fp32 partials for qkv: 6 slabs of M_*D_ (z = w*2 + khalf)
__device__ float g_part[6*(size_t)M_*D_];

// bf16 hi/lo q,k,v (written by reduce kernel)
__device__ __nv_bfloat16 g_qbh[(size_t)M_*D_];
__device__ __nv_bfloat16 g_qbl[(size_t)M_*D_];
__device__ __nv_bfloat16 g_kbh[(size_t)M_*D_];
__device__ __nv_bfloat16 g_kbl[(size_t)M_*D_];
__device__ __nv_bfloat16 g_vbh[(size_t)M_*D_];
__device__ __nv_bfloat16 g_vbl[(size_t)M_*D_];

// ---------------- helpers ----------------
__device__ __forceinline__ uint32_t smem_u32(const void* p){
    uint32_t a;
    asm("{ .reg .u64 t; cvta.to.shared.u64 t, %1; cvt.u32.u64 %0, t; }" : "=r"(a) : "l"(p));
    return a;
}
#define CP16(smem, gptr) \
    asm volatile("cp.async.cg.shared.global [%0], [%1], 16;" :: "r"(smem), "l"(gptr))
#define CP_COMMIT() asm volatile("cp.async.commit_group;" ::: "memory")
#define CP_WAIT1()  asm volatile("cp.async.wait_group 1;" ::: "memory")
#define CP_WAIT0()  asm volatile("cp.async.wait_group 0;" ::: "memory")

__device__ __forceinline__ void ldsm_x4(uint32_t (&r)[4], uint32_t addr){
    asm volatile("ldmatrix.sync.aligned.m8n8.x4.shared.b16 {%0,%1,%2,%3}, [%4];"
        : "=r"(r[0]), "=r"(r[1]), "=r"(r[2]), "=r"(r[3]) : "r"(addr));
}
__device__ __forceinline__ void ldsm_x4_t(uint32_t (&r)[4], uint32_t addr){
    asm volatile("ldmatrix.sync.aligned.m8n8.x4.trans.shared.b16 {%0,%1,%2,%3}, [%4];"
        : "=r"(r[0]), "=r"(r[1]), "=r"(r[2]), "=r"(r[3]) : "r"(addr));
}
__device__ __forceinline__ void mma16816(float (&d)[4], const uint32_t (&a)[4],
                                         uint32_t b0, uint32_t b1){
    asm volatile("mma.sync.aligned.m16n8k16.row.col.f32.bf16.bf16.f32 "
        "{%0,%1,%2,%3}, {%4,%5,%6,%7}, {%8,%9}, {%0,%1,%2,%3};"
        : "+f"(d[0]), "+f"(d[1]), "+f"(d[2]), "+f"(d[3])
        : "r"(a[0]), "r"(a[1]), "r"(a[2]), "r"(a[3]), "r"(b0), "r"(b1));
}
__device__ __forceinline__ uint32_t pack_hilo(float a, float c,
                                              __nv_bfloat16& ra, __nv_bfloat16& rc){
    ra = __float2bfloat16(a);
    rc = __float2bfloat16(c);
    return (uint32_t)*(uint16_t*)&ra | ((uint32_t)*(uint16_t*)&rc << 16);
}

// ================= conversion kernels: fp32 -> bf16 hi/lo =================
__device__ __forceinline__ void cvt_body(const float* __restrict__ in,
                                         __nv_bfloat16* hi, __nv_bfloat16* lo, int blk)
{
    const size_t base = (size_t)blk * 4096 + threadIdx.x * 4;
    float4 v[4];
    #pragma unroll
    for (int j = 0; j < 4; ++j) v[j] = *(const float4*)(in + base + j * 1024);
    #pragma unroll
    for (int j = 0; j < 4; ++j) {
        const size_t i = base + j * 1024;
        float f[4] = {v[j].x, v[j].y, v[j].z, v[j].w};
        union { __nv_bfloat16 b[4]; uint2 u; } H, L;
        #pragma unroll
        for (int e = 0; e < 4; ++e) {
            __nv_bfloat16 h = __float2bfloat16(f[e]);
            float r = f[e] - __bfloat162float(h);
            H.b[e] = h;
            L.b[e] = __float2bfloat16(r);
        }
        *(uint2*)(hi + i) = H.u;
        *(uint2*)(lo + i) = L.u;
    }
}

__global__ void __launch_bounds__(256)
cvt_x_kernel(const float* __restrict__ x)
{
    cvt_body(x, g_xh, g_xl, blockIdx.x);
}

__global__ void __launch_bounds__(256)
cvt_w_kernel(const float* __restrict__ wq, const float* __restrict__ wk,
             const float* __restrict__ wv, const float* __restrict__ wo)
{
    const int sel = blockIdx.x >> 9;
    const int blk = blockIdx.x & 511;
    const float* in;
    __nv_bfloat16 *hi, *lo;
    switch (sel) {
        case 0: in = wq; hi = g_wh;                 lo = g_wl;                 break;
        case 1: in = wk; hi = g_wh + (size_t)D_*V_;   lo = g_wl + (size_t)D_*V_;   break;
        case 2: in = wv; hi = g_wh + 2*(size_t)D_*V_; lo = g_wl + 2*(size_t)D_*V_; break;
        default: in = wo; hi = g_woh;               lo = g_wol;                break;
    }
    cvt_body(in, hi, lo, blk);
}

// ================= split-K reduce: partials -> bf16 hi/lo q/k/v =================
__global__ void __launch_bounds__(256)
reduce_qkv_kernel()
{
    const int w   = blockIdx.x >> 11;       // 2048 blocks per gemm
    const int blk = blockIdx.x & 2047;
    const size_t base = (size_t)blk * 1024 + threadIdx.x * 4;
    const float* p0 = g_part + (size_t)(2*w)   * ((size_t)M_*D_);
    const float* p1 = g_part + (size_t)(2*w+1) * ((size_t)M_*D_);
    __nv_bfloat16* hi = (w==0) ? g_qbh : (w==1) ? g_kbh : g_vbh;
    __nv_bfloat16* lo = (w==0) ? g_qbl : (w==1) ? g_kbl : g_vbl;
    float4 a = *(const float4*)(p0 + base);
    float4 b = *(const float4*)(p1 + base);
    float f[4] = {a.x+b.x, a.y+b.y, a.z+b.z, a.w+b.w};
    union { __nv_bfloat16 b[4]; uint2 u; } H, L;
    #pragma unroll
    for (int e = 0; e < 4; ++e) {
        __nv_bfloat16 h = __float2bfloat16(f[e]);
        float r = f[e] - __bfloat162float(h);
        H.b[e] = h;
        L.b[e] = __float2bfloat16(r);
    }
    *(uint2*)(hi + base) = H.u;
    *(uint2*)(lo + base) = L.u;
}

// ================= HMMA split-precision NT GEMM =================
// C = (Ah+Al)(Bh+Bl)^T * scale via Ah*Bh + Ah*Bl + Al*Bh
// CTA tile 128x128, BK=32, 256 threads, warp tile 64x32.
// K = loop extent; ldAB = row stride of A/B (>= K for split-K slices).
#define STG 40960
#define T_AH 0
#define T_AL 10240
#define T_BH 20480
#define T_BL 30720
#define LDS_B 80

__device__ __forceinline__ void hmma_gemm_body(
    const __nv_bfloat16* __restrict__ Agh, const __nv_bfloat16* __restrict__ Agl,
    const __nv_bfloat16* __restrict__ Bgh, const __nv_bfloat16* __restrict__ Bgl,
    float* __restrict__ Cf,
    int K, int ldAB, int ldC, float scale, int row0, int col0)
{
    extern __shared__ __align__(128) char sm[];
    const int tid  = threadIdx.x;
    const int lane = tid & 31;
    const int wid  = tid >> 5;
    const int wm   = wid >> 2;
    const int wn   = wid & 3;
    const uint32_t sbase = smem_u32(sm);

    float acc[4][4][4];
    #pragma unroll
    for (int a = 0; a < 4; ++a)
        #pragma unroll
        for (int b = 0; b < 4; ++b)
            #pragma unroll
            for (int c = 0; c < 4; ++c) acc[a][b][c] = 0.f;

    const int lrow = tid >> 2, lseg = tid & 3;

    auto load_stage = [&](int c, int s){
        const size_t k0 = (size_t)c * 32 + lseg * 8;
        const uint32_t sb = sbase + s * STG;
        #pragma unroll
        for (int h = 0; h < 2; ++h) {
            const int r = lrow + h * 64;
            const uint32_t soff = r * LDS_B + lseg * 16;
            CP16(sb + T_AH + soff, Agh + (size_t)(row0 + r) * ldAB + k0);
            CP16(sb + T_AL + soff, Agl + (size_t)(row0 + r) * ldAB + k0);
            CP16(sb + T_BH + soff, Bgh + (size_t)(col0 + r) * ldAB + k0);
            CP16(sb + T_BL + soff, Bgl + (size_t)(col0 + r) * ldAB + k0);
        }
    };

    const uint32_t offA = (lane & 15) * LDS_B + (lane >> 4) * 16;
    const uint32_t offB = ((lane & 7) + ((lane >> 4) & 1) * 8) * LDS_B
                        + ((lane >> 3) & 1) * 16;

    const int NC = K / 32;

    load_stage(0, 0);
    CP_COMMIT();

    for (int c = 0; c < NC; ++c) {
        if (c + 1 < NC) { load_stage(c + 1, (c + 1) & 1); CP_COMMIT(); CP_WAIT1(); }
        else            { CP_WAIT0(); }
        __syncthreads();

        const uint32_t sb = sbase + (c & 1) * STG;
        #pragma unroll
        for (int kk = 0; kk < 2; ++kk) {
            const uint32_t kb = kk * 32;
            uint32_t ah[4][4], al[4][4], bh[2][4], bl[2][4];
            #pragma unroll
            for (int mf = 0; mf < 4; ++mf)
                ldsm_x4(ah[mf], sb + T_AH + (wm*64 + mf*16) * LDS_B + kb + offA);
            #pragma unroll
            for (int g = 0; g < 2; ++g)
                ldsm_x4(bh[g], sb + T_BH + (wn*32 + g*16) * LDS_B + kb + offB);
            #pragma unroll
            for (int mf = 0; mf < 4; ++mf)
                #pragma unroll
                for (int nf = 0; nf < 4; ++nf)
                    mma16816(acc[mf][nf], ah[mf], bh[nf>>1][(nf&1)*2], bh[nf>>1][(nf&1)*2+1]);
            #pragma unroll
            for (int g = 0; g < 2; ++g)
                ldsm_x4(bl[g], sb + T_BL + (wn*32 + g*16) * LDS_B + kb + offB);
            #pragma unroll
            for (int mf = 0; mf < 4; ++mf)
                #pragma unroll
                for (int nf = 0; nf < 4; ++nf)
                    mma16816(acc[mf][nf], ah[mf], bl[nf>>1][(nf&1)*2], bl[nf>>1][(nf&1)*2+1]);
            #pragma unroll
            for (int mf = 0; mf < 4; ++mf)
                ldsm_x4(al[mf], sb + T_AL + (wm*64 + mf*16) * LDS_B + kb + offA);
            #pragma unroll
            for (int mf = 0; mf < 4; ++mf)
                #pragma unroll
                for (int nf = 0; nf < 4; ++nf)
                    mma16816(acc[mf][nf], al[mf], bh[nf>>1][(nf&1)*2], bh[nf>>1][(nf&1)*2+1]);
        }
        __syncthreads();
    }

    #pragma unroll
    for (int mf = 0; mf < 4; ++mf) {
        const int r0 = row0 + wm*64 + mf*16 + (lane >> 2);
        #pragma unroll
        for (int nf = 0; nf < 4; ++nf) {
            const int cc = col0 + wn*32 + nf*8 + (lane & 3) * 2;
            float2 v0 = { acc[mf][nf][0] * scale, acc[mf][nf][1] * scale };
            float2 v1 = { acc[mf][nf][2] * scale, acc[mf][nf][3] * scale };
            *(float2*)(Cf + (size_t)r0 * ldC + cc)       = v0;
            *(float2*)(Cf + (size_t)(r0 + 8) * ldC + cc) = v1;
        }
    }
}

// ---- QKV split-K: grid (2 Ntiles, 64 Mtiles, 6 = weight*2 + khalf) ----
__global__ void __launch_bounds__(256, 2)
hmma_qkv_kernel()
{
    const int z = blockIdx.z;
    const int w = z >> 1, kh = z & 1;
    const size_t koff = (size_t)kh * 4096;
    const __nv_bfloat16* Bh = g_wh + (size_t)w * D_ * V_ + koff;
    const __nv_bfloat16* Bl = g_wl + (size_t)w * D_ * V_ + koff;
    float* Cf = g_part + (size_t)z * ((size_t)M_*D_);
    hmma_gemm_body(g_xh + koff, g_xl + koff, Bh, Bl, Cf,
                   4096, V_, D_, 1.0f, blockIdx.y * 128, blockIdx.x * 128);
}

// ---- OUT: grid (64 Ntiles, 64 Mtiles) ----
__global__ void __launch_bounds__(256, 2)
hmma_out_kernel(const float* __restrict__ out_scale, float* __restrict__ out)
{
    hmma_gemm_body(g_rh, g_rl, g_woh, g_wol, out,
                   D_, D_, V_, out_scale[0], blockIdx.y * 128, blockIdx.x * 128);
}

// ================= HMMA attention =================
#define AT_STRIDE 528
#define SW_STRIDE 144
#define SM_QH 0
#define SM_QL 33792
#define SM_KH 67584
#define SM_KL 101376
#define SM_VH 135168
#define SM_VL 168960
#define SM_SWH 202752
#define SM_SWL 211968
#define ATT_SMEM 221184

__global__ void __launch_bounds__(256, 1)
attn_hmma_kernel(const float* __restrict__ dlp)
{
    extern __shared__ __align__(128) char shm[];
    const int tid = threadIdx.x, lane = tid & 31, wid = tid >> 5;
    const int wm = wid >> 1, wn = wid & 1;
    const int ib = blockIdx.x, b = blockIdx.y;
    const uint32_t sb = smem_u32(shm);

    const float logit = dlp[0];
    const float decay = 1.f / (1.f + expf(-logit));
    const float l2d   = log2f(decay);

    const int qrow0 = b * T_ + ib * 64;

    #pragma unroll
    for (int it = 0; it < 8; ++it) {
        int idx = it * 256 + tid;
        int r = idx >> 5, s = idx & 31;
        uint32_t soff = r * AT_STRIDE + s * 16;
        size_t gb = ((size_t)(qrow0 + r) * D_) * 2 + s * 16;
        CP16(sb + SM_QH + soff, (const char*)g_qbh + gb);
        CP16(sb + SM_QL + soff, (const char*)g_qbl + gb);
    }
    CP_COMMIT();

    float oacc[8][2][4];
    #pragma unroll
    for (int a = 0; a < 8; ++a)
        #pragma unroll
        for (int g = 0; g < 2; ++g)
            #pragma unroll
            for (int e = 0; e < 4; ++e) oacc[a][g][e] = 0.f;

    const uint32_t offA  = (lane & 15) * AT_STRIDE + (lane >> 4) * 16;
    const uint32_t offB  = ((lane & 7) + ((lane >> 4) & 1) * 8) * AT_STRIDE
                         + ((lane >> 3) & 1) * 16;
    const uint32_t offAs = (lane & 15) * SW_STRIDE + (lane >> 4) * 16;
    const uint32_t offV  = ((lane & 7) + ((lane >> 3) & 1) * 8) * AT_STRIDE
                         + (lane >> 4) * 16;

    const int rl0 = wm * 16 + (lane >> 2);
    const float er0 = exp2f(-l2d * (float)rl0);
    const float er1 = er0 * exp2f(-l2d * 8.f);

    CP_WAIT0();
    __syncthreads();

    for (int jb = ib; jb < T_/64; ++jb) {
        int emin = (jb - ib) * 64 - 64;
        if (emin > 0 && l2d * (float)emin < -35.f) break;
        const int krow0 = b * T_ + jb * 64;

        #pragma unroll
        for (int it = 0; it < 8; ++it) {
            int idx = it * 256 + tid;
            int r = idx >> 5, s = idx & 31;
            uint32_t soff = r * AT_STRIDE + s * 16;
            size_t gb = ((size_t)(krow0 + r) * D_) * 2 + s * 16;
            CP16(sb + SM_KH + soff, (const char*)g_kbh + gb);
            CP16(sb + SM_KL + soff, (const char*)g_kbl + gb);
        }
        CP_COMMIT();
        #pragma unroll
        for (int it = 0; it < 8; ++it) {
            int idx = it * 256 + tid;
            int r = idx >> 5, s = idx & 31;
            uint32_t soff = r * AT_STRIDE + s * 16;
            size_t gb = ((size_t)(krow0 + r) * D_) * 2 + s * 16;
            CP16(sb + SM_VH + soff, (const char*)g_vbh + gb);
            CP16(sb + SM_VL + soff, (const char*)g_vbl + gb);
        }
        CP_COMMIT();
        CP_WAIT1();
        __syncthreads();

        float sacc[4][4];
        #pragma unroll
        for (int nf = 0; nf < 4; ++nf)
            #pragma unroll
            for (int e = 0; e < 4; ++e) sacc[nf][e] = 0.f;

        #pragma unroll 4
        for (int kf = 0; kf < 16; ++kf) {
            const uint32_t kb = kf * 32;
            uint32_t qh[4], ql[4], kh[2][4], kl[2][4];
            ldsm_x4(qh, sb + SM_QH + (wm*16) * AT_STRIDE + kb + offA);
            ldsm_x4(ql, sb + SM_QL + (wm*16) * AT_STRIDE + kb + offA);
            ldsm_x4(kh[0], sb + SM_KH + (wn*32)      * AT_STRIDE + kb + offB);
            ldsm_x4(kh[1], sb + SM_KH + (wn*32 + 16) * AT_STRIDE + kb + offB);
            ldsm_x4(kl[0], sb + SM_KL + (wn*32)      * AT_STRIDE + kb + offB);
            ldsm_x4(kl[1], sb + SM_KL + (wn*32 + 16) * AT_STRIDE + kb + offB);
            #pragma unroll
            for (int nf = 0; nf < 4; ++nf) {
                mma16816(sacc[nf], qh, kh[nf>>1][(nf&1)*2], kh[nf>>1][(nf&1)*2+1]);
                mma16816(sacc[nf], qh, kl[nf>>1][(nf&1)*2], kl[nf>>1][(nf&1)*2+1]);
                mma16816(sacc[nf], ql, kh[nf>>1][(nf&1)*2], kh[nf>>1][(nf&1)*2+1]);
            }
        }

        const float wbase = exp2f(l2d * (float)((jb - ib) * 64 - 1));
        const bool diag = (jb == ib);
        #pragma unroll
        for (int nf = 0; nf < 4; ++nf) {
            const int cl = wn*32 + nf*8 + (lane & 3)*2;
            float ec0 = exp2f(l2d * (float)cl);
            float ec1 = ec0 * decay;
            float w00 = wbase*ec0*er0, w01 = wbase*ec1*er0;
            float w10 = wbase*ec0*er1, w11 = wbase*ec1*er1;
            if (diag) {
                if (cl     <= rl0)     w00 = 0.f;
                if (cl + 1 <= rl0)     w01 = 0.f;
                if (cl     <= rl0 + 8) w10 = 0.f;
                if (cl + 1 <= rl0 + 8) w11 = 0.f;
            }
            float v00 = sacc[nf][0]*w00, v01 = sacc[nf][1]*w01;
            float v10 = sacc[nf][2]*w10, v11 = sacc[nf][3]*w11;

            #pragma unroll
            for (int h = 0; h < 2; ++h) {
                float a = h ? v10 : v00, c = h ? v11 : v01;
                __nv_bfloat16 ha, hc;
                uint32_t ph = pack_hilo(a, c, ha, hc);
                float ra = a - __bfloat162float(ha), rc = c - __bfloat162float(hc);
                __nv_bfloat16 t0, t1;
                uint32_t pl = pack_hilo(ra, rc, t0, t1);
                uint32_t off = (rl0 + h*8) * SW_STRIDE + cl * 2;
                *(uint32_t*)(shm + SM_SWH + off) = ph;
                *(uint32_t*)(shm + SM_SWL + off) = pl;
            }
        }

        CP_WAIT0();
        __syncthreads();

        uint32_t sh4[4][4], sl4[4][4];
        #pragma unroll
        for (int kf = 0; kf < 4; ++kf) {
            ldsm_x4(sh4[kf], sb + SM_SWH + (wm*16) * SW_STRIDE + kf*32 + offAs);
            ldsm_x4(sl4[kf], sb + SM_SWL + (wm*16) * SW_STRIDE + kf*32 + offAs);
        }
        #pragma unroll
        for (int nb = 0; nb < 8; ++nb) {
            const uint32_t d0b = (uint32_t)(wn*128 + nb*16) * 2;
            #pragma unroll
            for (int kf = 0; kf < 4; ++kf) {
                uint32_t vh[4], vl[4];
                const uint32_t va = sb + (kf*16) * AT_STRIDE + d0b + offV;
                ldsm_x4_t(vh, va + SM_VH);
                ldsm_x4_t(vl, va + SM_VL);
                mma16816(oacc[nb][0], sh4[kf], vh[0], vh[1]);
                mma16816(oacc[nb][1], sh4[kf], vh[2], vh[3]);
                mma16816(oacc[nb][0], sh4[kf], vl[0], vl[1]);
                mma16816(oacc[nb][1], sh4[kf], vl[2], vl[3]);
                mma16816(oacc[nb][0], sl4[kf], vh[0], vh[1]);
                mma16816(oacc[nb][1], sl4[kf], vh[2], vh[3]);
            }
        }
        __syncthreads();
    }

    // ---- fused epilogue: write r directly as bf16 hi/lo ----
    const size_t rrow = (size_t)(qrow0 + wm*16 + (lane >> 2)) * D_;
    #pragma unroll
    for (int nb = 0; nb < 8; ++nb) {
        #pragma unroll
        for (int g = 0; g < 2; ++g) {
            const int c = wn*128 + nb*16 + g*8 + (lane & 3) * 2;
            #pragma unroll
            for (int h = 0; h < 2; ++h) {
                float a = oacc[nb][g][h*2], cc = oacc[nb][g][h*2+1];
                __nv_bfloat16 ha, hc;
                uint32_t ph = pack_hilo(a, cc, ha, hc);
                float la = a - __bfloat162float(ha), lc = cc - __bfloat162float(hc);
                __nv_bfloat16 t0, t1;
                uint32_t pl = pack_hilo(la, lc, t0, t1);
                *(uint32_t*)(g_rh + rrow + (size_t)h * 8 * D_ + c) = ph;
                *(uint32_t*)(g_rl + rrow + (size_t)h * 8 * D_ + c) = pl;
            }
        }
    }
}

// ================= launch =================
#define DSMEM_BYTES (2*STG)

extern "C" void kernel_launch(void* const* d_in, const int* in_sizes, int n_in,
                              void* d_out, int out_size)
{
    const float* x  = (const float*)d_in[0];
    const float* wq = (const float*)d_in[1];
    const float* wk = (const float*)d_in[2];
    const float* wv = (const float*)d_in[3];
    const float* wo = (const float*)d_in[4];
    const float* dl = (const float*)d_in[5];
    const float* os = (const float*)d_in[6];
    float* out = (float*)d_out;

    cudaFuncSetAttribute(hmma_qkv_kernel, cudaFuncAttributeMaxDynamicSharedMemorySize, DSMEM_BYTES);
    cudaFuncSetAttribute(hmma_out_kernel, cudaFuncAttributeMaxDynamicSharedMemorySize, DSMEM_BYTES);
    cudaFuncSetAttribute(attn_hmma_kernel, cudaFuncAttributeMaxDynamicSharedMemorySize, ATT_SMEM);

    cvt_x_kernel<<<((size_t)M_*V_)/4096, 256>>>(x);
    cvt_w_kernel<<<4*512, 256>>>(wq, wk, wv, wo);

    hmma_qkv_kernel<<<dim3(2, 64, 6), 256, DSMEM_BYTES>>>();

    reduce_qkv_kernel<<<3*2048, 256>>>();

    attn_hmma_kernel<<<dim3(T_/64, B_), 256, ATT_SMEM>>>(dl);

    hmma_out_kernel<<<dim3(64, 64), 256, DSMEM_BYTES>>>(os, out);
}

// round 9
// speedup vs baseline: 1.5394x; 1.3010x over previous
#include <cuda_runtime.h>
#include <cuda_bf16.h>
#include <cuda_fp16.h>
#include <cstdint>

#define B_ 4
#define T_ 2048
#define V_ 8192
#define D_ 256
#define M_ (B_*T_)   // 8192 rows of (b,t)

// ---------------- scratch (device globals; no allocs allowed) ----------------
__device__ __half g_xh[(size_t)M_*V_];
__device__ __half g_xl[(size_t)M_*V_];
__device__ __half g_wf[3*(size_t)D_*V_];
__device__ __half g_wof[(size_t)V_*D_];
__device__ __half g_rh[(size_t)M_*D_];
__device__ __half g_rl[(size_t)M_*D_];

// split-K fp32 partials for qkv: 6 slabs of M_*D_ (z = w*2 + khalf)
__device__ float g_part[6*(size_t)M_*D_];

// bf16 hi/lo q,k,v (written by reduce kernel; attention stays 3-pass bf16)
__device__ __nv_bfloat16 g_qbh[(size_t)M_*D_];
__device__ __nv_bfloat16 g_qbl[(size_t)M_*D_];
__device__ __nv_bfloat16 g_kbh[(size_t)M_*D_];
__device__ __nv_bfloat16 g_kbl[(size_t)M_*D_];
__device__ __nv_bfloat16 g_vbh[(size_t)M_*D_];
__device__ __nv_bfloat16 g_vbl[(size_t)M_*D_];

// ---------------- helpers ----------------
__device__ __forceinline__ uint32_t smem_u32(const void* p){
    uint32_t a;
    asm("{ .reg .u64 t; cvta.to.shared.u64 t, %1; cvt.u32.u64 %0, t; }" : "=r"(a) : "l"(p));
    return a;
}
#define CP16(smem, gptr) \
    asm volatile("cp.async.cg.shared.global [%0], [%1], 16;" :: "r"(smem), "l"(gptr))
#define CP_COMMIT() asm volatile("cp.async.commit_group;" ::: "memory")
#define CP_WAIT1()  asm volatile("cp.async.wait_group 1;" ::: "memory")
#define CP_WAIT0()  asm volatile("cp.async.wait_group 0;" ::: "memory")

__device__ __forceinline__ void ldsm_x4(uint32_t (&r)[4], uint32_t addr){
    asm volatile("ldmatrix.sync.aligned.m8n8.x4.shared.b16 {%0,%1,%2,%3}, [%4];"
        : "=r"(r[0]), "=r"(r[1]), "=r"(r[2]), "=r"(r[3]) : "r"(addr));
}
__device__ __forceinline__ void ldsm_x4_t(uint32_t (&r)[4], uint32_t addr){
    asm volatile("ldmatrix.sync.aligned.m8n8.x4.trans.shared.b16 {%0,%1,%2,%3}, [%4];"
        : "=r"(r[0]), "=r"(r[1]), "=r"(r[2]), "=r"(r[3]) : "r"(addr));
}
// bf16 mma (attention)
__device__ __forceinline__ void mma16816(float (&d)[4], const uint32_t (&a)[4],
                                         uint32_t b0, uint32_t b1){
    asm volatile("mma.sync.aligned.m16n8k16.row.col.f32.bf16.bf16.f32 "
        "{%0,%1,%2,%3}, {%4,%5,%6,%7}, {%8,%9}, {%0,%1,%2,%3};"
        : "+f"(d[0]), "+f"(d[1]), "+f"(d[2]), "+f"(d[3])
        : "r"(a[0]), "r"(a[1]), "r"(a[2]), "r"(a[3]), "r"(b0), "r"(b1));
}
// fp16 mma (projection GEMMs)
__device__ __forceinline__ void mma16816h(float (&d)[4], const uint32_t (&a)[4],
                                          uint32_t b0, uint32_t b1){
    asm volatile("mma.sync.aligned.m16n8k16.row.col.f32.f16.f16.f32 "
        "{%0,%1,%2,%3}, {%4,%5,%6,%7}, {%8,%9}, {%0,%1,%2,%3};"
        : "+f"(d[0]), "+f"(d[1]), "+f"(d[2]), "+f"(d[3])
        : "r"(a[0]), "r"(a[1]), "r"(a[2]), "r"(a[3]), "r"(b0), "r"(b1));
}
__device__ __forceinline__ uint32_t pack_hilo_b(float a, float c,
                                                __nv_bfloat16& ra, __nv_bfloat16& rc){
    ra = __float2bfloat16(a);
    rc = __float2bfloat16(c);
    return (uint32_t)*(uint16_t*)&ra | ((uint32_t)*(uint16_t*)&rc << 16);
}
__device__ __forceinline__ uint32_t pack_hilo_h(float a, float c,
                                                __half& ra, __half& rc){
    ra = __float2half_rn(a);
    rc = __float2half_rn(c);
    return (uint32_t)*(uint16_t*)&ra | ((uint32_t)*(uint16_t*)&rc << 16);
}

// ================= conversion kernels =================
// x: fp32 -> fp16 hi/lo (full split of A operand)
__global__ void __launch_bounds__(256)
cvt_x_kernel(const float* __restrict__ x)
{
    const size_t base = (size_t)blockIdx.x * 4096 + threadIdx.x * 4;
    float4 v[4];
    #pragma unroll
    for (int j = 0; j < 4; ++j) v[j] = *(const float4*)(x + base + j * 1024);
    #pragma unroll
    for (int j = 0; j < 4; ++j) {
        const size_t i = base + j * 1024;
        float f[4] = {v[j].x, v[j].y, v[j].z, v[j].w};
        union { __half b[4]; uint2 u; } H, L;
        #pragma unroll
        for (int e = 0; e < 4; ++e) {
            __half h = __float2half_rn(f[e]);
            float r = f[e] - __half2float(h);
            H.b[e] = h;
            L.b[e] = __float2half_rn(r);
        }
        *(uint2*)(g_xh + i) = H.u;
        *(uint2*)(g_xl + i) = L.u;
    }
}

// weights: fp32 -> single fp16 (B operand unsplit)
__global__ void __launch_bounds__(256)
cvt_w_kernel(const float* __restrict__ wq, const float* __restrict__ wk,
             const float* __restrict__ wv, const float* __restrict__ wo)
{
    const int sel = blockIdx.x >> 9;
    const int blk = blockIdx.x & 511;
    const float* in;
    __half* outp;
    switch (sel) {
        case 0: in = wq; outp = g_wf;                 break;
        case 1: in = wk; outp = g_wf + (size_t)D_*V_;   break;
        case 2: in = wv; outp = g_wf + 2*(size_t)D_*V_; break;
        default: in = wo; outp = g_wof;               break;
    }
    const size_t base = (size_t)blk * 4096 + threadIdx.x * 4;
    float4 v[4];
    #pragma unroll
    for (int j = 0; j < 4; ++j) v[j] = *(const float4*)(in + base + j * 1024);
    #pragma unroll
    for (int j = 0; j < 4; ++j) {
        const size_t i = base + j * 1024;
        float f[4] = {v[j].x, v[j].y, v[j].z, v[j].w};
        union { __half b[4]; uint2 u; } H;
        #pragma unroll
        for (int e = 0; e < 4; ++e) H.b[e] = __float2half_rn(f[e]);
        *(uint2*)(outp + i) = H.u;
    }
}

// ================= split-K reduce: partials -> bf16 hi/lo q/k/v =================
__global__ void __launch_bounds__(256)
reduce_qkv_kernel()
{
    const int w   = blockIdx.x >> 11;
    const int blk = blockIdx.x & 2047;
    const size_t base = (size_t)blk * 1024 + threadIdx.x * 4;
    const float* p0 = g_part + (size_t)(2*w)   * ((size_t)M_*D_);
    const float* p1 = g_part + (size_t)(2*w+1) * ((size_t)M_*D_);
    __nv_bfloat16* hi = (w==0) ? g_qbh : (w==1) ? g_kbh : g_vbh;
    __nv_bfloat16* lo = (w==0) ? g_qbl : (w==1) ? g_kbl : g_vbl;
    float4 a = *(const float4*)(p0 + base);
    float4 b = *(const float4*)(p1 + base);
    float f[4] = {a.x+b.x, a.y+b.y, a.z+b.z, a.w+b.w};
    union { __nv_bfloat16 b[4]; uint2 u; } H, L;
    #pragma unroll
    for (int e = 0; e < 4; ++e) {
        __nv_bfloat16 h = __float2bfloat16(f[e]);
        float r = f[e] - __bfloat162float(h);
        H.b[e] = h;
        L.b[e] = __float2bfloat16(r);
    }
    *(uint2*)(hi + base) = H.u;
    *(uint2*)(lo + base) = L.u;
}

// ================= fp16 2-pass NT GEMM =================
// C = (Ah+Al)[M,K] * B[N,K]^T * scale  (exact A split; error = B fp16 rounding)
// CTA tile 128x128, BK=32, 256 threads, warp tile 64x32.
#define STG 30720
#define T_AH 0
#define T_AL 10240
#define T_B  20480
#define LDS_B 80

__device__ __forceinline__ void hmma_gemm_body(
    const __half* __restrict__ Agh, const __half* __restrict__ Agl,
    const __half* __restrict__ Bg,
    float* __restrict__ Cf,
    int K, int ldAB, int ldC, float scale, int row0, int col0)
{
    extern __shared__ __align__(128) char sm[];
    const int tid  = threadIdx.x;
    const int lane = tid & 31;
    const int wid  = tid >> 5;
    const int wm   = wid >> 2;
    const int wn   = wid & 3;
    const uint32_t sbase = smem_u32(sm);

    float acc[4][4][4];
    #pragma unroll
    for (int a = 0; a < 4; ++a)
        #pragma unroll
        for (int b = 0; b < 4; ++b)
            #pragma unroll
            for (int c = 0; c < 4; ++c) acc[a][b][c] = 0.f;

    const int lrow = tid >> 2, lseg = tid & 3;

    auto load_stage = [&](int c, int s){
        const size_t k0 = (size_t)c * 32 + lseg * 8;
        const uint32_t sb = sbase + s * STG;
        #pragma unroll
        for (int h = 0; h < 2; ++h) {
            const int r = lrow + h * 64;
            const uint32_t soff = r * LDS_B + lseg * 16;
            CP16(sb + T_AH + soff, Agh + (size_t)(row0 + r) * ldAB + k0);
            CP16(sb + T_AL + soff, Agl + (size_t)(row0 + r) * ldAB + k0);
            CP16(sb + T_B  + soff, Bg  + (size_t)(col0 + r) * ldAB + k0);
        }
    };

    const uint32_t offA = (lane & 15) * LDS_B + (lane >> 4) * 16;
    const uint32_t offB = ((lane & 7) + ((lane >> 4) & 1) * 8) * LDS_B
                        + ((lane >> 3) & 1) * 16;

    const int NC = K / 32;

    load_stage(0, 0);
    CP_COMMIT();

    for (int c = 0; c < NC; ++c) {
        if (c + 1 < NC) { load_stage(c + 1, (c + 1) & 1); CP_COMMIT(); CP_WAIT1(); }
        else            { CP_WAIT0(); }
        __syncthreads();

        const uint32_t sb = sbase + (c & 1) * STG;
        #pragma unroll
        for (int kk = 0; kk < 2; ++kk) {
            const uint32_t kb = kk * 32;
            uint32_t ah[4][4], al[4][4], bb[2][4];
            #pragma unroll
            for (int mf = 0; mf < 4; ++mf)
                ldsm_x4(ah[mf], sb + T_AH + (wm*64 + mf*16) * LDS_B + kb + offA);
            #pragma unroll
            for (int g = 0; g < 2; ++g)
                ldsm_x4(bb[g], sb + T_B + (wn*32 + g*16) * LDS_B + kb + offB);
            #pragma unroll
            for (int mf = 0; mf < 4; ++mf)
                #pragma unroll
                for (int nf = 0; nf < 4; ++nf)
                    mma16816h(acc[mf][nf], ah[mf], bb[nf>>1][(nf&1)*2], bb[nf>>1][(nf&1)*2+1]);
            #pragma unroll
            for (int mf = 0; mf < 4; ++mf)
                ldsm_x4(al[mf], sb + T_AL + (wm*64 + mf*16) * LDS_B + kb + offA);
            #pragma unroll
            for (int mf = 0; mf < 4; ++mf)
                #pragma unroll
                for (int nf = 0; nf < 4; ++nf)
                    mma16816h(acc[mf][nf], al[mf], bb[nf>>1][(nf&1)*2], bb[nf>>1][(nf&1)*2+1]);
        }
        __syncthreads();
    }

    #pragma unroll
    for (int mf = 0; mf < 4; ++mf) {
        const int r0 = row0 + wm*64 + mf*16 + (lane >> 2);
        #pragma unroll
        for (int nf = 0; nf < 4; ++nf) {
            const int cc = col0 + wn*32 + nf*8 + (lane & 3) * 2;
            float2 v0 = { acc[mf][nf][0] * scale, acc[mf][nf][1] * scale };
            float2 v1 = { acc[mf][nf][2] * scale, acc[mf][nf][3] * scale };
            *(float2*)(Cf + (size_t)r0 * ldC + cc)       = v0;
            *(float2*)(Cf + (size_t)(r0 + 8) * ldC + cc) = v1;
        }
    }
}

// ---- QKV split-K: grid (2 Ntiles, 64 Mtiles, 6 = weight*2 + khalf) ----
__global__ void __launch_bounds__(256, 2)
hmma_qkv_kernel()
{
    const int z = blockIdx.z;
    const int w = z >> 1, kh = z & 1;
    const size_t koff = (size_t)kh * 4096;
    const __half* Bg = g_wf + (size_t)w * D_ * V_ + koff;
    float* Cf = g_part + (size_t)z * ((size_t)M_*D_);
    hmma_gemm_body(g_xh + koff, g_xl + koff, Bg, Cf,
                   4096, V_, D_, 1.0f, blockIdx.y * 128, blockIdx.x * 128);
}

// ---- OUT: grid (64 Ntiles, 64 Mtiles) ----
__global__ void __launch_bounds__(256, 2)
hmma_out_kernel(const float* __restrict__ out_scale, float* __restrict__ out)
{
    hmma_gemm_body(g_rh, g_rl, g_wof, out,
                   D_, D_, V_, out_scale[0], blockIdx.y * 128, blockIdx.x * 128);
}

// ================= HMMA attention (bf16 3-pass, fp16 hi/lo r output) =================
#define AT_STRIDE 528
#define SW_STRIDE 144
#define SM_QH 0
#define SM_QL 33792
#define SM_KH 67584
#define SM_KL 101376
#define SM_VH 135168
#define SM_VL 168960
#define SM_SWH 202752
#define SM_SWL 211968
#define ATT_SMEM 221184

__global__ void __launch_bounds__(256, 1)
attn_hmma_kernel(const float* __restrict__ dlp)
{
    extern __shared__ __align__(128) char shm[];
    const int tid = threadIdx.x, lane = tid & 31, wid = tid >> 5;
    const int wm = wid >> 1, wn = wid & 1;
    const int ib = blockIdx.x, b = blockIdx.y;
    const uint32_t sb = smem_u32(shm);

    const float logit = dlp[0];
    const float decay = 1.f / (1.f + expf(-logit));
    const float l2d   = log2f(decay);

    const int qrow0 = b * T_ + ib * 64;

    #pragma unroll
    for (int it = 0; it < 8; ++it) {
        int idx = it * 256 + tid;
        int r = idx >> 5, s = idx & 31;
        uint32_t soff = r * AT_STRIDE + s * 16;
        size_t gb = ((size_t)(qrow0 + r) * D_) * 2 + s * 16;
        CP16(sb + SM_QH + soff, (const char*)g_qbh + gb);
        CP16(sb + SM_QL + soff, (const char*)g_qbl + gb);
    }
    CP_COMMIT();

    float oacc[8][2][4];
    #pragma unroll
    for (int a = 0; a < 8; ++a)
        #pragma unroll
        for (int g = 0; g < 2; ++g)
            #pragma unroll
            for (int e = 0; e < 4; ++e) oacc[a][g][e] = 0.f;

    const uint32_t offA  = (lane & 15) * AT_STRIDE + (lane >> 4) * 16;
    const uint32_t offB  = ((lane & 7) + ((lane >> 4) & 1) * 8) * AT_STRIDE
                         + ((lane >> 3) & 1) * 16;
    const uint32_t offAs = (lane & 15) * SW_STRIDE + (lane >> 4) * 16;
    const uint32_t offV  = ((lane & 7) + ((lane >> 3) & 1) * 8) * AT_STRIDE
                         + (lane >> 4) * 16;

    const int rl0 = wm * 16 + (lane >> 2);
    const float er0 = exp2f(-l2d * (float)rl0);
    const float er1 = er0 * exp2f(-l2d * 8.f);

    CP_WAIT0();
    __syncthreads();

    for (int jb = ib; jb < T_/64; ++jb) {
        int emin = (jb - ib) * 64 - 64;
        if (emin > 0 && l2d * (float)emin < -35.f) break;
        const int krow0 = b * T_ + jb * 64;

        #pragma unroll
        for (int it = 0; it < 8; ++it) {
            int idx = it * 256 + tid;
            int r = idx >> 5, s = idx & 31;
            uint32_t soff = r * AT_STRIDE + s * 16;
            size_t gb = ((size_t)(krow0 + r) * D_) * 2 + s * 16;
            CP16(sb + SM_KH + soff, (const char*)g_kbh + gb);
            CP16(sb + SM_KL + soff, (const char*)g_kbl + gb);
        }
        CP_COMMIT();
        #pragma unroll
        for (int it = 0; it < 8; ++it) {
            int idx = it * 256 + tid;
            int r = idx >> 5, s = idx & 31;
            uint32_t soff = r * AT_STRIDE + s * 16;
            size_t gb = ((size_t)(krow0 + r) * D_) * 2 + s * 16;
            CP16(sb + SM_VH + soff, (const char*)g_vbh + gb);
            CP16(sb + SM_VL + soff, (const char*)g_vbl + gb);
        }
        CP_COMMIT();
        CP_WAIT1();
        __syncthreads();

        float sacc[4][4];
        #pragma unroll
        for (int nf = 0; nf < 4; ++nf)
            #pragma unroll
            for (int e = 0; e < 4; ++e) sacc[nf][e] = 0.f;

        #pragma unroll 4
        for (int kf = 0; kf < 16; ++kf) {
            const uint32_t kb = kf * 32;
            uint32_t qh[4], ql[4], kh[2][4], kl[2][4];
            ldsm_x4(qh, sb + SM_QH + (wm*16) * AT_STRIDE + kb + offA);
            ldsm_x4(ql, sb + SM_QL + (wm*16) * AT_STRIDE + kb + offA);
            ldsm_x4(kh[0], sb + SM_KH + (wn*32)      * AT_STRIDE + kb + offB);
            ldsm_x4(kh[1], sb + SM_KH + (wn*32 + 16) * AT_STRIDE + kb + offB);
            ldsm_x4(kl[0], sb + SM_KL + (wn*32)      * AT_STRIDE + kb + offB);
            ldsm_x4(kl[1], sb + SM_KL + (wn*32 + 16) * AT_STRIDE + kb + offB);
            #pragma unroll
            for (int nf = 0; nf < 4; ++nf) {
                mma16816(sacc[nf], qh, kh[nf>>1][(nf&1)*2], kh[nf>>1][(nf&1)*2+1]);
                mma16816(sacc[nf], qh, kl[nf>>1][(nf&1)*2], kl[nf>>1][(nf&1)*2+1]);
                mma16816(sacc[nf], ql, kh[nf>>1][(nf&1)*2], kh[nf>>1][(nf&1)*2+1]);
            }
        }

        const float wbase = exp2f(l2d * (float)((jb - ib) * 64 - 1));
        const bool diag = (jb == ib);
        #pragma unroll
        for (int nf = 0; nf < 4; ++nf) {
            const int cl = wn*32 + nf*8 + (lane & 3)*2;
            float ec0 = exp2f(l2d * (float)cl);
            float ec1 = ec0 * decay;
            float w00 = wbase*ec0*er0, w01 = wbase*ec1*er0;
            float w10 = wbase*ec0*er1, w11 = wbase*ec1*er1;
            if (diag) {
                if (cl     <= rl0)     w00 = 0.f;
                if (cl + 1 <= rl0)     w01 = 0.f;
                if (cl     <= rl0 + 8) w10 = 0.f;
                if (cl + 1 <= rl0 + 8) w11 = 0.f;
            }
            float v00 = sacc[nf][0]*w00, v01 = sacc[nf][1]*w01;
            float v10 = sacc[nf][2]*w10, v11 = sacc[nf][3]*w11;

            #pragma unroll
            for (int h = 0; h < 2; ++h) {
                float a = h ? v10 : v00, c = h ? v11 : v01;
                __nv_bfloat16 ha, hc;
                uint32_t ph = pack_hilo_b(a, c, ha, hc);
                float ra = a - __bfloat162float(ha), rc = c - __bfloat162float(hc);
                __nv_bfloat16 t0, t1;
                uint32_t pl = pack_hilo_b(ra, rc, t0, t1);
                uint32_t off = (rl0 + h*8) * SW_STRIDE + cl * 2;
                *(uint32_t*)(shm + SM_SWH + off) = ph;
                *(uint32_t*)(shm + SM_SWL + off) = pl;
            }
        }

        CP_WAIT0();
        __syncthreads();

        uint32_t sh4[4][4], sl4[4][4];
        #pragma unroll
        for (int kf = 0; kf < 4; ++kf) {
            ldsm_x4(sh4[kf], sb + SM_SWH + (wm*16) * SW_STRIDE + kf*32 + offAs);
            ldsm_x4(sl4[kf], sb + SM_SWL + (wm*16) * SW_STRIDE + kf*32 + offAs);
        }
        #pragma unroll
        for (int nb = 0; nb < 8; ++nb) {
            const uint32_t d0b = (uint32_t)(wn*128 + nb*16) * 2;
            #pragma unroll
            for (int kf = 0; kf < 4; ++kf) {
                uint32_t vh[4], vl[4];
                const uint32_t va = sb + (kf*16) * AT_STRIDE + d0b + offV;
                ldsm_x4_t(vh, va + SM_VH);
                ldsm_x4_t(vl, va + SM_VL);
                mma16816(oacc[nb][0], sh4[kf], vh[0], vh[1]);
                mma16816(oacc[nb][1], sh4[kf], vh[2], vh[3]);
                mma16816(oacc[nb][0], sh4[kf], vl[0], vl[1]);
                mma16816(oacc[nb][1], sh4[kf], vl[2], vl[3]);
                mma16816(oacc[nb][0], sl4[kf], vh[0], vh[1]);
                mma16816(oacc[nb][1], sl4[kf], vh[2], vh[3]);
            }
        }
        __syncthreads();
    }

    // ---- fused epilogue: write r directly as fp16 hi/lo (for 2-pass out GEMM) ----
    const size_t rrow = (size_t)(qrow0 + wm*16 + (lane >> 2)) * D_;
    #pragma unroll
    for (int nb = 0; nb < 8; ++nb) {
        #pragma unroll
        for (int g = 0; g < 2; ++g) {
            const int c = wn*128 + nb*16 + g*8 + (lane & 3) * 2;
            #pragma unroll
            for (int h = 0; h < 2; ++h) {
                float a = oacc[nb][g][h*2], cc = oacc[nb][g][h*2+1];
                __half ha, hc;
                uint32_t ph = pack_hilo_h(a, cc, ha, hc);
                float la = a - __half2float(ha), lc = cc - __half2float(hc);
                __half t0, t1;
                uint32_t pl = pack_hilo_h(la, lc, t0, t1);
                *(uint32_t*)(g_rh + rrow + (size_t)h * 8 * D_ + c) = ph;
                *(uint32_t*)(g_rl + rrow + (size_t)h * 8 * D_ + c) = pl;
            }
        }
    }
}

// ================= launch =================
#define DSMEM_BYTES (2*STG)

extern "C" void kernel_launch(void* const* d_in, const int* in_sizes, int n_in,
                              void* d_out, int out_size)
{
    const float* x  = (const float*)d_in[0];
    const float* wq = (const float*)d_in[1];
    const float* wk = (const float*)d_in[2];
    const float* wv = (const float*)d_in[3];
    const float* wo = (const float*)d_in[4];
    const float* dl = (const float*)d_in[5];
    const float* os = (const float*)d_in[6];
    float* out = (float*)d_out;

    cudaFuncSetAttribute(hmma_qkv_kernel, cudaFuncAttributeMaxDynamicSharedMemorySize, DSMEM_BYTES);
    cudaFuncSetAttribute(hmma_out_kernel, cudaFuncAttributeMaxDynamicSharedMemorySize, DSMEM_BYTES);
    cudaFuncSetAttribute(attn_hmma_kernel, cudaFuncAttributeMaxDynamicSharedMemorySize, ATT_SMEM);

    cvt_x_kernel<<<((size_t)M_*V_)/4096, 256>>>(x);
    cvt_w_kernel<<<4*512, 256>>>(wq, wk, wv, wo);

    hmma_qkv_kernel<<<dim3(2, 64, 6), 256, DSMEM_BYTES>>>();

    reduce_qkv_kernel<<<3*2048, 256>>>();

    attn_hmma_kernel<<<dim3(T_/64, B_), 256, ATT_SMEM>>>(dl);

    hmma_out_kernel<<<dim3(64, 64), 256, DSMEM_BYTES>>>(os, out);
}

// round 10
// speedup vs baseline: 1.6702x; 1.0850x over previous
#include <cuda_runtime.h>
#include <cuda_bf16.h>
#include <cuda_fp16.h>
#include <cstdint>

#define B_ 4
#define T_ 2048
#define V_ 8192
#define D_ 256
#define M_ (B_*T_)   // 8192 rows of (b,t)

// ---------------- scratch (device globals; no allocs allowed) ----------------
__device__ __half g_xh[(size_t)M_*V_];
__device__ __half g_xl[(size_t)M_*V_];
__device__ __half g_wf[3*(size_t)D_*V_];
__device__ __half g_wof[(size_t)V_*D_];
__device__ __half g_rf[(size_t)M_*D_];      // single fp16 r (1-pass out GEMM)

// split-K fp32 partials for qkv: 6 slabs of M_*D_ (z = w*2 + khalf)
__device__ float g_part[6*(size_t)M_*D_];

// bf16 hi/lo q,k,v (attention stays 3-pass bf16)
__device__ __nv_bfloat16 g_qbh[(size_t)M_*D_];
__device__ __nv_bfloat16 g_qbl[(size_t)M_*D_];
__device__ __nv_bfloat16 g_kbh[(size_t)M_*D_];
__device__ __nv_bfloat16 g_kbl[(size_t)M_*D_];
__device__ __nv_bfloat16 g_vbh[(size_t)M_*D_];
__device__ __nv_bfloat16 g_vbl[(size_t)M_*D_];

// ---------------- helpers ----------------
__device__ __forceinline__ uint32_t smem_u32(const void* p){
    uint32_t a;
    asm("{ .reg .u64 t; cvta.to.shared.u64 t, %1; cvt.u32.u64 %0, t; }" : "=r"(a) : "l"(p));
    return a;
}
#define CP16(smem, gptr) \
    asm volatile("cp.async.cg.shared.global [%0], [%1], 16;" :: "r"(smem), "l"(gptr))
#define CP_COMMIT() asm volatile("cp.async.commit_group;" ::: "memory")
#define CP_WAIT1()  asm volatile("cp.async.wait_group 1;" ::: "memory")
#define CP_WAIT0()  asm volatile("cp.async.wait_group 0;" ::: "memory")

__device__ __forceinline__ void ldsm_x4(uint32_t (&r)[4], uint32_t addr){
    asm volatile("ldmatrix.sync.aligned.m8n8.x4.shared.b16 {%0,%1,%2,%3}, [%4];"
        : "=r"(r[0]), "=r"(r[1]), "=r"(r[2]), "=r"(r[3]) : "r"(addr));
}
__device__ __forceinline__ void ldsm_x4_t(uint32_t (&r)[4], uint32_t addr){
    asm volatile("ldmatrix.sync.aligned.m8n8.x4.trans.shared.b16 {%0,%1,%2,%3}, [%4];"
        : "=r"(r[0]), "=r"(r[1]), "=r"(r[2]), "=r"(r[3]) : "r"(addr));
}
// bf16 mma (attention)
__device__ __forceinline__ void mma16816(float (&d)[4], const uint32_t (&a)[4],
                                         uint32_t b0, uint32_t b1){
    asm volatile("mma.sync.aligned.m16n8k16.row.col.f32.bf16.bf16.f32 "
        "{%0,%1,%2,%3}, {%4,%5,%6,%7}, {%8,%9}, {%0,%1,%2,%3};"
        : "+f"(d[0]), "+f"(d[1]), "+f"(d[2]), "+f"(d[3])
        : "r"(a[0]), "r"(a[1]), "r"(a[2]), "r"(a[3]), "r"(b0), "r"(b1));
}
// fp16 mma (projection GEMMs)
__device__ __forceinline__ void mma16816h(float (&d)[4], const uint32_t (&a)[4],
                                          uint32_t b0, uint32_t b1){
    asm volatile("mma.sync.aligned.m16n8k16.row.col.f32.f16.f16.f32 "
        "{%0,%1,%2,%3}, {%4,%5,%6,%7}, {%8,%9}, {%0,%1,%2,%3};"
        : "+f"(d[0]), "+f"(d[1]), "+f"(d[2]), "+f"(d[3])
        : "r"(a[0]), "r"(a[1]), "r"(a[2]), "r"(a[3]), "r"(b0), "r"(b1));
}
__device__ __forceinline__ uint32_t pack_hilo_b(float a, float c,
                                                __nv_bfloat16& ra, __nv_bfloat16& rc){
    ra = __float2bfloat16(a);
    rc = __float2bfloat16(c);
    return (uint32_t)*(uint16_t*)&ra | ((uint32_t)*(uint16_t*)&rc << 16);
}
__device__ __forceinline__ uint32_t pack_h2(float a, float c){
    __half ra = __float2half_rn(a);
    __half rc = __float2half_rn(c);
    return (uint32_t)*(uint16_t*)&ra | ((uint32_t)*(uint16_t*)&rc << 16);
}

// ================= conversion kernels =================
// x: fp32 -> fp16 hi/lo (full split of A operand)
__global__ void __launch_bounds__(256)
cvt_x_kernel(const float* __restrict__ x)
{
    const size_t base = (size_t)blockIdx.x * 4096 + threadIdx.x * 4;
    float4 v[4];
    #pragma unroll
    for (int j = 0; j < 4; ++j) v[j] = *(const float4*)(x + base + j * 1024);
    #pragma unroll
    for (int j = 0; j < 4; ++j) {
        const size_t i = base + j * 1024;
        float f[4] = {v[j].x, v[j].y, v[j].z, v[j].w};
        union { __half b[4]; uint2 u; } H, L;
        #pragma unroll
        for (int e = 0; e < 4; ++e) {
            __half h = __float2half_rn(f[e]);
            float r = f[e] - __half2float(h);
            H.b[e] = h;
            L.b[e] = __float2half_rn(r);
        }
        *(uint2*)(g_xh + i) = H.u;
        *(uint2*)(g_xl + i) = L.u;
    }
}

// weights: fp32 -> single fp16 (B operand unsplit)
__global__ void __launch_bounds__(256)
cvt_w_kernel(const float* __restrict__ wq, const float* __restrict__ wk,
             const float* __restrict__ wv, const float* __restrict__ wo)
{
    const int sel = blockIdx.x >> 9;
    const int blk = blockIdx.x & 511;
    const float* in;
    __half* outp;
    switch (sel) {
        case 0: in = wq; outp = g_wf;                 break;
        case 1: in = wk; outp = g_wf + (size_t)D_*V_;   break;
        case 2: in = wv; outp = g_wf + 2*(size_t)D_*V_; break;
        default: in = wo; outp = g_wof;               break;
    }
    const size_t base = (size_t)blk * 4096 + threadIdx.x * 4;
    float4 v[4];
    #pragma unroll
    for (int j = 0; j < 4; ++j) v[j] = *(const float4*)(in + base + j * 1024);
    #pragma unroll
    for (int j = 0; j < 4; ++j) {
        const size_t i = base + j * 1024;
        float f[4] = {v[j].x, v[j].y, v[j].z, v[j].w};
        union { __half b[4]; uint2 u; } H;
        #pragma unroll
        for (int e = 0; e < 4; ++e) H.b[e] = __float2half_rn(f[e]);
        *(uint2*)(outp + i) = H.u;
    }
}

// ================= split-K reduce: partials -> bf16 hi/lo q/k/v =================
__global__ void __launch_bounds__(256)
reduce_qkv_kernel()
{
    const int w   = blockIdx.x >> 11;
    const int blk = blockIdx.x & 2047;
    const size_t base = (size_t)blk * 1024 + threadIdx.x * 4;
    const float* p0 = g_part + (size_t)(2*w)   * ((size_t)M_*D_);
    const float* p1 = g_part + (size_t)(2*w+1) * ((size_t)M_*D_);
    __nv_bfloat16* hi = (w==0) ? g_qbh : (w==1) ? g_kbh : g_vbh;
    __nv_bfloat16* lo = (w==0) ? g_qbl : (w==1) ? g_kbl : g_vbl;
    float4 a = *(const float4*)(p0 + base);
    float4 b = *(const float4*)(p1 + base);
    float f[4] = {a.x+b.x, a.y+b.y, a.z+b.z, a.w+b.w};
    union { __nv_bfloat16 b[4]; uint2 u; } H, L;
    #pragma unroll
    for (int e = 0; e < 4; ++e) {
        __nv_bfloat16 h = __float2bfloat16(f[e]);
        float r = f[e] - __bfloat162float(h);
        H.b[e] = h;
        L.b[e] = __float2bfloat16(r);
    }
    *(uint2*)(hi + base) = H.u;
    *(uint2*)(lo + base) = L.u;
}

// ================= fp16 NT GEMM (APASS = 1 or 2 A-operand passes) =================
// APASS=2: C = (Ah+Al) * B^T * scale   (exact A split; error = B fp16 rounding)
// APASS=1: C =  Ah     * B^T * scale   (error = A + B fp16 rounding)
// CTA tile 128x128, BK=32, 256 threads, warp tile 64x32.
#define LDS_B 80

template<int APASS>
__device__ __forceinline__ void hmma_gemm_body(
    const __half* __restrict__ Agh, const __half* __restrict__ Agl,
    const __half* __restrict__ Bg,
    float* __restrict__ Cf,
    int K, int ldAB, int ldC, float scale, int row0, int col0)
{
    constexpr uint32_t STG_ = (APASS == 2) ? 30720 : 20480;
    constexpr uint32_t T_AH_ = 0;
    constexpr uint32_t T_AL_ = 10240;
    constexpr uint32_t T_B_  = (APASS == 2) ? 20480 : 10240;

    extern __shared__ __align__(128) char sm[];
    const int tid  = threadIdx.x;
    const int lane = tid & 31;
    const int wid  = tid >> 5;
    const int wm   = wid >> 2;
    const int wn   = wid & 3;
    const uint32_t sbase = smem_u32(sm);

    float acc[4][4][4];
    #pragma unroll
    for (int a = 0; a < 4; ++a)
        #pragma unroll
        for (int b = 0; b < 4; ++b)
            #pragma unroll
            for (int c = 0; c < 4; ++c) acc[a][b][c] = 0.f;

    const int lrow = tid >> 2, lseg = tid & 3;

    auto load_stage = [&](int c, int s){
        const size_t k0 = (size_t)c * 32 + lseg * 8;
        const uint32_t sb = sbase + s * STG_;
        #pragma unroll
        for (int h = 0; h < 2; ++h) {
            const int r = lrow + h * 64;
            const uint32_t soff = r * LDS_B + lseg * 16;
            CP16(sb + T_AH_ + soff, Agh + (size_t)(row0 + r) * ldAB + k0);
            if (APASS == 2)
                CP16(sb + T_AL_ + soff, Agl + (size_t)(row0 + r) * ldAB + k0);
            CP16(sb + T_B_  + soff, Bg  + (size_t)(col0 + r) * ldAB + k0);
        }
    };

    const uint32_t offA = (lane & 15) * LDS_B + (lane >> 4) * 16;
    const uint32_t offB = ((lane & 7) + ((lane >> 4) & 1) * 8) * LDS_B
                        + ((lane >> 3) & 1) * 16;

    const int NC = K / 32;

    load_stage(0, 0);
    CP_COMMIT();

    for (int c = 0; c < NC; ++c) {
        if (c + 1 < NC) { load_stage(c + 1, (c + 1) & 1); CP_COMMIT(); CP_WAIT1(); }
        else            { CP_WAIT0(); }
        __syncthreads();

        const uint32_t sb = sbase + (c & 1) * STG_;
        #pragma unroll
        for (int kk = 0; kk < 2; ++kk) {
            const uint32_t kb = kk * 32;
            uint32_t ah[4][4], bb[2][4];
            #pragma unroll
            for (int mf = 0; mf < 4; ++mf)
                ldsm_x4(ah[mf], sb + T_AH_ + (wm*64 + mf*16) * LDS_B + kb + offA);
            #pragma unroll
            for (int g = 0; g < 2; ++g)
                ldsm_x4(bb[g], sb + T_B_ + (wn*32 + g*16) * LDS_B + kb + offB);
            #pragma unroll
            for (int mf = 0; mf < 4; ++mf)
                #pragma unroll
                for (int nf = 0; nf < 4; ++nf)
                    mma16816h(acc[mf][nf], ah[mf], bb[nf>>1][(nf&1)*2], bb[nf>>1][(nf&1)*2+1]);
            if (APASS == 2) {
                uint32_t al[4][4];
                #pragma unroll
                for (int mf = 0; mf < 4; ++mf)
                    ldsm_x4(al[mf], sb + T_AL_ + (wm*64 + mf*16) * LDS_B + kb + offA);
                #pragma unroll
                for (int mf = 0; mf < 4; ++mf)
                    #pragma unroll
                    for (int nf = 0; nf < 4; ++nf)
                        mma16816h(acc[mf][nf], al[mf], bb[nf>>1][(nf&1)*2], bb[nf>>1][(nf&1)*2+1]);
            }
        }
        __syncthreads();
    }

    #pragma unroll
    for (int mf = 0; mf < 4; ++mf) {
        const int r0 = row0 + wm*64 + mf*16 + (lane >> 2);
        #pragma unroll
        for (int nf = 0; nf < 4; ++nf) {
            const int cc = col0 + wn*32 + nf*8 + (lane & 3) * 2;
            float2 v0 = { acc[mf][nf][0] * scale, acc[mf][nf][1] * scale };
            float2 v1 = { acc[mf][nf][2] * scale, acc[mf][nf][3] * scale };
            *(float2*)(Cf + (size_t)r0 * ldC + cc)       = v0;
            *(float2*)(Cf + (size_t)(r0 + 8) * ldC + cc) = v1;
        }
    }
}

// ---- QKV split-K: grid (2 Ntiles, 64 Mtiles, 6 = weight*2 + khalf) ----
__global__ void __launch_bounds__(256, 2)
hmma_qkv_kernel()
{
    const int z = blockIdx.z;
    const int w = z >> 1, kh = z & 1;
    const size_t koff = (size_t)kh * 4096;
    const __half* Bg = g_wf + (size_t)w * D_ * V_ + koff;
    float* Cf = g_part + (size_t)z * ((size_t)M_*D_);
    hmma_gemm_body<2>(g_xh + koff, g_xl + koff, Bg, Cf,
                      4096, V_, D_, 1.0f, blockIdx.y * 128, blockIdx.x * 128);
}

// ---- OUT (1-pass): grid (64 Ntiles, 64 Mtiles) ----
__global__ void __launch_bounds__(256, 2)
hmma_out_kernel(const float* __restrict__ out_scale, float* __restrict__ out)
{
    hmma_gemm_body<1>(g_rf, nullptr, g_wof, out,
                      D_, D_, V_, out_scale[0], blockIdx.y * 128, blockIdx.x * 128);
}

// ================= HMMA attention (bf16 3-pass, single fp16 r output) =================
#define AT_STRIDE 528
#define SW_STRIDE 144
#define SM_QH 0
#define SM_QL 33792
#define SM_KH 67584
#define SM_KL 101376
#define SM_VH 135168
#define SM_VL 168960
#define SM_SWH 202752
#define SM_SWL 211968
#define ATT_SMEM 221184

__global__ void __launch_bounds__(256, 1)
attn_hmma_kernel(const float* __restrict__ dlp)
{
    extern __shared__ __align__(128) char shm[];
    const int tid = threadIdx.x, lane = tid & 31, wid = tid >> 5;
    const int wm = wid >> 1, wn = wid & 1;
    const int ib = blockIdx.x, b = blockIdx.y;
    const uint32_t sb = smem_u32(shm);

    const float logit = dlp[0];
    const float decay = 1.f / (1.f + expf(-logit));
    const float l2d   = log2f(decay);

    const int qrow0 = b * T_ + ib * 64;

    #pragma unroll
    for (int it = 0; it < 8; ++it) {
        int idx = it * 256 + tid;
        int r = idx >> 5, s = idx & 31;
        uint32_t soff = r * AT_STRIDE + s * 16;
        size_t gb = ((size_t)(qrow0 + r) * D_) * 2 + s * 16;
        CP16(sb + SM_QH + soff, (const char*)g_qbh + gb);
        CP16(sb + SM_QL + soff, (const char*)g_qbl + gb);
    }
    CP_COMMIT();

    float oacc[8][2][4];
    #pragma unroll
    for (int a = 0; a < 8; ++a)
        #pragma unroll
        for (int g = 0; g < 2; ++g)
            #pragma unroll
            for (int e = 0; e < 4; ++e) oacc[a][g][e] = 0.f;

    const uint32_t offA  = (lane & 15) * AT_STRIDE + (lane >> 4) * 16;
    const uint32_t offB  = ((lane & 7) + ((lane >> 4) & 1) * 8) * AT_STRIDE
                         + ((lane >> 3) & 1) * 16;
    const uint32_t offAs = (lane & 15) * SW_STRIDE + (lane >> 4) * 16;
    const uint32_t offV  = ((lane & 7) + ((lane >> 3) & 1) * 8) * AT_STRIDE
                         + (lane >> 4) * 16;

    const int rl0 = wm * 16 + (lane >> 2);
    const float er0 = exp2f(-l2d * (float)rl0);
    const float er1 = er0 * exp2f(-l2d * 8.f);

    CP_WAIT0();
    __syncthreads();

    for (int jb = ib; jb < T_/64; ++jb) {
        int emin = (jb - ib) * 64 - 64;
        if (emin > 0 && l2d * (float)emin < -35.f) break;
        const int krow0 = b * T_ + jb * 64;

        #pragma unroll
        for (int it = 0; it < 8; ++it) {
            int idx = it * 256 + tid;
            int r = idx >> 5, s = idx & 31;
            uint32_t soff = r * AT_STRIDE + s * 16;
            size_t gb = ((size_t)(krow0 + r) * D_) * 2 + s * 16;
            CP16(sb + SM_KH + soff, (const char*)g_kbh + gb);
            CP16(sb + SM_KL + soff, (const char*)g_kbl + gb);
        }
        CP_COMMIT();
        #pragma unroll
        for (int it = 0; it < 8; ++it) {
            int idx = it * 256 + tid;
            int r = idx >> 5, s = idx & 31;
            uint32_t soff = r * AT_STRIDE + s * 16;
            size_t gb = ((size_t)(krow0 + r) * D_) * 2 + s * 16;
            CP16(sb + SM_VH + soff, (const char*)g_vbh + gb);
            CP16(sb + SM_VL + soff, (const char*)g_vbl + gb);
        }
        CP_COMMIT();
        CP_WAIT1();
        __syncthreads();

        float sacc[4][4];
        #pragma unroll
        for (int nf = 0; nf < 4; ++nf)
            #pragma unroll
            for (int e = 0; e < 4; ++e) sacc[nf][e] = 0.f;

        #pragma unroll 4
        for (int kf = 0; kf < 16; ++kf) {
            const uint32_t kb = kf * 32;
            uint32_t qh[4], ql[4], kh[2][4], kl[2][4];
            ldsm_x4(qh, sb + SM_QH + (wm*16) * AT_STRIDE + kb + offA);
            ldsm_x4(ql, sb + SM_QL + (wm*16) * AT_STRIDE + kb + offA);
            ldsm_x4(kh[0], sb + SM_KH + (wn*32)      * AT_STRIDE + kb + offB);
            ldsm_x4(kh[1], sb + SM_KH + (wn*32 + 16) * AT_STRIDE + kb + offB);
            ldsm_x4(kl[0], sb + SM_KL + (wn*32)      * AT_STRIDE + kb + offB);
            ldsm_x4(kl[1], sb + SM_KL + (wn*32 + 16) * AT_STRIDE + kb + offB);
            #pragma unroll
            for (int nf = 0; nf < 4; ++nf) {
                mma16816(sacc[nf], qh, kh[nf>>1][(nf&1)*2], kh[nf>>1][(nf&1)*2+1]);
                mma16816(sacc[nf], qh, kl[nf>>1][(nf&1)*2], kl[nf>>1][(nf&1)*2+1]);
                mma16816(sacc[nf], ql, kh[nf>>1][(nf&1)*2], kh[nf>>1][(nf&1)*2+1]);
            }
        }

        const float wbase = exp2f(l2d * (float)((jb - ib) * 64 - 1));
        const bool diag = (jb == ib);
        #pragma unroll
        for (int nf = 0; nf < 4; ++nf) {
            const int cl = wn*32 + nf*8 + (lane & 3)*2;
            float ec0 = exp2f(l2d * (float)cl);
            float ec1 = ec0 * decay;
            float w00 = wbase*ec0*er0, w01 = wbase*ec1*er0;
            float w10 = wbase*ec0*er1, w11 = wbase*ec1*er1;
            if (diag) {
                if (cl     <= rl0)     w00 = 0.f;
                if (cl + 1 <= rl0)     w01 = 0.f;
                if (cl     <= rl0 + 8) w10 = 0.f;
                if (cl + 1 <= rl0 + 8) w11 = 0.f;
            }
            float v00 = sacc[nf][0]*w00, v01 = sacc[nf][1]*w01;
            float v10 = sacc[nf][2]*w10, v11 = sacc[nf][3]*w11;

            #pragma unroll
            for (int h = 0; h < 2; ++h) {
                float a = h ? v10 : v00, c = h ? v11 : v01;
                __nv_bfloat16 ha, hc;
                uint32_t ph = pack_hilo_b(a, c, ha, hc);
                float ra = a - __bfloat162float(ha), rc = c - __bfloat162float(hc);
                __nv_bfloat16 t0, t1;
                uint32_t pl = pack_hilo_b(ra, rc, t0, t1);
                uint32_t off = (rl0 + h*8) * SW_STRIDE + cl * 2;
                *(uint32_t*)(shm + SM_SWH + off) = ph;
                *(uint32_t*)(shm + SM_SWL + off) = pl;
            }
        }

        CP_WAIT0();
        __syncthreads();

        uint32_t sh4[4][4], sl4[4][4];
        #pragma unroll
        for (int kf = 0; kf < 4; ++kf) {
            ldsm_x4(sh4[kf], sb + SM_SWH + (wm*16) * SW_STRIDE + kf*32 + offAs);
            ldsm_x4(sl4[kf], sb + SM_SWL + (wm*16) * SW_STRIDE + kf*32 + offAs);
        }
        #pragma unroll
        for (int nb = 0; nb < 8; ++nb) {
            const uint32_t d0b = (uint32_t)(wn*128 + nb*16) * 2;
            #pragma unroll
            for (int kf = 0; kf < 4; ++kf) {
                uint32_t vh[4], vl[4];
                const uint32_t va = sb + (kf*16) * AT_STRIDE + d0b + offV;
                ldsm_x4_t(vh, va + SM_VH);
                ldsm_x4_t(vl, va + SM_VL);
                mma16816(oacc[nb][0], sh4[kf], vh[0], vh[1]);
                mma16816(oacc[nb][1], sh4[kf], vh[2], vh[3]);
                mma16816(oacc[nb][0], sh4[kf], vl[0], vl[1]);
                mma16816(oacc[nb][1], sh4[kf], vl[2], vl[3]);
                mma16816(oacc[nb][0], sl4[kf], vh[0], vh[1]);
                mma16816(oacc[nb][1], sl4[kf], vh[2], vh[3]);
            }
        }
        __syncthreads();
    }

    // ---- fused epilogue: write r as single fp16 (1-pass out GEMM) ----
    const size_t rrow = (size_t)(qrow0 + wm*16 + (lane >> 2)) * D_;
    #pragma unroll
    for (int nb = 0; nb < 8; ++nb) {
        #pragma unroll
        for (int g = 0; g < 2; ++g) {
            const int c = wn*128 + nb*16 + g*8 + (lane & 3) * 2;
            #pragma unroll
            for (int h = 0; h < 2; ++h) {
                uint32_t ph = pack_h2(oacc[nb][g][h*2], oacc[nb][g][h*2+1]);
                *(uint32_t*)(g_rf + rrow + (size_t)h * 8 * D_ + c) = ph;
            }
        }
    }
}

// ================= launch =================
#define QKV_SMEM (2*30720)
#define OUT_SMEM (2*20480)

extern "C" void kernel_launch(void* const* d_in, const int* in_sizes, int n_in,
                              void* d_out, int out_size)
{
    const float* x  = (const float*)d_in[0];
    const float* wq = (const float*)d_in[1];
    const float* wk = (const float*)d_in[2];
    const float* wv = (const float*)d_in[3];
    const float* wo = (const float*)d_in[4];
    const float* dl = (const float*)d_in[5];
    const float* os = (const float*)d_in[6];
    float* out = (float*)d_out;

    cudaFuncSetAttribute(hmma_qkv_kernel, cudaFuncAttributeMaxDynamicSharedMemorySize, QKV_SMEM);
    cudaFuncSetAttribute(hmma_out_kernel, cudaFuncAttributeMaxDynamicSharedMemorySize, OUT_SMEM);
    cudaFuncSetAttribute(attn_hmma_kernel, cudaFuncAttributeMaxDynamicSharedMemorySize, ATT_SMEM);

    cvt_x_kernel<<<((size_t)M_*V_)/4096, 256>>>(x);
    cvt_w_kernel<<<4*512, 256>>>(wq, wk, wv, wo);

    hmma_qkv_kernel<<<dim3(2, 64, 6), 256, QKV_SMEM>>>();

    reduce_qkv_kernel<<<3*2048, 256>>>();

    attn_hmma_kernel<<<dim3(T_/64, B_), 256, ATT_SMEM>>>(dl);

    hmma_out_kernel<<<dim3(64, 64), 256, OUT_SMEM>>>(os, out);
}

// round 11
// speedup vs baseline: 2.5043x; 1.4994x over previous
#include <cuda_runtime.h>
#include <cuda_bf16.h>
#include <cuda_fp16.h>
#include <cstdint>

#define B_ 4
#define T_ 2048
#define V_ 8192
#define D_ 256
#define M_ (B_*T_)   // 8192 rows of (b,t)

// ---------------- scratch (device globals; no allocs allowed) ----------------
__device__ __half g_xf[(size_t)M_*V_];      // single fp16 x (1-pass qkv)
__device__ __half g_wf[3*(size_t)D_*V_];
__device__ __half g_wof[(size_t)V_*D_];
__device__ __half g_rf[(size_t)M_*D_];      // single fp16 r (1-pass out GEMM)

// split-K fp32 partials for qkv: 6 slabs of M_*D_ (z = w*2 + khalf)
__device__ float g_part[6*(size_t)M_*D_];

// bf16 hi/lo q,k,v (attention stays 3-pass bf16)
__device__ __nv_bfloat16 g_qbh[(size_t)M_*D_];
__device__ __nv_bfloat16 g_qbl[(size_t)M_*D_];
__device__ __nv_bfloat16 g_kbh[(size_t)M_*D_];
__device__ __nv_bfloat16 g_kbl[(size_t)M_*D_];
__device__ __nv_bfloat16 g_vbh[(size_t)M_*D_];
__device__ __nv_bfloat16 g_vbl[(size_t)M_*D_];

// ---------------- helpers ----------------
__device__ __forceinline__ uint32_t smem_u32(const void* p){
    uint32_t a;
    asm("{ .reg .u64 t; cvta.to.shared.u64 t, %1; cvt.u32.u64 %0, t; }" : "=r"(a) : "l"(p));
    return a;
}
#define CP16(smem, gptr) \
    asm volatile("cp.async.cg.shared.global [%0], [%1], 16;" :: "r"(smem), "l"(gptr))
#define CP_COMMIT() asm volatile("cp.async.commit_group;" ::: "memory")
#define CP_WAIT1()  asm volatile("cp.async.wait_group 1;" ::: "memory")
#define CP_WAIT0()  asm volatile("cp.async.wait_group 0;" ::: "memory")

__device__ __forceinline__ void ldsm_x4(uint32_t (&r)[4], uint32_t addr){
    asm volatile("ldmatrix.sync.aligned.m8n8.x4.shared.b16 {%0,%1,%2,%3}, [%4];"
        : "=r"(r[0]), "=r"(r[1]), "=r"(r[2]), "=r"(r[3]) : "r"(addr));
}
__device__ __forceinline__ void ldsm_x4_t(uint32_t (&r)[4], uint32_t addr){
    asm volatile("ldmatrix.sync.aligned.m8n8.x4.trans.shared.b16 {%0,%1,%2,%3}, [%4];"
        : "=r"(r[0]), "=r"(r[1]), "=r"(r[2]), "=r"(r[3]) : "r"(addr));
}
// bf16 mma (attention)
__device__ __forceinline__ void mma16816(float (&d)[4], const uint32_t (&a)[4],
                                         uint32_t b0, uint32_t b1){
    asm volatile("mma.sync.aligned.m16n8k16.row.col.f32.bf16.bf16.f32 "
        "{%0,%1,%2,%3}, {%4,%5,%6,%7}, {%8,%9}, {%0,%1,%2,%3};"
        : "+f"(d[0]), "+f"(d[1]), "+f"(d[2]), "+f"(d[3])
        : "r"(a[0]), "r"(a[1]), "r"(a[2]), "r"(a[3]), "r"(b0), "r"(b1));
}
// fp16 mma (projection GEMMs)
__device__ __forceinline__ void mma16816h(float (&d)[4], const uint32_t (&a)[4],
                                          uint32_t b0, uint32_t b1){
    asm volatile("mma.sync.aligned.m16n8k16.row.col.f32.f16.f16.f32 "
        "{%0,%1,%2,%3}, {%4,%5,%6,%7}, {%8,%9}, {%0,%1,%2,%3};"
        : "+f"(d[0]), "+f"(d[1]), "+f"(d[2]), "+f"(d[3])
        : "r"(a[0]), "r"(a[1]), "r"(a[2]), "r"(a[3]), "r"(b0), "r"(b1));
}
__device__ __forceinline__ uint32_t pack_hilo_b(float a, float c,
                                                __nv_bfloat16& ra, __nv_bfloat16& rc){
    ra = __float2bfloat16(a);
    rc = __float2bfloat16(c);
    return (uint32_t)*(uint16_t*)&ra | ((uint32_t)*(uint16_t*)&rc << 16);
}
__device__ __forceinline__ uint32_t pack_h2(float a, float c){
    __half ra = __float2half_rn(a);
    __half rc = __float2half_rn(c);
    return (uint32_t)*(uint16_t*)&ra | ((uint32_t)*(uint16_t*)&rc << 16);
}

// ================= conversion kernels =================
// x: fp32 -> single fp16
__global__ void __launch_bounds__(256)
cvt_x_kernel(const float* __restrict__ x)
{
    const size_t base = (size_t)blockIdx.x * 4096 + threadIdx.x * 4;
    float4 v[4];
    #pragma unroll
    for (int j = 0; j < 4; ++j) v[j] = *(const float4*)(x + base + j * 1024);
    #pragma unroll
    for (int j = 0; j < 4; ++j) {
        const size_t i = base + j * 1024;
        float f[4] = {v[j].x, v[j].y, v[j].z, v[j].w};
        union { __half b[4]; uint2 u; } H;
        #pragma unroll
        for (int e = 0; e < 4; ++e) H.b[e] = __float2half_rn(f[e]);
        *(uint2*)(g_xf + i) = H.u;
    }
}

// weights: fp32 -> single fp16
__global__ void __launch_bounds__(256)
cvt_w_kernel(const float* __restrict__ wq, const float* __restrict__ wk,
             const float* __restrict__ wv, const float* __restrict__ wo)
{
    const int sel = blockIdx.x >> 9;
    const int blk = blockIdx.x & 511;
    const float* in;
    __half* outp;
    switch (sel) {
        case 0: in = wq; outp = g_wf;                 break;
        case 1: in = wk; outp = g_wf + (size_t)D_*V_;   break;
        case 2: in = wv; outp = g_wf + 2*(size_t)D_*V_; break;
        default: in = wo; outp = g_wof;               break;
    }
    const size_t base = (size_t)blk * 4096 + threadIdx.x * 4;
    float4 v[4];
    #pragma unroll
    for (int j = 0; j < 4; ++j) v[j] = *(const float4*)(in + base + j * 1024);
    #pragma unroll
    for (int j = 0; j < 4; ++j) {
        const size_t i = base + j * 1024;
        float f[4] = {v[j].x, v[j].y, v[j].z, v[j].w};
        union { __half b[4]; uint2 u; } H;
        #pragma unroll
        for (int e = 0; e < 4; ++e) H.b[e] = __float2half_rn(f[e]);
        *(uint2*)(outp + i) = H.u;
    }
}

// ================= split-K reduce: partials -> bf16 hi/lo q/k/v =================
__global__ void __launch_bounds__(256)
reduce_qkv_kernel()
{
    const int w   = blockIdx.x >> 11;
    const int blk = blockIdx.x & 2047;
    const size_t base = (size_t)blk * 1024 + threadIdx.x * 4;
    const float* p0 = g_part + (size_t)(2*w)   * ((size_t)M_*D_);
    const float* p1 = g_part + (size_t)(2*w+1) * ((size_t)M_*D_);
    __nv_bfloat16* hi = (w==0) ? g_qbh : (w==1) ? g_kbh : g_vbh;
    __nv_bfloat16* lo = (w==0) ? g_qbl : (w==1) ? g_kbl : g_vbl;
    float4 a = *(const float4*)(p0 + base);
    float4 b = *(const float4*)(p1 + base);
    float f[4] = {a.x+b.x, a.y+b.y, a.z+b.z, a.w+b.w};
    union { __nv_bfloat16 b[4]; uint2 u; } H, L;
    #pragma unroll
    for (int e = 0; e < 4; ++e) {
        __nv_bfloat16 h = __float2bfloat16(f[e]);
        float r = f[e] - __bfloat162float(h);
        H.b[e] = h;
        L.b[e] = __float2bfloat16(r);
    }
    *(uint2*)(hi + base) = H.u;
    *(uint2*)(lo + base) = L.u;
}

// ================= fp16 NT GEMM (APASS = 1 or 2 A-operand passes) =================
// APASS=2: C = (Ah+Al) * B^T * scale   (exact A split; error = B fp16 rounding)
// APASS=1: C =  Ah     * B^T * scale   (error = A + B fp16 rounding)
// CTA tile 128x128, BK=32, 256 threads, warp tile 64x32.
#define LDS_B 80

template<int APASS>
__device__ __forceinline__ void hmma_gemm_body(
    const __half* __restrict__ Agh, const __half* __restrict__ Agl,
    const __half* __restrict__ Bg,
    float* __restrict__ Cf,
    int K, int ldAB, int ldC, float scale, int row0, int col0)
{
    constexpr uint32_t STG_ = (APASS == 2) ? 30720 : 20480;
    constexpr uint32_t T_AH_ = 0;
    constexpr uint32_t T_AL_ = 10240;
    constexpr uint32_t T_B_  = (APASS == 2) ? 20480 : 10240;

    extern __shared__ __align__(128) char sm[];
    const int tid  = threadIdx.x;
    const int lane = tid & 31;
    const int wid  = tid >> 5;
    const int wm   = wid >> 2;
    const int wn   = wid & 3;
    const uint32_t sbase = smem_u32(sm);

    float acc[4][4][4];
    #pragma unroll
    for (int a = 0; a < 4; ++a)
        #pragma unroll
        for (int b = 0; b < 4; ++b)
            #pragma unroll
            for (int c = 0; c < 4; ++c) acc[a][b][c] = 0.f;

    const int lrow = tid >> 2, lseg = tid & 3;

    auto load_stage = [&](int c, int s){
        const size_t k0 = (size_t)c * 32 + lseg * 8;
        const uint32_t sb = sbase + s * STG_;
        #pragma unroll
        for (int h = 0; h < 2; ++h) {
            const int r = lrow + h * 64;
            const uint32_t soff = r * LDS_B + lseg * 16;
            CP16(sb + T_AH_ + soff, Agh + (size_t)(row0 + r) * ldAB + k0);
            if (APASS == 2)
                CP16(sb + T_AL_ + soff, Agl + (size_t)(row0 + r) * ldAB + k0);
            CP16(sb + T_B_  + soff, Bg  + (size_t)(col0 + r) * ldAB + k0);
        }
    };

    const uint32_t offA = (lane & 15) * LDS_B + (lane >> 4) * 16;
    const uint32_t offB = ((lane & 7) + ((lane >> 4) & 1) * 8) * LDS_B
                        + ((lane >> 3) & 1) * 16;

    const int NC = K / 32;

    load_stage(0, 0);
    CP_COMMIT();

    for (int c = 0; c < NC; ++c) {
        if (c + 1 < NC) { load_stage(c + 1, (c + 1) & 1); CP_COMMIT(); CP_WAIT1(); }
        else            { CP_WAIT0(); }
        __syncthreads();

        const uint32_t sb = sbase + (c & 1) * STG_;
        #pragma unroll
        for (int kk = 0; kk < 2; ++kk) {
            const uint32_t kb = kk * 32;
            uint32_t ah[4][4], bb[2][4];
            #pragma unroll
            for (int mf = 0; mf < 4; ++mf)
                ldsm_x4(ah[mf], sb + T_AH_ + (wm*64 + mf*16) * LDS_B + kb + offA);
            #pragma unroll
            for (int g = 0; g < 2; ++g)
                ldsm_x4(bb[g], sb + T_B_ + (wn*32 + g*16) * LDS_B + kb + offB);
            #pragma unroll
            for (int mf = 0; mf < 4; ++mf)
                #pragma unroll
                for (int nf = 0; nf < 4; ++nf)
                    mma16816h(acc[mf][nf], ah[mf], bb[nf>>1][(nf&1)*2], bb[nf>>1][(nf&1)*2+1]);
            if (APASS == 2) {
                uint32_t al[4][4];
                #pragma unroll
                for (int mf = 0; mf < 4; ++mf)
                    ldsm_x4(al[mf], sb + T_AL_ + (wm*64 + mf*16) * LDS_B + kb + offA);
                #pragma unroll
                for (int mf = 0; mf < 4; ++mf)
                    #pragma unroll
                    for (int nf = 0; nf < 4; ++nf)
                        mma16816h(acc[mf][nf], al[mf], bb[nf>>1][(nf&1)*2], bb[nf>>1][(nf&1)*2+1]);
            }
        }
        __syncthreads();
    }

    #pragma unroll
    for (int mf = 0; mf < 4; ++mf) {
        const int r0 = row0 + wm*64 + mf*16 + (lane >> 2);
        #pragma unroll
        for (int nf = 0; nf < 4; ++nf) {
            const int cc = col0 + wn*32 + nf*8 + (lane & 3) * 2;
            float2 v0 = { acc[mf][nf][0] * scale, acc[mf][nf][1] * scale };
            float2 v1 = { acc[mf][nf][2] * scale, acc[mf][nf][3] * scale };
            *(float2*)(Cf + (size_t)r0 * ldC + cc)       = v0;
            *(float2*)(Cf + (size_t)(r0 + 8) * ldC + cc) = v1;
        }
    }
}

// ---- QKV split-K (1-pass): grid (2 Ntiles, 64 Mtiles, 6 = weight*2 + khalf) ----
__global__ void __launch_bounds__(256, 2)
hmma_qkv_kernel()
{
    const int z = blockIdx.z;
    const int w = z >> 1, kh = z & 1;
    const size_t koff = (size_t)kh * 4096;
    const __half* Bg = g_wf + (size_t)w * D_ * V_ + koff;
    float* Cf = g_part + (size_t)z * ((size_t)M_*D_);
    hmma_gemm_body<1>(g_xf + koff, nullptr, Bg, Cf,
                      4096, V_, D_, 1.0f, blockIdx.y * 128, blockIdx.x * 128);
}

// ---- OUT (1-pass): grid (64 Ntiles, 64 Mtiles) ----
__global__ void __launch_bounds__(256, 2)
hmma_out_kernel(const float* __restrict__ out_scale, float* __restrict__ out)
{
    hmma_gemm_body<1>(g_rf, nullptr, g_wof, out,
                      D_, D_, V_, out_scale[0], blockIdx.y * 128, blockIdx.x * 128);
}

// ================= HMMA attention (bf16 3-pass, single fp16 r output) =================
#define AT_STRIDE 528
#define SW_STRIDE 144
#define SM_QH 0
#define SM_QL 33792
#define SM_KH 67584
#define SM_KL 101376
#define SM_VH 135168
#define SM_VL 168960
#define SM_SWH 202752
#define SM_SWL 211968
#define ATT_SMEM 221184

__global__ void __launch_bounds__(256, 1)
attn_hmma_kernel(const float* __restrict__ dlp)
{
    extern __shared__ __align__(128) char shm[];
    const int tid = threadIdx.x, lane = tid & 31, wid = tid >> 5;
    const int wm = wid >> 1, wn = wid & 1;
    const int ib = blockIdx.x, b = blockIdx.y;
    const uint32_t sb = smem_u32(shm);

    const float logit = dlp[0];
    const float decay = 1.f / (1.f + expf(-logit));
    const float l2d   = log2f(decay);

    const int qrow0 = b * T_ + ib * 64;

    #pragma unroll
    for (int it = 0; it < 8; ++it) {
        int idx = it * 256 + tid;
        int r = idx >> 5, s = idx & 31;
        uint32_t soff = r * AT_STRIDE + s * 16;
        size_t gb = ((size_t)(qrow0 + r) * D_) * 2 + s * 16;
        CP16(sb + SM_QH + soff, (const char*)g_qbh + gb);
        CP16(sb + SM_QL + soff, (const char*)g_qbl + gb);
    }
    CP_COMMIT();

    float oacc[8][2][4];
    #pragma unroll
    for (int a = 0; a < 8; ++a)
        #pragma unroll
        for (int g = 0; g < 2; ++g)
            #pragma unroll
            for (int e = 0; e < 4; ++e) oacc[a][g][e] = 0.f;

    const uint32_t offA  = (lane & 15) * AT_STRIDE + (lane >> 4) * 16;
    const uint32_t offB  = ((lane & 7) + ((lane >> 4) & 1) * 8) * AT_STRIDE
                         + ((lane >> 3) & 1) * 16;
    const uint32_t offAs = (lane & 15) * SW_STRIDE + (lane >> 4) * 16;
    const uint32_t offV  = ((lane & 7) + ((lane >> 3) & 1) * 8) * AT_STRIDE
                         + (lane >> 4) * 16;

    const int rl0 = wm * 16 + (lane >> 2);
    const float er0 = exp2f(-l2d * (float)rl0);
    const float er1 = er0 * exp2f(-l2d * 8.f);

    CP_WAIT0();
    __syncthreads();

    for (int jb = ib; jb < T_/64; ++jb) {
        int emin = (jb - ib) * 64 - 64;
        if (emin > 0 && l2d * (float)emin < -35.f) break;
        const int krow0 = b * T_ + jb * 64;

        #pragma unroll
        for (int it = 0; it < 8; ++it) {
            int idx = it * 256 + tid;
            int r = idx >> 5, s = idx & 31;
            uint32_t soff = r * AT_STRIDE + s * 16;
            size_t gb = ((size_t)(krow0 + r) * D_) * 2 + s * 16;
            CP16(sb + SM_KH + soff, (const char*)g_kbh + gb);
            CP16(sb + SM_KL + soff, (const char*)g_kbl + gb);
        }
        CP_COMMIT();
        #pragma unroll
        for (int it = 0; it < 8; ++it) {
            int idx = it * 256 + tid;
            int r = idx >> 5, s = idx & 31;
            uint32_t soff = r * AT_STRIDE + s * 16;
            size_t gb = ((size_t)(krow0 + r) * D_) * 2 + s * 16;
            CP16(sb + SM_VH + soff, (const char*)g_vbh + gb);
            CP16(sb + SM_VL + soff, (const char*)g_vbl + gb);
        }
        CP_COMMIT();
        CP_WAIT1();
        __syncthreads();

        float sacc[4][4];
        #pragma unroll
        for (int nf = 0; nf < 4; ++nf)
            #pragma unroll
            for (int e = 0; e < 4; ++e) sacc[nf][e] = 0.f;

        #pragma unroll 4
        for (int kf = 0; kf < 16; ++kf) {
            const uint32_t kb = kf * 32;
            uint32_t qh[4], ql[4], kh[2][4], kl[2][4];
            ldsm_x4(qh, sb + SM_QH + (wm*16) * AT_STRIDE + kb + offA);
            ldsm_x4(ql, sb + SM_QL + (wm*16) * AT_STRIDE + kb + offA);
            ldsm_x4(kh[0], sb + SM_KH + (wn*32)      * AT_STRIDE + kb + offB);
            ldsm_x4(kh[1], sb + SM_KH + (wn*32 + 16) * AT_STRIDE + kb + offB);
            ldsm_x4(kl[0], sb + SM_KL + (wn*32)      * AT_STRIDE + kb + offB);
            ldsm_x4(kl[1], sb + SM_KL + (wn*32 + 16) * AT_STRIDE + kb + offB);
            #pragma unroll
            for (int nf = 0; nf < 4; ++nf) {
                mma16816(sacc[nf], qh, kh[nf>>1][(nf&1)*2], kh[nf>>1][(nf&1)*2+1]);
                mma16816(sacc[nf], qh, kl[nf>>1][(nf&1)*2], kl[nf>>1][(nf&1)*2+1]);
                mma16816(sacc[nf], ql, kh[nf>>1][(nf&1)*2], kh[nf>>1][(nf&1)*2+1]);
            }
        }

        const float wbase = exp2f(l2d * (float)((jb - ib) * 64 - 1));
        const bool diag = (jb == ib);
        #pragma unroll
        for (int nf = 0; nf < 4; ++nf) {
            const int cl = wn*32 + nf*8 + (lane & 3)*2;
            float ec0 = exp2f(l2d * (float)cl);
            float ec1 = ec0 * decay;
            float w00 = wbase*ec0*er0, w01 = wbase*ec1*er0;
            float w10 = wbase*ec0*er1, w11 = wbase*ec1*er1;
            if (diag) {
                if (cl     <= rl0)     w00 = 0.f;
                if (cl + 1 <= rl0)     w01 = 0.f;
                if (cl     <= rl0 + 8) w10 = 0.f;
                if (cl + 1 <= rl0 + 8) w11 = 0.f;
            }
            float v00 = sacc[nf][0]*w00, v01 = sacc[nf][1]*w01;
            float v10 = sacc[nf][2]*w10, v11 = sacc[nf][3]*w11;

            #pragma unroll
            for (int h = 0; h < 2; ++h) {
                float a = h ? v10 : v00, c = h ? v11 : v01;
                __nv_bfloat16 ha, hc;
                uint32_t ph = pack_hilo_b(a, c, ha, hc);
                float ra = a - __bfloat162float(ha), rc = c - __bfloat162float(hc);
                __nv_bfloat16 t0, t1;
                uint32_t pl = pack_hilo_b(ra, rc, t0, t1);
                uint32_t off = (rl0 + h*8) * SW_STRIDE + cl * 2;
                *(uint32_t*)(shm + SM_SWH + off) = ph;
                *(uint32_t*)(shm + SM_SWL + off) = pl;
            }
        }

        CP_WAIT0();
        __syncthreads();

        uint32_t sh4[4][4], sl4[4][4];
        #pragma unroll
        for (int kf = 0; kf < 4; ++kf) {
            ldsm_x4(sh4[kf], sb + SM_SWH + (wm*16) * SW_STRIDE + kf*32 + offAs);
            ldsm_x4(sl4[kf], sb + SM_SWL + (wm*16) * SW_STRIDE + kf*32 + offAs);
        }
        #pragma unroll
        for (int nb = 0; nb < 8; ++nb) {
            const uint32_t d0b = (uint32_t)(wn*128 + nb*16) * 2;
            #pragma unroll
            for (int kf = 0; kf < 4; ++kf) {
                uint32_t vh[4], vl[4];
                const uint32_t va = sb + (kf*16) * AT_STRIDE + d0b + offV;
                ldsm_x4_t(vh, va + SM_VH);
                ldsm_x4_t(vl, va + SM_VL);
                mma16816(oacc[nb][0], sh4[kf], vh[0], vh[1]);
                mma16816(oacc[nb][1], sh4[kf], vh[2], vh[3]);
                mma16816(oacc[nb][0], sh4[kf], vl[0], vl[1]);
                mma16816(oacc[nb][1], sh4[kf], vl[2], vl[3]);
                mma16816(oacc[nb][0], sl4[kf], vh[0], vh[1]);
                mma16816(oacc[nb][1], sl4[kf], vh[2], vh[3]);
            }
        }
        __syncthreads();
    }

    // ---- fused epilogue: write r as single fp16 (1-pass out GEMM) ----
    const size_t rrow = (size_t)(qrow0 + wm*16 + (lane >> 2)) * D_;
    #pragma unroll
    for (int nb = 0; nb < 8; ++nb) {
        #pragma unroll
        for (int g = 0; g < 2; ++g) {
            const int c = wn*128 + nb*16 + g*8 + (lane & 3) * 2;
            #pragma unroll
            for (int h = 0; h < 2; ++h) {
                uint32_t ph = pack_h2(oacc[nb][g][h*2], oacc[nb][g][h*2+1]);
                *(uint32_t*)(g_rf + rrow + (size_t)h * 8 * D_ + c) = ph;
            }
        }
    }
}

// ================= launch =================
#define QKV_SMEM (2*20480)
#define OUT_SMEM (2*20480)

extern "C" void kernel_launch(void* const* d_in, const int* in_sizes, int n_in,
                              void* d_out, int out_size)
{
    const float* x  = (const float*)d_in[0];
    const float* wq = (const float*)d_in[1];
    const float* wk = (const float*)d_in[2];
    const float* wv = (const float*)d_in[3];
    const float* wo = (const float*)d_in[4];
    const float* dl = (const float*)d_in[5];
    const float* os = (const float*)d_in[6];
    float* out = (float*)d_out;

    cudaFuncSetAttribute(hmma_qkv_kernel, cudaFuncAttributeMaxDynamicSharedMemorySize, QKV_SMEM);
    cudaFuncSetAttribute(hmma_out_kernel, cudaFuncAttributeMaxDynamicSharedMemorySize, OUT_SMEM);
    cudaFuncSetAttribute(attn_hmma_kernel, cudaFuncAttributeMaxDynamicSharedMemorySize, ATT_SMEM);

    cvt_x_kernel<<<((size_t)M_*V_)/4096, 256>>>(x);
    cvt_w_kernel<<<4*512, 256>>>(wq, wk, wv, wo);

    hmma_qkv_kernel<<<dim3(2, 64, 6), 256, QKV_SMEM>>>();

    reduce_qkv_kernel<<<3*2048, 256>>>();

    attn_hmma_kernel<<<dim3(T_/64, B_), 256, ATT_SMEM>>>(dl);

    hmma_out_kernel<<<dim3(64, 64), 256, OUT_SMEM>>>(os, out);
}

// round 12
// speedup vs baseline: 2.7989x; 1.1177x over previous
#include <cuda_runtime.h>
#include <cuda_bf16.h>
#include <cuda_fp16.h>
#include <cstdint>

#define B_ 4
#define T_ 2048
#define V_ 8192
#define D_ 256
#define M_ (B_*T_)   // 8192 rows of (b,t)

// ---------------- scratch (device globals; no allocs allowed) ----------------
__device__ __half g_xf[(size_t)M_*V_];      // single fp16 x
__device__ __half g_wf[3*(size_t)D_*V_];
__device__ __half g_wof[(size_t)V_*D_];
__device__ __half g_rf[(size_t)M_*D_];      // single fp16 r

// split-K fp32 partials for qkv: 6 slabs of M_*D_ (z = w*2 + khalf)
__device__ float g_part[6*(size_t)M_*D_];

// bf16 hi/lo q,k,v (attention stays 3-pass bf16)
__device__ __nv_bfloat16 g_qbh[(size_t)M_*D_];
__device__ __nv_bfloat16 g_qbl[(size_t)M_*D_];
__device__ __nv_bfloat16 g_kbh[(size_t)M_*D_];
__device__ __nv_bfloat16 g_kbl[(size_t)M_*D_];
__device__ __nv_bfloat16 g_vbh[(size_t)M_*D_];
__device__ __nv_bfloat16 g_vbl[(size_t)M_*D_];

// ---------------- helpers ----------------
__device__ __forceinline__ uint32_t smem_u32(const void* p){
    uint32_t a;
    asm("{ .reg .u64 t; cvta.to.shared.u64 t, %1; cvt.u32.u64 %0, t; }" : "=r"(a) : "l"(p));
    return a;
}
#define CP16(smem, gptr) \
    asm volatile("cp.async.cg.shared.global [%0], [%1], 16;" :: "r"(smem), "l"(gptr))
#define CP_COMMIT() asm volatile("cp.async.commit_group;" ::: "memory")
#define CP_WAIT1()  asm volatile("cp.async.wait_group 1;" ::: "memory")
#define CP_WAIT0()  asm volatile("cp.async.wait_group 0;" ::: "memory")

__device__ __forceinline__ void ldsm_x4(uint32_t (&r)[4], uint32_t addr){
    asm volatile("ldmatrix.sync.aligned.m8n8.x4.shared.b16 {%0,%1,%2,%3}, [%4];"
        : "=r"(r[0]), "=r"(r[1]), "=r"(r[2]), "=r"(r[3]) : "r"(addr));
}
__device__ __forceinline__ void ldsm_x4_t(uint32_t (&r)[4], uint32_t addr){
    asm volatile("ldmatrix.sync.aligned.m8n8.x4.trans.shared.b16 {%0,%1,%2,%3}, [%4];"
        : "=r"(r[0]), "=r"(r[1]), "=r"(r[2]), "=r"(r[3]) : "r"(addr));
}
// bf16 mma (attention)
__device__ __forceinline__ void mma16816(float (&d)[4], const uint32_t (&a)[4],
                                         uint32_t b0, uint32_t b1){
    asm volatile("mma.sync.aligned.m16n8k16.row.col.f32.bf16.bf16.f32 "
        "{%0,%1,%2,%3}, {%4,%5,%6,%7}, {%8,%9}, {%0,%1,%2,%3};"
        : "+f"(d[0]), "+f"(d[1]), "+f"(d[2]), "+f"(d[3])
        : "r"(a[0]), "r"(a[1]), "r"(a[2]), "r"(a[3]), "r"(b0), "r"(b1));
}
// fp16 mma (projection GEMMs)
__device__ __forceinline__ void mma16816h(float (&d)[4], const uint32_t (&a)[4],
                                          uint32_t b0, uint32_t b1){
    asm volatile("mma.sync.aligned.m16n8k16.row.col.f32.f16.f16.f32 "
        "{%0,%1,%2,%3}, {%4,%5,%6,%7}, {%8,%9}, {%0,%1,%2,%3};"
        : "+f"(d[0]), "+f"(d[1]), "+f"(d[2]), "+f"(d[3])
        : "r"(a[0]), "r"(a[1]), "r"(a[2]), "r"(a[3]), "r"(b0), "r"(b1));
}
__device__ __forceinline__ uint32_t pack_hilo_b(float a, float c,
                                                __nv_bfloat16& ra, __nv_bfloat16& rc){
    ra = __float2bfloat16(a);
    rc = __float2bfloat16(c);
    return (uint32_t)*(uint16_t*)&ra | ((uint32_t)*(uint16_t*)&rc << 16);
}
__device__ __forceinline__ uint32_t pack_h2(float a, float c){
    __half ra = __float2half_rn(a);
    __half rc = __float2half_rn(c);
    return (uint32_t)*(uint16_t*)&ra | ((uint32_t)*(uint16_t*)&rc << 16);
}

// ================= conversion kernels =================
__global__ void __launch_bounds__(256)
cvt_x_kernel(const float* __restrict__ x)
{
    const size_t base = (size_t)blockIdx.x * 4096 + threadIdx.x * 4;
    float4 v[4];
    #pragma unroll
    for (int j = 0; j < 4; ++j) v[j] = *(const float4*)(x + base + j * 1024);
    #pragma unroll
    for (int j = 0; j < 4; ++j) {
        const size_t i = base + j * 1024;
        float f[4] = {v[j].x, v[j].y, v[j].z, v[j].w};
        union { __half b[4]; uint2 u; } H;
        #pragma unroll
        for (int e = 0; e < 4; ++e) H.b[e] = __float2half_rn(f[e]);
        *(uint2*)(g_xf + i) = H.u;
    }
}

__global__ void __launch_bounds__(256)
cvt_w_kernel(const float* __restrict__ wq, const float* __restrict__ wk,
             const float* __restrict__ wv, const float* __restrict__ wo)
{
    const int sel = blockIdx.x >> 9;
    const int blk = blockIdx.x & 511;
    const float* in;
    __half* outp;
    switch (sel) {
        case 0: in = wq; outp = g_wf;                 break;
        case 1: in = wk; outp = g_wf + (size_t)D_*V_;   break;
        case 2: in = wv; outp = g_wf + 2*(size_t)D_*V_; break;
        default: in = wo; outp = g_wof;               break;
    }
    const size_t base = (size_t)blk * 4096 + threadIdx.x * 4;
    float4 v[4];
    #pragma unroll
    for (int j = 0; j < 4; ++j) v[j] = *(const float4*)(in + base + j * 1024);
    #pragma unroll
    for (int j = 0; j < 4; ++j) {
        const size_t i = base + j * 1024;
        float f[4] = {v[j].x, v[j].y, v[j].z, v[j].w};
        union { __half b[4]; uint2 u; } H;
        #pragma unroll
        for (int e = 0; e < 4; ++e) H.b[e] = __float2half_rn(f[e]);
        *(uint2*)(outp + i) = H.u;
    }
}

// ================= split-K reduce: partials -> bf16 hi/lo q/k/v =================
__global__ void __launch_bounds__(256)
reduce_qkv_kernel()
{
    const int w   = blockIdx.x >> 11;
    const int blk = blockIdx.x & 2047;
    const size_t base = (size_t)blk * 1024 + threadIdx.x * 4;
    const float* p0 = g_part + (size_t)(2*w)   * ((size_t)M_*D_);
    const float* p1 = g_part + (size_t)(2*w+1) * ((size_t)M_*D_);
    __nv_bfloat16* hi = (w==0) ? g_qbh : (w==1) ? g_kbh : g_vbh;
    __nv_bfloat16* lo = (w==0) ? g_qbl : (w==1) ? g_kbl : g_vbl;
    float4 a = *(const float4*)(p0 + base);
    float4 b = *(const float4*)(p1 + base);
    float f[4] = {a.x+b.x, a.y+b.y, a.z+b.z, a.w+b.w};
    union { __nv_bfloat16 b[4]; uint2 u; } H, L;
    #pragma unroll
    for (int e = 0; e < 4; ++e) {
        __nv_bfloat16 h = __float2bfloat16(f[e]);
        float r = f[e] - __bfloat162float(h);
        H.b[e] = h;
        L.b[e] = __float2bfloat16(r);
    }
    *(uint2*)(hi + base) = H.u;
    *(uint2*)(lo + base) = L.u;
}

// ================= fp16 1-pass NT GEMM, BK=64 =================
// C = A[M,K](fp16) * B[N,K]^T(fp16) * scale, fp32 accum.
// CTA tile 128x128, BK=64, 256 threads, warp tile 64x32 (2x4 warps).
#define LDS_B 144                 // 128 B data + 16 B pad per row
#define GSTG  36864               // (128 A rows + 128 B rows) * 144
#define GT_B  18432

__device__ __forceinline__ void hmma_gemm_body(
    const __half* __restrict__ Ag, const __half* __restrict__ Bg,
    float* __restrict__ Cf,
    int K, int ldAB, int ldC, float scale, int row0, int col0)
{
    extern __shared__ __align__(128) char sm[];
    const int tid  = threadIdx.x;
    const int lane = tid & 31;
    const int wid  = tid >> 5;
    const int wm   = wid >> 2;
    const int wn   = wid & 3;
    const uint32_t sbase = smem_u32(sm);

    float acc[4][4][4];
    #pragma unroll
    for (int a = 0; a < 4; ++a)
        #pragma unroll
        for (int b = 0; b < 4; ++b)
            #pragma unroll
            for (int c = 0; c < 4; ++c) acc[a][b][c] = 0.f;

    // 128 rows x 8 segs of 16B per operand; 1024 transfers / 256 threads = 4 each
    auto load_stage = [&](int c, int s){
        const uint32_t sb = sbase + s * GSTG;
        #pragma unroll
        for (int q = 0; q < 4; ++q) {
            const int idx = tid + q * 256;
            const int r = idx >> 3, seg = idx & 7;
            const size_t k0 = (size_t)c * 64 + seg * 8;
            const uint32_t soff = r * LDS_B + seg * 16;
            CP16(sb + soff,        Ag + (size_t)(row0 + r) * ldAB + k0);
            CP16(sb + GT_B + soff, Bg + (size_t)(col0 + r) * ldAB + k0);
        }
    };

    const uint32_t offA = (lane & 15) * LDS_B + (lane >> 4) * 16;
    const uint32_t offB = ((lane & 7) + ((lane >> 4) & 1) * 8) * LDS_B
                        + ((lane >> 3) & 1) * 16;

    const int NC = K / 64;

    load_stage(0, 0);
    CP_COMMIT();

    for (int c = 0; c < NC; ++c) {
        if (c + 1 < NC) { load_stage(c + 1, (c + 1) & 1); CP_COMMIT(); CP_WAIT1(); }
        else            { CP_WAIT0(); }
        __syncthreads();

        const uint32_t sb = sbase + (c & 1) * GSTG;
        #pragma unroll
        for (int kk = 0; kk < 4; ++kk) {
            const uint32_t kb = kk * 32;   // 16 fp16 = 32 B per k-step
            uint32_t ah[4][4], bb[2][4];
            #pragma unroll
            for (int mf = 0; mf < 4; ++mf)
                ldsm_x4(ah[mf], sb + (wm*64 + mf*16) * LDS_B + kb + offA);
            #pragma unroll
            for (int g = 0; g < 2; ++g)
                ldsm_x4(bb[g], sb + GT_B + (wn*32 + g*16) * LDS_B + kb + offB);
            #pragma unroll
            for (int mf = 0; mf < 4; ++mf)
                #pragma unroll
                for (int nf = 0; nf < 4; ++nf)
                    mma16816h(acc[mf][nf], ah[mf], bb[nf>>1][(nf&1)*2], bb[nf>>1][(nf&1)*2+1]);
        }
        __syncthreads();
    }

    #pragma unroll
    for (int mf = 0; mf < 4; ++mf) {
        const int r0 = row0 + wm*64 + mf*16 + (lane >> 2);
        #pragma unroll
        for (int nf = 0; nf < 4; ++nf) {
            const int cc = col0 + wn*32 + nf*8 + (lane & 3) * 2;
            float2 v0 = { acc[mf][nf][0] * scale, acc[mf][nf][1] * scale };
            float2 v1 = { acc[mf][nf][2] * scale, acc[mf][nf][3] * scale };
            *(float2*)(Cf + (size_t)r0 * ldC + cc)       = v0;
            *(float2*)(Cf + (size_t)(r0 + 8) * ldC + cc) = v1;
        }
    }
}

// ---- QKV split-K: grid (2 Ntiles, 64 Mtiles, 6 = weight*2 + khalf) ----
__global__ void __launch_bounds__(256, 2)
hmma_qkv_kernel()
{
    const int z = blockIdx.z;
    const int w = z >> 1, kh = z & 1;
    const size_t koff = (size_t)kh * 4096;
    const __half* Bg = g_wf + (size_t)w * D_ * V_ + koff;
    float* Cf = g_part + (size_t)z * ((size_t)M_*D_);
    hmma_gemm_body(g_xf + koff, Bg, Cf,
                   4096, V_, D_, 1.0f, blockIdx.y * 128, blockIdx.x * 128);
}

// ---- OUT: grid (64 Ntiles, 64 Mtiles) ----
__global__ void __launch_bounds__(256, 2)
hmma_out_kernel(const float* __restrict__ out_scale, float* __restrict__ out)
{
    hmma_gemm_body(g_rf, g_wof, out,
                   D_, D_, V_, out_scale[0], blockIdx.y * 128, blockIdx.x * 128);
}

// ================= HMMA attention (bf16 3-pass, single fp16 r output) =================
#define AT_STRIDE 528
#define SW_STRIDE 144
#define SM_QH 0
#define SM_QL 33792
#define SM_KH 67584
#define SM_KL 101376
#define SM_VH 135168
#define SM_VL 168960
#define SM_SWH 202752
#define SM_SWL 211968
#define ATT_SMEM 221184

__global__ void __launch_bounds__(256, 1)
attn_hmma_kernel(const float* __restrict__ dlp)
{
    extern __shared__ __align__(128) char shm[];
    const int tid = threadIdx.x, lane = tid & 31, wid = tid >> 5;
    const int wm = wid >> 1, wn = wid & 1;
    const int ib = blockIdx.x, b = blockIdx.y;
    const uint32_t sb = smem_u32(shm);

    const float logit = dlp[0];
    const float decay = 1.f / (1.f + expf(-logit));
    const float l2d   = log2f(decay);

    const int qrow0 = b * T_ + ib * 64;

    #pragma unroll
    for (int it = 0; it < 8; ++it) {
        int idx = it * 256 + tid;
        int r = idx >> 5, s = idx & 31;
        uint32_t soff = r * AT_STRIDE + s * 16;
        size_t gb = ((size_t)(qrow0 + r) * D_) * 2 + s * 16;
        CP16(sb + SM_QH + soff, (const char*)g_qbh + gb);
        CP16(sb + SM_QL + soff, (const char*)g_qbl + gb);
    }
    CP_COMMIT();

    float oacc[8][2][4];
    #pragma unroll
    for (int a = 0; a < 8; ++a)
        #pragma unroll
        for (int g = 0; g < 2; ++g)
            #pragma unroll
            for (int e = 0; e < 4; ++e) oacc[a][g][e] = 0.f;

    const uint32_t offA  = (lane & 15) * AT_STRIDE + (lane >> 4) * 16;
    const uint32_t offB  = ((lane & 7) + ((lane >> 4) & 1) * 8) * AT_STRIDE
                         + ((lane >> 3) & 1) * 16;
    const uint32_t offAs = (lane & 15) * SW_STRIDE + (lane >> 4) * 16;
    const uint32_t offV  = ((lane & 7) + ((lane >> 3) & 1) * 8) * AT_STRIDE
                         + (lane >> 4) * 16;

    const int rl0 = wm * 16 + (lane >> 2);
    const float er0 = exp2f(-l2d * (float)rl0);
    const float er1 = er0 * exp2f(-l2d * 8.f);

    CP_WAIT0();
    __syncthreads();

    for (int jb = ib; jb < T_/64; ++jb) {
        int emin = (jb - ib) * 64 - 64;
        if (emin > 0 && l2d * (float)emin < -30.f) break;
        const int krow0 = b * T_ + jb * 64;

        #pragma unroll
        for (int it = 0; it < 8; ++it) {
            int idx = it * 256 + tid;
            int r = idx >> 5, s = idx & 31;
            uint32_t soff = r * AT_STRIDE + s * 16;
            size_t gb = ((size_t)(krow0 + r) * D_) * 2 + s * 16;
            CP16(sb + SM_KH + soff, (const char*)g_kbh + gb);
            CP16(sb + SM_KL + soff, (const char*)g_kbl + gb);
        }
        CP_COMMIT();
        #pragma unroll
        for (int it = 0; it < 8; ++it) {
            int idx = it * 256 + tid;
            int r = idx >> 5, s = idx & 31;
            uint32_t soff = r * AT_STRIDE + s * 16;
            size_t gb = ((size_t)(krow0 + r) * D_) * 2 + s * 16;
            CP16(sb + SM_VH + soff, (const char*)g_vbh + gb);
            CP16(sb + SM_VL + soff, (const char*)g_vbl + gb);
        }
        CP_COMMIT();
        CP_WAIT1();
        __syncthreads();

        float sacc[4][4];
        #pragma unroll
        for (int nf = 0; nf < 4; ++nf)
            #pragma unroll
            for (int e = 0; e < 4; ++e) sacc[nf][e] = 0.f;

        #pragma unroll 4
        for (int kf = 0; kf < 16; ++kf) {
            const uint32_t kb = kf * 32;
            uint32_t qh[4], ql[4], kh[2][4], kl[2][4];
            ldsm_x4(qh, sb + SM_QH + (wm*16) * AT_STRIDE + kb + offA);
            ldsm_x4(ql, sb + SM_QL + (wm*16) * AT_STRIDE + kb + offA);
            ldsm_x4(kh[0], sb + SM_KH + (wn*32)      * AT_STRIDE + kb + offB);
            ldsm_x4(kh[1], sb + SM_KH + (wn*32 + 16) * AT_STRIDE + kb + offB);
            ldsm_x4(kl[0], sb + SM_KL + (wn*32)      * AT_STRIDE + kb + offB);
            ldsm_x4(kl[1], sb + SM_KL + (wn*32 + 16) * AT_STRIDE + kb + offB);
            #pragma unroll
            for (int nf = 0; nf < 4; ++nf) {
                mma16816(sacc[nf], qh, kh[nf>>1][(nf&1)*2], kh[nf>>1][(nf&1)*2+1]);
                mma16816(sacc[nf], qh, kl[nf>>1][(nf&1)*2], kl[nf>>1][(nf&1)*2+1]);
                mma16816(sacc[nf], ql, kh[nf>>1][(nf&1)*2], kh[nf>>1][(nf&1)*2+1]);
            }
        }

        const float wbase = exp2f(l2d * (float)((jb - ib) * 64 - 1));
        const bool diag = (jb == ib);
        #pragma unroll
        for (int nf = 0; nf < 4; ++nf) {
            const int cl = wn*32 + nf*8 + (lane & 3)*2;
            float ec0 = exp2f(l2d * (float)cl);
            float ec1 = ec0 * decay;
            float w00 = wbase*ec0*er0, w01 = wbase*ec1*er0;
            float w10 = wbase*ec0*er1, w11 = wbase*ec1*er1;
            if (diag) {
                if (cl     <= rl0)     w00 = 0.f;
                if (cl + 1 <= rl0)     w01 = 0.f;
                if (cl     <= rl0 + 8) w10 = 0.f;
                if (cl + 1 <= rl0 + 8) w11 = 0.f;
            }
            float v00 = sacc[nf][0]*w00, v01 = sacc[nf][1]*w01;
            float v10 = sacc[nf][2]*w10, v11 = sacc[nf][3]*w11;

            #pragma unroll
            for (int h = 0; h < 2; ++h) {
                float a = h ? v10 : v00, c = h ? v11 : v01;
                __nv_bfloat16 ha, hc;
                uint32_t ph = pack_hilo_b(a, c, ha, hc);
                float ra = a - __bfloat162float(ha), rc = c - __bfloat162float(hc);
                __nv_bfloat16 t0, t1;
                uint32_t pl = pack_hilo_b(ra, rc, t0, t1);
                uint32_t off = (rl0 + h*8) * SW_STRIDE + cl * 2;
                *(uint32_t*)(shm + SM_SWH + off) = ph;
                *(uint32_t*)(shm + SM_SWL + off) = pl;
            }
        }

        CP_WAIT0();
        __syncthreads();

        uint32_t sh4[4][4], sl4[4][4];
        #pragma unroll
        for (int kf = 0; kf < 4; ++kf) {
            ldsm_x4(sh4[kf], sb + SM_SWH + (wm*16) * SW_STRIDE + kf*32 + offAs);
            ldsm_x4(sl4[kf], sb + SM_SWL + (wm*16) * SW_STRIDE + kf*32 + offAs);
        }
        #pragma unroll
        for (int nb = 0; nb < 8; ++nb) {
            const uint32_t d0b = (uint32_t)(wn*128 + nb*16) * 2;
            #pragma unroll
            for (int kf = 0; kf < 4; ++kf) {
                uint32_t vh[4], vl[4];
                const uint32_t va = sb + (kf*16) * AT_STRIDE + d0b + offV;
                ldsm_x4_t(vh, va + SM_VH);
                ldsm_x4_t(vl, va + SM_VL);
                mma16816(oacc[nb][0], sh4[kf], vh[0], vh[1]);
                mma16816(oacc[nb][1], sh4[kf], vh[2], vh[3]);
                mma16816(oacc[nb][0], sh4[kf], vl[0], vl[1]);
                mma16816(oacc[nb][1], sh4[kf], vl[2], vl[3]);
                mma16816(oacc[nb][0], sl4[kf], vh[0], vh[1]);
                mma16816(oacc[nb][1], sl4[kf], vh[2], vh[3]);
            }
        }
        __syncthreads();
    }

    // ---- fused epilogue: write r as single fp16 ----
    const size_t rrow = (size_t)(qrow0 + wm*16 + (lane >> 2)) * D_;
    #pragma unroll
    for (int nb = 0; nb < 8; ++nb) {
        #pragma unroll
        for (int g = 0; g < 2; ++g) {
            const int c = wn*128 + nb*16 + g*8 + (lane & 3) * 2;
            #pragma unroll
            for (int h = 0; h < 2; ++h) {
                uint32_t ph = pack_h2(oacc[nb][g][h*2], oacc[nb][g][h*2+1]);
                *(uint32_t*)(g_rf + rrow + (size_t)h * 8 * D_ + c) = ph;
            }
        }
    }
}

// ================= launch =================
#define GEMM_SMEM (2*GSTG)

extern "C" void kernel_launch(void* const* d_in, const int* in_sizes, int n_in,
                              void* d_out, int out_size)
{
    const float* x  = (const float*)d_in[0];
    const float* wq = (const float*)d_in[1];
    const float* wk = (const float*)d_in[2];
    const float* wv = (const float*)d_in[3];
    const float* wo = (const float*)d_in[4];
    const float* dl = (const float*)d_in[5];
    const float* os = (const float*)d_in[6];
    float* out = (float*)d_out;

    cudaFuncSetAttribute(hmma_qkv_kernel, cudaFuncAttributeMaxDynamicSharedMemorySize, GEMM_SMEM);
    cudaFuncSetAttribute(hmma_out_kernel, cudaFuncAttributeMaxDynamicSharedMemorySize, GEMM_SMEM);
    cudaFuncSetAttribute(attn_hmma_kernel, cudaFuncAttributeMaxDynamicSharedMemorySize, ATT_SMEM);

    cvt_x_kernel<<<((size_t)M_*V_)/4096, 256>>>(x);
    cvt_w_kernel<<<4*512, 256>>>(wq, wk, wv, wo);

    hmma_qkv_kernel<<<dim3(2, 64, 6), 256, GEMM_SMEM>>>();

    reduce_qkv_kernel<<<3*2048, 256>>>();

    attn_hmma_kernel<<<dim3(T_/64, B_), 256, ATT_SMEM>>>(dl);

    hmma_out_kernel<<<dim3(64, 64), 256, GEMM_SMEM>>>(os, out);
}

// round 13
// speedup vs baseline: 3.1232x; 1.1159x over previous
#include <cuda_runtime.h>
#include <cuda_bf16.h>
#include <cuda_fp16.h>
#include <cstdint>

#define B_ 4
#define T_ 2048
#define V_ 8192
#define D_ 256
#define M_ (B_*T_)   // 8192 rows of (b,t)

// ---------------- scratch (device globals; no allocs allowed) ----------------
__device__ __half g_xf[(size_t)M_*V_];      // single fp16 x
__device__ __half g_wf[3*(size_t)D_*V_];
__device__ __half g_wof[(size_t)V_*D_];
__device__ __half g_rf[(size_t)M_*D_];      // single fp16 r

// split-K fp32 partials for qkv: 6 slabs of M_*D_ (z = w*2 + khalf)
__device__ float g_part[6*(size_t)M_*D_];

// bf16 hi/lo q,k,v (attention stays 3-pass bf16)
__device__ __nv_bfloat16 g_qbh[(size_t)M_*D_];
__device__ __nv_bfloat16 g_qbl[(size_t)M_*D_];
__device__ __nv_bfloat16 g_kbh[(size_t)M_*D_];
__device__ __nv_bfloat16 g_kbl[(size_t)M_*D_];
__device__ __nv_bfloat16 g_vbh[(size_t)M_*D_];
__device__ __nv_bfloat16 g_vbl[(size_t)M_*D_];

// ---------------- helpers ----------------
__device__ __forceinline__ uint32_t smem_u32(const void* p){
    uint32_t a;
    asm("{ .reg .u64 t; cvta.to.shared.u64 t, %1; cvt.u32.u64 %0, t; }" : "=r"(a) : "l"(p));
    return a;
}
#define CP16(smem, gptr) \
    asm volatile("cp.async.cg.shared.global [%0], [%1], 16;" :: "r"(smem), "l"(gptr))
#define CP_COMMIT() asm volatile("cp.async.commit_group;" ::: "memory")
#define CP_WAIT1()  asm volatile("cp.async.wait_group 1;" ::: "memory")
#define CP_WAIT0()  asm volatile("cp.async.wait_group 0;" ::: "memory")

__device__ __forceinline__ void ldsm_x4(uint32_t (&r)[4], uint32_t addr){
    asm volatile("ldmatrix.sync.aligned.m8n8.x4.shared.b16 {%0,%1,%2,%3}, [%4];"
        : "=r"(r[0]), "=r"(r[1]), "=r"(r[2]), "=r"(r[3]) : "r"(addr));
}
__device__ __forceinline__ void ldsm_x4_t(uint32_t (&r)[4], uint32_t addr){
    asm volatile("ldmatrix.sync.aligned.m8n8.x4.trans.shared.b16 {%0,%1,%2,%3}, [%4];"
        : "=r"(r[0]), "=r"(r[1]), "=r"(r[2]), "=r"(r[3]) : "r"(addr));
}
// bf16 mma (attention)
__device__ __forceinline__ void mma16816(float (&d)[4], const uint32_t (&a)[4],
                                         uint32_t b0, uint32_t b1){
    asm volatile("mma.sync.aligned.m16n8k16.row.col.f32.bf16.bf16.f32 "
        "{%0,%1,%2,%3}, {%4,%5,%6,%7}, {%8,%9}, {%0,%1,%2,%3};"
        : "+f"(d[0]), "+f"(d[1]), "+f"(d[2]), "+f"(d[3])
        : "r"(a[0]), "r"(a[1]), "r"(a[2]), "r"(a[3]), "r"(b0), "r"(b1));
}
// fp16 mma (projection GEMMs)
__device__ __forceinline__ void mma16816h(float (&d)[4], const uint32_t (&a)[4],
                                          uint32_t b0, uint32_t b1){
    asm volatile("mma.sync.aligned.m16n8k16.row.col.f32.f16.f16.f32 "
        "{%0,%1,%2,%3}, {%4,%5,%6,%7}, {%8,%9}, {%0,%1,%2,%3};"
        : "+f"(d[0]), "+f"(d[1]), "+f"(d[2]), "+f"(d[3])
        : "r"(a[0]), "r"(a[1]), "r"(a[2]), "r"(a[3]), "r"(b0), "r"(b1));
}
__device__ __forceinline__ uint32_t pack_hilo_b(float a, float c,
                                                __nv_bfloat16& ra, __nv_bfloat16& rc){
    ra = __float2bfloat16(a);
    rc = __float2bfloat16(c);
    return (uint32_t)*(uint16_t*)&ra | ((uint32_t)*(uint16_t*)&rc << 16);
}
__device__ __forceinline__ uint32_t pack_h2(float a, float c){
    __half ra = __float2half_rn(a);
    __half rc = __float2half_rn(c);
    return (uint32_t)*(uint16_t*)&ra | ((uint32_t)*(uint16_t*)&rc << 16);
}

// ================= conversion kernels =================
__global__ void __launch_bounds__(256)
cvt_x_kernel(const float* __restrict__ x)
{
    const size_t base = (size_t)blockIdx.x * 4096 + threadIdx.x * 4;
    float4 v[4];
    #pragma unroll
    for (int j = 0; j < 4; ++j) v[j] = *(const float4*)(x + base + j * 1024);
    #pragma unroll
    for (int j = 0; j < 4; ++j) {
        const size_t i = base + j * 1024;
        float f[4] = {v[j].x, v[j].y, v[j].z, v[j].w};
        union { __half b[4]; uint2 u; } H;
        #pragma unroll
        for (int e = 0; e < 4; ++e) H.b[e] = __float2half_rn(f[e]);
        *(uint2*)(g_xf + i) = H.u;
    }
}

__global__ void __launch_bounds__(256)
cvt_w_kernel(const float* __restrict__ wq, const float* __restrict__ wk,
             const float* __restrict__ wv, const float* __restrict__ wo)
{
    const int sel = blockIdx.x >> 9;
    const int blk = blockIdx.x & 511;
    const float* in;
    __half* outp;
    switch (sel) {
        case 0: in = wq; outp = g_wf;                 break;
        case 1: in = wk; outp = g_wf + (size_t)D_*V_;   break;
        case 2: in = wv; outp = g_wf + 2*(size_t)D_*V_; break;
        default: in = wo; outp = g_wof;               break;
    }
    const size_t base = (size_t)blk * 4096 + threadIdx.x * 4;
    float4 v[4];
    #pragma unroll
    for (int j = 0; j < 4; ++j) v[j] = *(const float4*)(in + base + j * 1024);
    #pragma unroll
    for (int j = 0; j < 4; ++j) {
        const size_t i = base + j * 1024;
        float f[4] = {v[j].x, v[j].y, v[j].z, v[j].w};
        union { __half b[4]; uint2 u; } H;
        #pragma unroll
        for (int e = 0; e < 4; ++e) H.b[e] = __float2half_rn(f[e]);
        *(uint2*)(outp + i) = H.u;
    }
}

// ================= split-K reduce: partials -> bf16 hi/lo q/k/v =================
__global__ void __launch_bounds__(256)
reduce_qkv_kernel()
{
    const int w   = blockIdx.x >> 11;
    const int blk = blockIdx.x & 2047;
    const size_t base = (size_t)blk * 1024 + threadIdx.x * 4;
    const float* p0 = g_part + (size_t)(2*w)   * ((size_t)M_*D_);
    const float* p1 = g_part + (size_t)(2*w+1) * ((size_t)M_*D_);
    __nv_bfloat16* hi = (w==0) ? g_qbh : (w==1) ? g_kbh : g_vbh;
    __nv_bfloat16* lo = (w==0) ? g_qbl : (w==1) ? g_kbl : g_vbl;
    float4 a = *(const float4*)(p0 + base);
    float4 b = *(const float4*)(p1 + base);
    float f[4] = {a.x+b.x, a.y+b.y, a.z+b.z, a.w+b.w};
    union { __nv_bfloat16 b[4]; uint2 u; } H, L;
    #pragma unroll
    for (int e = 0; e < 4; ++e) {
        __nv_bfloat16 h = __float2bfloat16(f[e]);
        float r = f[e] - __bfloat162float(h);
        H.b[e] = h;
        L.b[e] = __float2bfloat16(r);
    }
    *(uint2*)(hi + base) = H.u;
    *(uint2*)(lo + base) = L.u;
}

// ================= fp16 1-pass NT GEMM, BK=64, 3-stage cp.async ring =================
// C = A[M,K](fp16) * B[N,K]^T(fp16) * scale, fp32 accum.
// CTA tile 128x128, BK=64, 256 threads, warp tile 64x32 (2x4 warps).
#define LDS_B 144                 // 128 B data + 16 B pad per row
#define GSTG  36864               // (128 A rows + 128 B rows) * 144
#define GT_B  18432
#define NSTAGE 3

__device__ __forceinline__ void hmma_gemm_body(
    const __half* __restrict__ Ag, const __half* __restrict__ Bg,
    float* __restrict__ Cf,
    int K, int ldAB, int ldC, float scale, int row0, int col0)
{
    extern __shared__ __align__(128) char sm[];
    const int tid  = threadIdx.x;
    const int lane = tid & 31;
    const int wid  = tid >> 5;
    const int wm   = wid >> 2;
    const int wn   = wid & 3;
    const uint32_t sbase = smem_u32(sm);

    float acc[4][4][4];
    #pragma unroll
    for (int a = 0; a < 4; ++a)
        #pragma unroll
        for (int b = 0; b < 4; ++b)
            #pragma unroll
            for (int c = 0; c < 4; ++c) acc[a][b][c] = 0.f;

    // 128 rows x 8 segs of 16B per operand; 1024 transfers / 256 threads = 4 each
    auto load_stage = [&](int c, int s){
        const uint32_t sb = sbase + s * GSTG;
        #pragma unroll
        for (int q = 0; q < 4; ++q) {
            const int idx = tid + q * 256;
            const int r = idx >> 3, seg = idx & 7;
            const size_t k0 = (size_t)c * 64 + seg * 8;
            const uint32_t soff = r * LDS_B + seg * 16;
            CP16(sb + soff,        Ag + (size_t)(row0 + r) * ldAB + k0);
            CP16(sb + GT_B + soff, Bg + (size_t)(col0 + r) * ldAB + k0);
        }
    };

    const uint32_t offA = (lane & 15) * LDS_B + (lane >> 4) * 16;
    const uint32_t offB = ((lane & 7) + ((lane >> 4) & 1) * 8) * LDS_B
                        + ((lane >> 3) & 1) * 16;

    const int NC = K / 64;

    // prologue: fill 2 stages
    load_stage(0, 0); CP_COMMIT();
    if (NC > 1) { load_stage(1, 1); CP_COMMIT(); }

    int sidx = 0;                     // stage slot for chunk c
    for (int c = 0; c < NC; ++c) {
        if (c + 1 < NC) CP_WAIT1();   // stage c complete (stage c+1 may be in flight)
        else            CP_WAIT0();
        __syncthreads();              // one sync: data visible + prior-iter reads done

        const uint32_t sb = sbase + sidx * GSTG;
        #pragma unroll
        for (int kk = 0; kk < 4; ++kk) {
            const uint32_t kb = kk * 32;   // 16 fp16 = 32 B per k-step
            uint32_t ah[4][4], bb[2][4];
            #pragma unroll
            for (int mf = 0; mf < 4; ++mf)
                ldsm_x4(ah[mf], sb + (wm*64 + mf*16) * LDS_B + kb + offA);
            #pragma unroll
            for (int g = 0; g < 2; ++g)
                ldsm_x4(bb[g], sb + GT_B + (wn*32 + g*16) * LDS_B + kb + offB);
            #pragma unroll
            for (int mf = 0; mf < 4; ++mf)
                #pragma unroll
                for (int nf = 0; nf < 4; ++nf)
                    mma16816h(acc[mf][nf], ah[mf], bb[nf>>1][(nf&1)*2], bb[nf>>1][(nf&1)*2+1]);
        }

        if (c + 2 < NC) {
            int s2 = sidx + 2; if (s2 >= NSTAGE) s2 -= NSTAGE;
            load_stage(c + 2, s2);
            CP_COMMIT();
        }
        if (++sidx == NSTAGE) sidx = 0;
    }

    #pragma unroll
    for (int mf = 0; mf < 4; ++mf) {
        const int r0 = row0 + wm*64 + mf*16 + (lane >> 2);
        #pragma unroll
        for (int nf = 0; nf < 4; ++nf) {
            const int cc = col0 + wn*32 + nf*8 + (lane & 3) * 2;
            float2 v0 = { acc[mf][nf][0] * scale, acc[mf][nf][1] * scale };
            float2 v1 = { acc[mf][nf][2] * scale, acc[mf][nf][3] * scale };
            *(float2*)(Cf + (size_t)r0 * ldC + cc)       = v0;
            *(float2*)(Cf + (size_t)(r0 + 8) * ldC + cc) = v1;
        }
    }
}

// ---- QKV split-K: grid (2 Ntiles, 64 Mtiles, 6 = weight*2 + khalf) ----
__global__ void __launch_bounds__(256, 2)
hmma_qkv_kernel()
{
    const int z = blockIdx.z;
    const int w = z >> 1, kh = z & 1;
    const size_t koff = (size_t)kh * 4096;
    const __half* Bg = g_wf + (size_t)w * D_ * V_ + koff;
    float* Cf = g_part + (size_t)z * ((size_t)M_*D_);
    hmma_gemm_body(g_xf + koff, Bg, Cf,
                   4096, V_, D_, 1.0f, blockIdx.y * 128, blockIdx.x * 128);
}

// ---- OUT: grid (64 Ntiles, 64 Mtiles) ----
__global__ void __launch_bounds__(256, 2)
hmma_out_kernel(const float* __restrict__ out_scale, float* __restrict__ out)
{
    hmma_gemm_body(g_rf, g_wof, out,
                   D_, D_, V_, out_scale[0], blockIdx.y * 128, blockIdx.x * 128);
}

// ================= HMMA attention (bf16 3-pass, single fp16 r output) =================
#define AT_STRIDE 528
#define SW_STRIDE 144
#define SM_QH 0
#define SM_QL 33792
#define SM_KH 67584
#define SM_KL 101376
#define SM_VH 135168
#define SM_VL 168960
#define SM_SWH 202752
#define SM_SWL 211968
#define ATT_SMEM 221184

__global__ void __launch_bounds__(256, 1)
attn_hmma_kernel(const float* __restrict__ dlp)
{
    extern __shared__ __align__(128) char shm[];
    const int tid = threadIdx.x, lane = tid & 31, wid = tid >> 5;
    const int wm = wid >> 1, wn = wid & 1;
    const int ib = blockIdx.x, b = blockIdx.y;
    const uint32_t sb = smem_u32(shm);

    const float logit = dlp[0];
    const float decay = 1.f / (1.f + expf(-logit));
    const float l2d   = log2f(decay);

    const int qrow0 = b * T_ + ib * 64;

    #pragma unroll
    for (int it = 0; it < 8; ++it) {
        int idx = it * 256 + tid;
        int r = idx >> 5, s = idx & 31;
        uint32_t soff = r * AT_STRIDE + s * 16;
        size_t gb = ((size_t)(qrow0 + r) * D_) * 2 + s * 16;
        CP16(sb + SM_QH + soff, (const char*)g_qbh + gb);
        CP16(sb + SM_QL + soff, (const char*)g_qbl + gb);
    }
    CP_COMMIT();

    float oacc[8][2][4];
    #pragma unroll
    for (int a = 0; a < 8; ++a)
        #pragma unroll
        for (int g = 0; g < 2; ++g)
            #pragma unroll
            for (int e = 0; e < 4; ++e) oacc[a][g][e] = 0.f;

    const uint32_t offA  = (lane & 15) * AT_STRIDE + (lane >> 4) * 16;
    const uint32_t offB  = ((lane & 7) + ((lane >> 4) & 1) * 8) * AT_STRIDE
                         + ((lane >> 3) & 1) * 16;
    const uint32_t offAs = (lane & 15) * SW_STRIDE + (lane >> 4) * 16;
    const uint32_t offV  = ((lane & 7) + ((lane >> 3) & 1) * 8) * AT_STRIDE
                         + (lane >> 4) * 16;

    const int rl0 = wm * 16 + (lane >> 2);
    const float er0 = exp2f(-l2d * (float)rl0);
    const float er1 = er0 * exp2f(-l2d * 8.f);

    CP_WAIT0();
    __syncthreads();

    for (int jb = ib; jb < T_/64; ++jb) {
        int emin = (jb - ib) * 64 - 64;
        if (emin > 0 && l2d * (float)emin < -20.f) break;
        const int krow0 = b * T_ + jb * 64;

        #pragma unroll
        for (int it = 0; it < 8; ++it) {
            int idx = it * 256 + tid;
            int r = idx >> 5, s = idx & 31;
            uint32_t soff = r * AT_STRIDE + s * 16;
            size_t gb = ((size_t)(krow0 + r) * D_) * 2 + s * 16;
            CP16(sb + SM_KH + soff, (const char*)g_kbh + gb);
            CP16(sb + SM_KL + soff, (const char*)g_kbl + gb);
        }
        CP_COMMIT();
        #pragma unroll
        for (int it = 0; it < 8; ++it) {
            int idx = it * 256 + tid;
            int r = idx >> 5, s = idx & 31;
            uint32_t soff = r * AT_STRIDE + s * 16;
            size_t gb = ((size_t)(krow0 + r) * D_) * 2 + s * 16;
            CP16(sb + SM_VH + soff, (const char*)g_vbh + gb);
            CP16(sb + SM_VL + soff, (const char*)g_vbl + gb);
        }
        CP_COMMIT();
        CP_WAIT1();
        __syncthreads();

        float sacc[4][4];
        #pragma unroll
        for (int nf = 0; nf < 4; ++nf)
            #pragma unroll
            for (int e = 0; e < 4; ++e) sacc[nf][e] = 0.f;

        #pragma unroll 4
        for (int kf = 0; kf < 16; ++kf) {
            const uint32_t kb = kf * 32;
            uint32_t qh[4], ql[4], kh[2][4], kl[2][4];
            ldsm_x4(qh, sb + SM_QH + (wm*16) * AT_STRIDE + kb + offA);
            ldsm_x4(ql, sb + SM_QL + (wm*16) * AT_STRIDE + kb + offA);
            ldsm_x4(kh[0], sb + SM_KH + (wn*32)      * AT_STRIDE + kb + offB);
            ldsm_x4(kh[1], sb + SM_KH + (wn*32 + 16) * AT_STRIDE + kb + offB);
            ldsm_x4(kl[0], sb + SM_KL + (wn*32)      * AT_STRIDE + kb + offB);
            ldsm_x4(kl[1], sb + SM_KL + (wn*32 + 16) * AT_STRIDE + kb + offB);
            #pragma unroll
            for (int nf = 0; nf < 4; ++nf) {
                mma16816(sacc[nf], qh, kh[nf>>1][(nf&1)*2], kh[nf>>1][(nf&1)*2+1]);
                mma16816(sacc[nf], qh, kl[nf>>1][(nf&1)*2], kl[nf>>1][(nf&1)*2+1]);
                mma16816(sacc[nf], ql, kh[nf>>1][(nf&1)*2], kh[nf>>1][(nf&1)*2+1]);
            }
        }

        const float wbase = exp2f(l2d * (float)((jb - ib) * 64 - 1));
        const bool diag = (jb == ib);
        #pragma unroll
        for (int nf = 0; nf < 4; ++nf) {
            const int cl = wn*32 + nf*8 + (lane & 3)*2;
            float ec0 = exp2f(l2d * (float)cl);
            float ec1 = ec0 * decay;
            float w00 = wbase*ec0*er0, w01 = wbase*ec1*er0;
            float w10 = wbase*ec0*er1, w11 = wbase*ec1*er1;
            if (diag) {
                if (cl     <= rl0)     w00 = 0.f;
                if (cl + 1 <= rl0)     w01 = 0.f;
                if (cl     <= rl0 + 8) w10 = 0.f;
                if (cl + 1 <= rl0 + 8) w11 = 0.f;
            }
            float v00 = sacc[nf][0]*w00, v01 = sacc[nf][1]*w01;
            float v10 = sacc[nf][2]*w10, v11 = sacc[nf][3]*w11;

            #pragma unroll
            for (int h = 0; h < 2; ++h) {
                float a = h ? v10 : v00, c = h ? v11 : v01;
                __nv_bfloat16 ha, hc;
                uint32_t ph = pack_hilo_b(a, c, ha, hc);
                float ra = a - __bfloat162float(ha), rc = c - __bfloat162float(hc);
                __nv_bfloat16 t0, t1;
                uint32_t pl = pack_hilo_b(ra, rc, t0, t1);
                uint32_t off = (rl0 + h*8) * SW_STRIDE + cl * 2;
                *(uint32_t*)(shm + SM_SWH + off) = ph;
                *(uint32_t*)(shm + SM_SWL + off) = pl;
            }
        }

        CP_WAIT0();
        __syncthreads();

        uint32_t sh4[4][4], sl4[4][4];
        #pragma unroll
        for (int kf = 0; kf < 4; ++kf) {
            ldsm_x4(sh4[kf], sb + SM_SWH + (wm*16) * SW_STRIDE + kf*32 + offAs);
            ldsm_x4(sl4[kf], sb + SM_SWL + (wm*16) * SW_STRIDE + kf*32 + offAs);
        }
        #pragma unroll
        for (int nb = 0; nb < 8; ++nb) {
            const uint32_t d0b = (uint32_t)(wn*128 + nb*16) * 2;
            #pragma unroll
            for (int kf = 0; kf < 4; ++kf) {
                uint32_t vh[4], vl[4];
                const uint32_t va = sb + (kf*16) * AT_STRIDE + d0b + offV;
                ldsm_x4_t(vh, va + SM_VH);
                ldsm_x4_t(vl, va + SM_VL);
                mma16816(oacc[nb][0], sh4[kf], vh[0], vh[1]);
                mma16816(oacc[nb][1], sh4[kf], vh[2], vh[3]);
                mma16816(oacc[nb][0], sh4[kf], vl[0], vl[1]);
                mma16816(oacc[nb][1], sh4[kf], vl[2], vl[3]);
                mma16816(oacc[nb][0], sl4[kf], vh[0], vh[1]);
                mma16816(oacc[nb][1], sl4[kf], vh[2], vh[3]);
            }
        }
        __syncthreads();
    }

    // ---- fused epilogue: write r as single fp16 ----
    const size_t rrow = (size_t)(qrow0 + wm*16 + (lane >> 2)) * D_;
    #pragma unroll
    for (int nb = 0; nb < 8; ++nb) {
        #pragma unroll
        for (int g = 0; g < 2; ++g) {
            const int c = wn*128 + nb*16 + g*8 + (lane & 3) * 2;
            #pragma unroll
            for (int h = 0; h < 2; ++h) {
                uint32_t ph = pack_h2(oacc[nb][g][h*2], oacc[nb][g][h*2+1]);
                *(uint32_t*)(g_rf + rrow + (size_t)h * 8 * D_ + c) = ph;
            }
        }
    }
}

// ================= launch =================
#define GEMM_SMEM (NSTAGE*GSTG)

extern "C" void kernel_launch(void* const* d_in, const int* in_sizes, int n_in,
                              void* d_out, int out_size)
{
    const float* x  = (const float*)d_in[0];
    const float* wq = (const float*)d_in[1];
    const float* wk = (const float*)d_in[2];
    const float* wv = (const float*)d_in[3];
    const float* wo = (const float*)d_in[4];
    const float* dl = (const float*)d_in[5];
    const float* os = (const float*)d_in[6];
    float* out = (float*)d_out;

    cudaFuncSetAttribute(hmma_qkv_kernel, cudaFuncAttributeMaxDynamicSharedMemorySize, GEMM_SMEM);
    cudaFuncSetAttribute(hmma_out_kernel, cudaFuncAttributeMaxDynamicSharedMemorySize, GEMM_SMEM);
    cudaFuncSetAttribute(attn_hmma_kernel, cudaFuncAttributeMaxDynamicSharedMemorySize, ATT_SMEM);

    cvt_x_kernel<<<((size_t)M_*V_)/4096, 256>>>(x);
    cvt_w_kernel<<<4*512, 256>>>(wq, wk, wv, wo);

    hmma_qkv_kernel<<<dim3(2, 64, 6), 256, GEMM_SMEM>>>();

    reduce_qkv_kernel<<<3*2048, 256>>>();

    attn_hmma_kernel<<<dim3(T_/64, B_), 256, ATT_SMEM>>>(dl);

    hmma_out_kernel<<<dim3(64, 64), 256, GEMM_SMEM>>>(os, out);
}

// round 14
// speedup vs baseline: 3.1622x; 1.0125x over previous
#include <cuda_runtime.h>
#include <cuda_bf16.h>
#include <cuda_fp16.h>
#include <cstdint>

#define B_ 4
#define T_ 2048
#define V_ 8192
#define D_ 256
#define M_ (B_*T_)   // 8192 rows of (b,t)

// ---------------- scratch (device globals; no allocs allowed) ----------------
__device__ __half g_xf[(size_t)M_*V_];      // single fp16 x
__device__ __half g_wf[3*(size_t)D_*V_];
__device__ __half g_wof[(size_t)V_*D_];
__device__ __half g_rf[(size_t)M_*D_];      // single fp16 r

// split-K fp32 partials for qkv: 6 slabs of M_*D_ (z = w*2 + khalf)
__device__ float g_part[6*(size_t)M_*D_];

// bf16 hi/lo q,k,v (attention stays 3-pass bf16)
__device__ __nv_bfloat16 g_qbh[(size_t)M_*D_];
__device__ __nv_bfloat16 g_qbl[(size_t)M_*D_];
__device__ __nv_bfloat16 g_kbh[(size_t)M_*D_];
__device__ __nv_bfloat16 g_kbl[(size_t)M_*D_];
__device__ __nv_bfloat16 g_vbh[(size_t)M_*D_];
__device__ __nv_bfloat16 g_vbl[(size_t)M_*D_];

// ---------------- helpers ----------------
__device__ __forceinline__ uint32_t smem_u32(const void* p){
    uint32_t a;
    asm("{ .reg .u64 t; cvta.to.shared.u64 t, %1; cvt.u32.u64 %0, t; }" : "=r"(a) : "l"(p));
    return a;
}
#define CP16(smem, gptr) \
    asm volatile("cp.async.cg.shared.global [%0], [%1], 16;" :: "r"(smem), "l"(gptr))
#define CP_COMMIT() asm volatile("cp.async.commit_group;" ::: "memory")
#define CP_WAIT1()  asm volatile("cp.async.wait_group 1;" ::: "memory")
#define CP_WAIT0()  asm volatile("cp.async.wait_group 0;" ::: "memory")

__device__ __forceinline__ void ldsm_x4(uint32_t (&r)[4], uint32_t addr){
    asm volatile("ldmatrix.sync.aligned.m8n8.x4.shared.b16 {%0,%1,%2,%3}, [%4];"
        : "=r"(r[0]), "=r"(r[1]), "=r"(r[2]), "=r"(r[3]) : "r"(addr));
}
__device__ __forceinline__ void ldsm_x4_t(uint32_t (&r)[4], uint32_t addr){
    asm volatile("ldmatrix.sync.aligned.m8n8.x4.trans.shared.b16 {%0,%1,%2,%3}, [%4];"
        : "=r"(r[0]), "=r"(r[1]), "=r"(r[2]), "=r"(r[3]) : "r"(addr));
}
// bf16 mma (attention)
__device__ __forceinline__ void mma16816(float (&d)[4], const uint32_t (&a)[4],
                                         uint32_t b0, uint32_t b1){
    asm volatile("mma.sync.aligned.m16n8k16.row.col.f32.bf16.bf16.f32 "
        "{%0,%1,%2,%3}, {%4,%5,%6,%7}, {%8,%9}, {%0,%1,%2,%3};"
        : "+f"(d[0]), "+f"(d[1]), "+f"(d[2]), "+f"(d[3])
        : "r"(a[0]), "r"(a[1]), "r"(a[2]), "r"(a[3]), "r"(b0), "r"(b1));
}
// fp16 mma (projection GEMMs)
__device__ __forceinline__ void mma16816h(float (&d)[4], const uint32_t (&a)[4],
                                          uint32_t b0, uint32_t b1){
    asm volatile("mma.sync.aligned.m16n8k16.row.col.f32.f16.f16.f32 "
        "{%0,%1,%2,%3}, {%4,%5,%6,%7}, {%8,%9}, {%0,%1,%2,%3};"
        : "+f"(d[0]), "+f"(d[1]), "+f"(d[2]), "+f"(d[3])
        : "r"(a[0]), "r"(a[1]), "r"(a[2]), "r"(a[3]), "r"(b0), "r"(b1));
}
__device__ __forceinline__ uint32_t pack_hilo_b(float a, float c,
                                                __nv_bfloat16& ra, __nv_bfloat16& rc){
    ra = __float2bfloat16(a);
    rc = __float2bfloat16(c);
    return (uint32_t)*(uint16_t*)&ra | ((uint32_t)*(uint16_t*)&rc << 16);
}
__device__ __forceinline__ uint32_t pack_h2(float a, float c){
    __half ra = __float2half_rn(a);
    __half rc = __float2half_rn(c);
    return (uint32_t)*(uint16_t*)&ra | ((uint32_t)*(uint16_t*)&rc << 16);
}

// ================= merged conversion kernel: x + all weights -> fp16 =================
// blocks [0, 16384): x; [16384, 16384+2048): weights (512 blocks each).
#define XBLKS ((int)(((size_t)M_*V_)/4096))      // 16384
#define WBLKS 512

__global__ void __launch_bounds__(256)
cvt_all_kernel(const float* __restrict__ x,
               const float* __restrict__ wq, const float* __restrict__ wk,
               const float* __restrict__ wv, const float* __restrict__ wo)
{
    const float* in;
    __half* outp;
    int blk;
    if (blockIdx.x < XBLKS) {
        in = x; outp = g_xf; blk = blockIdx.x;
    } else {
        const int wb = blockIdx.x - XBLKS;
        const int sel = wb >> 9;
        blk = wb & (WBLKS - 1);
        switch (sel) {
            case 0: in = wq; outp = g_wf;                 break;
            case 1: in = wk; outp = g_wf + (size_t)D_*V_;   break;
            case 2: in = wv; outp = g_wf + 2*(size_t)D_*V_; break;
            default: in = wo; outp = g_wof;               break;
        }
    }
    const size_t base = (size_t)blk * 4096 + threadIdx.x * 4;
    float4 v[4];
    #pragma unroll
    for (int j = 0; j < 4; ++j) v[j] = *(const float4*)(in + base + j * 1024);
    #pragma unroll
    for (int j = 0; j < 4; ++j) {
        const size_t i = base + j * 1024;
        float f[4] = {v[j].x, v[j].y, v[j].z, v[j].w};
        union { __half b[4]; uint2 u; } H;
        #pragma unroll
        for (int e = 0; e < 4; ++e) H.b[e] = __float2half_rn(f[e]);
        *(uint2*)(outp + i) = H.u;
    }
}

// ================= split-K reduce: partials -> bf16 hi/lo q/k/v =================
__global__ void __launch_bounds__(256)
reduce_qkv_kernel()
{
    const int w   = blockIdx.x >> 11;
    const int blk = blockIdx.x & 2047;
    const size_t base = (size_t)blk * 1024 + threadIdx.x * 4;
    const float* p0 = g_part + (size_t)(2*w)   * ((size_t)M_*D_);
    const float* p1 = g_part + (size_t)(2*w+1) * ((size_t)M_*D_);
    __nv_bfloat16* hi = (w==0) ? g_qbh : (w==1) ? g_kbh : g_vbh;
    __nv_bfloat16* lo = (w==0) ? g_qbl : (w==1) ? g_kbl : g_vbl;
    float4 a = *(const float4*)(p0 + base);
    float4 b = *(const float4*)(p1 + base);
    float f[4] = {a.x+b.x, a.y+b.y, a.z+b.z, a.w+b.w};
    union { __nv_bfloat16 b[4]; uint2 u; } H, L;
    #pragma unroll
    for (int e = 0; e < 4; ++e) {
        __nv_bfloat16 h = __float2bfloat16(f[e]);
        float r = f[e] - __bfloat162float(h);
        H.b[e] = h;
        L.b[e] = __float2bfloat16(r);
    }
    *(uint2*)(hi + base) = H.u;
    *(uint2*)(lo + base) = L.u;
}

// ================= fp16 1-pass NT GEMM, BK=64, 3-stage cp.async ring =================
// C = A[M,K](fp16) * B[N,K]^T(fp16) * scale, fp32 accum.
// CTA tile 128x128, BK=64, 256 threads, warp tile 64x32 (2x4 warps).
#define LDS_B 144                 // 128 B data + 16 B pad per row
#define GSTG  36864               // (128 A rows + 128 B rows) * 144
#define GT_B  18432
#define NSTAGE 3

__device__ __forceinline__ void hmma_gemm_body(
    const __half* __restrict__ Ag, const __half* __restrict__ Bg,
    float* __restrict__ Cf,
    int K, int ldAB, int ldC, float scale, int row0, int col0)
{
    extern __shared__ __align__(128) char sm[];
    const int tid  = threadIdx.x;
    const int lane = tid & 31;
    const int wid  = tid >> 5;
    const int wm   = wid >> 2;
    const int wn   = wid & 3;
    const uint32_t sbase = smem_u32(sm);

    float acc[4][4][4];
    #pragma unroll
    for (int a = 0; a < 4; ++a)
        #pragma unroll
        for (int b = 0; b < 4; ++b)
            #pragma unroll
            for (int c = 0; c < 4; ++c) acc[a][b][c] = 0.f;

    auto load_stage = [&](int c, int s){
        const uint32_t sb = sbase + s * GSTG;
        #pragma unroll
        for (int q = 0; q < 4; ++q) {
            const int idx = tid + q * 256;
            const int r = idx >> 3, seg = idx & 7;
            const size_t k0 = (size_t)c * 64 + seg * 8;
            const uint32_t soff = r * LDS_B + seg * 16;
            CP16(sb + soff,        Ag + (size_t)(row0 + r) * ldAB + k0);
            CP16(sb + GT_B + soff, Bg + (size_t)(col0 + r) * ldAB + k0);
        }
    };

    const uint32_t offA = (lane & 15) * LDS_B + (lane >> 4) * 16;
    const uint32_t offB = ((lane & 7) + ((lane >> 4) & 1) * 8) * LDS_B
                        + ((lane >> 3) & 1) * 16;

    const int NC = K / 64;

    load_stage(0, 0); CP_COMMIT();
    if (NC > 1) { load_stage(1, 1); CP_COMMIT(); }

    int sidx = 0;
    for (int c = 0; c < NC; ++c) {
        if (c + 1 < NC) CP_WAIT1();
        else            CP_WAIT0();
        __syncthreads();

        const uint32_t sb = sbase + sidx * GSTG;
        #pragma unroll
        for (int kk = 0; kk < 4; ++kk) {
            const uint32_t kb = kk * 32;
            uint32_t ah[4][4], bb[2][4];
            #pragma unroll
            for (int mf = 0; mf < 4; ++mf)
                ldsm_x4(ah[mf], sb + (wm*64 + mf*16) * LDS_B + kb + offA);
            #pragma unroll
            for (int g = 0; g < 2; ++g)
                ldsm_x4(bb[g], sb + GT_B + (wn*32 + g*16) * LDS_B + kb + offB);
            #pragma unroll
            for (int mf = 0; mf < 4; ++mf)
                #pragma unroll
                for (int nf = 0; nf < 4; ++nf)
                    mma16816h(acc[mf][nf], ah[mf], bb[nf>>1][(nf&1)*2], bb[nf>>1][(nf&1)*2+1]);
        }

        if (c + 2 < NC) {
            int s2 = sidx + 2; if (s2 >= NSTAGE) s2 -= NSTAGE;
            load_stage(c + 2, s2);
            CP_COMMIT();
        }
        if (++sidx == NSTAGE) sidx = 0;
    }

    #pragma unroll
    for (int mf = 0; mf < 4; ++mf) {
        const int r0 = row0 + wm*64 + mf*16 + (lane >> 2);
        #pragma unroll
        for (int nf = 0; nf < 4; ++nf) {
            const int cc = col0 + wn*32 + nf*8 + (lane & 3) * 2;
            float2 v0 = { acc[mf][nf][0] * scale, acc[mf][nf][1] * scale };
            float2 v1 = { acc[mf][nf][2] * scale, acc[mf][nf][3] * scale };
            *(float2*)(Cf + (size_t)r0 * ldC + cc)       = v0;
            *(float2*)(Cf + (size_t)(r0 + 8) * ldC + cc) = v1;
        }
    }
}

// ---- QKV split-K: grid (2 Ntiles, 64 Mtiles, 6 = weight*2 + khalf) ----
__global__ void __launch_bounds__(256, 2)
hmma_qkv_kernel()
{
    const int z = blockIdx.z;
    const int w = z >> 1, kh = z & 1;
    const size_t koff = (size_t)kh * 4096;
    const __half* Bg = g_wf + (size_t)w * D_ * V_ + koff;
    float* Cf = g_part + (size_t)z * ((size_t)M_*D_);
    hmma_gemm_body(g_xf + koff, Bg, Cf,
                   4096, V_, D_, 1.0f, blockIdx.y * 128, blockIdx.x * 128);
}

// ---- OUT: grid (64 Ntiles, 64 Mtiles) ----
__global__ void __launch_bounds__(256, 2)
hmma_out_kernel(const float* __restrict__ out_scale, float* __restrict__ out)
{
    hmma_gemm_body(g_rf, g_wof, out,
                   D_, D_, V_, out_scale[0], blockIdx.y * 128, blockIdx.x * 128);
}

// ================= HMMA attention (bf16 3-pass, single fp16 r output) =================
#define AT_STRIDE 528
#define SW_STRIDE 144
#define SM_QH 0
#define SM_QL 33792
#define SM_KH 67584
#define SM_KL 101376
#define SM_VH 135168
#define SM_VL 168960
#define SM_SWH 202752
#define SM_SWL 211968
#define ATT_SMEM 221184

__global__ void __launch_bounds__(256, 1)
attn_hmma_kernel(const float* __restrict__ dlp)
{
    extern __shared__ __align__(128) char shm[];
    const int tid = threadIdx.x, lane = tid & 31, wid = tid >> 5;
    const int wm = wid >> 1, wn = wid & 1;
    const int ib = blockIdx.x, b = blockIdx.y;
    const uint32_t sb = smem_u32(shm);

    const float logit = dlp[0];
    const float decay = 1.f / (1.f + expf(-logit));
    const float l2d   = log2f(decay);

    const int qrow0 = b * T_ + ib * 64;

    #pragma unroll
    for (int it = 0; it < 8; ++it) {
        int idx = it * 256 + tid;
        int r = idx >> 5, s = idx & 31;
        uint32_t soff = r * AT_STRIDE + s * 16;
        size_t gb = ((size_t)(qrow0 + r) * D_) * 2 + s * 16;
        CP16(sb + SM_QH + soff, (const char*)g_qbh + gb);
        CP16(sb + SM_QL + soff, (const char*)g_qbl + gb);
    }
    CP_COMMIT();

    float oacc[8][2][4];
    #pragma unroll
    for (int a = 0; a < 8; ++a)
        #pragma unroll
        for (int g = 0; g < 2; ++g)
            #pragma unroll
            for (int e = 0; e < 4; ++e) oacc[a][g][e] = 0.f;

    const uint32_t offA  = (lane & 15) * AT_STRIDE + (lane >> 4) * 16;
    const uint32_t offB  = ((lane & 7) + ((lane >> 4) & 1) * 8) * AT_STRIDE
                         + ((lane >> 3) & 1) * 16;
    const uint32_t offAs = (lane & 15) * SW_STRIDE + (lane >> 4) * 16;
    const uint32_t offV  = ((lane & 7) + ((lane >> 3) & 1) * 8) * AT_STRIDE
                         + (lane >> 4) * 16;

    const int rl0 = wm * 16 + (lane >> 2);
    const float er0 = exp2f(-l2d * (float)rl0);
    const float er1 = er0 * exp2f(-l2d * 8.f);

    CP_WAIT0();
    __syncthreads();

    for (int jb = ib; jb < T_/64; ++jb) {
        int emin = (jb - ib) * 64 - 64;
        if (emin > 0 && l2d * (float)emin < -15.f) break;
        const int krow0 = b * T_ + jb * 64;

        #pragma unroll
        for (int it = 0; it < 8; ++it) {
            int idx = it * 256 + tid;
            int r = idx >> 5, s = idx & 31;
            uint32_t soff = r * AT_STRIDE + s * 16;
            size_t gb = ((size_t)(krow0 + r) * D_) * 2 + s * 16;
            CP16(sb + SM_KH + soff, (const char*)g_kbh + gb);
            CP16(sb + SM_KL + soff, (const char*)g_kbl + gb);
        }
        CP_COMMIT();
        #pragma unroll
        for (int it = 0; it < 8; ++it) {
            int idx = it * 256 + tid;
            int r = idx >> 5, s = idx & 31;
            uint32_t soff = r * AT_STRIDE + s * 16;
            size_t gb = ((size_t)(krow0 + r) * D_) * 2 + s * 16;
            CP16(sb + SM_VH + soff, (const char*)g_vbh + gb);
            CP16(sb + SM_VL + soff, (const char*)g_vbl + gb);
        }
        CP_COMMIT();
        CP_WAIT1();
        __syncthreads();

        float sacc[4][4];
        #pragma unroll
        for (int nf = 0; nf < 4; ++nf)
            #pragma unroll
            for (int e = 0; e < 4; ++e) sacc[nf][e] = 0.f;

        #pragma unroll 4
        for (int kf = 0; kf < 16; ++kf) {
            const uint32_t kb = kf * 32;
            uint32_t qh[4], ql[4], kh[2][4], kl[2][4];
            ldsm_x4(qh, sb + SM_QH + (wm*16) * AT_STRIDE + kb + offA);
            ldsm_x4(ql, sb + SM_QL + (wm*16) * AT_STRIDE + kb + offA);
            ldsm_x4(kh[0], sb + SM_KH + (wn*32)      * AT_STRIDE + kb + offB);
            ldsm_x4(kh[1], sb + SM_KH + (wn*32 + 16) * AT_STRIDE + kb + offB);
            ldsm_x4(kl[0], sb + SM_KL + (wn*32)      * AT_STRIDE + kb + offB);
            ldsm_x4(kl[1], sb + SM_KL + (wn*32 + 16) * AT_STRIDE + kb + offB);
            #pragma unroll
            for (int nf = 0; nf < 4; ++nf) {
                mma16816(sacc[nf], qh, kh[nf>>1][(nf&1)*2], kh[nf>>1][(nf&1)*2+1]);
                mma16816(sacc[nf], qh, kl[nf>>1][(nf&1)*2], kl[nf>>1][(nf&1)*2+1]);
                mma16816(sacc[nf], ql, kh[nf>>1][(nf&1)*2], kh[nf>>1][(nf&1)*2+1]);
            }
        }

        const float wbase = exp2f(l2d * (float)((jb - ib) * 64 - 1));
        const bool diag = (jb == ib);
        #pragma unroll
        for (int nf = 0; nf < 4; ++nf) {
            const int cl = wn*32 + nf*8 + (lane & 3)*2;
            float ec0 = exp2f(l2d * (float)cl);
            float ec1 = ec0 * decay;
            float w00 = wbase*ec0*er0, w01 = wbase*ec1*er0;
            float w10 = wbase*ec0*er1, w11 = wbase*ec1*er1;
            if (diag) {
                if (cl     <= rl0)     w00 = 0.f;
                if (cl + 1 <= rl0)     w01 = 0.f;
                if (cl     <= rl0 + 8) w10 = 0.f;
                if (cl + 1 <= rl0 + 8) w11 = 0.f;
            }
            float v00 = sacc[nf][0]*w00, v01 = sacc[nf][1]*w01;
            float v10 = sacc[nf][2]*w10, v11 = sacc[nf][3]*w11;

            #pragma unroll
            for (int h = 0; h < 2; ++h) {
                float a = h ? v10 : v00, c = h ? v11 : v01;
                __nv_bfloat16 ha, hc;
                uint32_t ph = pack_hilo_b(a, c, ha, hc);
                float ra = a - __bfloat162float(ha), rc = c - __bfloat162float(hc);
                __nv_bfloat16 t0, t1;
                uint32_t pl = pack_hilo_b(ra, rc, t0, t1);
                uint32_t off = (rl0 + h*8) * SW_STRIDE + cl * 2;
                *(uint32_t*)(shm + SM_SWH + off) = ph;
                *(uint32_t*)(shm + SM_SWL + off) = pl;
            }
        }

        CP_WAIT0();
        __syncthreads();

        uint32_t sh4[4][4], sl4[4][4];
        #pragma unroll
        for (int kf = 0; kf < 4; ++kf) {
            ldsm_x4(sh4[kf], sb + SM_SWH + (wm*16) * SW_STRIDE + kf*32 + offAs);
            ldsm_x4(sl4[kf], sb + SM_SWL + (wm*16) * SW_STRIDE + kf*32 + offAs);
        }
        #pragma unroll
        for (int nb = 0; nb < 8; ++nb) {
            const uint32_t d0b = (uint32_t)(wn*128 + nb*16) * 2;
            #pragma unroll
            for (int kf = 0; kf < 4; ++kf) {
                uint32_t vh[4], vl[4];
                const uint32_t va = sb + (kf*16) * AT_STRIDE + d0b + offV;
                ldsm_x4_t(vh, va + SM_VH);
                ldsm_x4_t(vl, va + SM_VL);
                mma16816(oacc[nb][0], sh4[kf], vh[0], vh[1]);
                mma16816(oacc[nb][1], sh4[kf], vh[2], vh[3]);
                mma16816(oacc[nb][0], sh4[kf], vl[0], vl[1]);
                mma16816(oacc[nb][1], sh4[kf], vl[2], vl[3]);
                mma16816(oacc[nb][0], sl4[kf], vh[0], vh[1]);
                mma16816(oacc[nb][1], sl4[kf], vh[2], vh[3]);
            }
        }
        __syncthreads();
    }

    // ---- fused epilogue: write r as single fp16 ----
    const size_t rrow = (size_t)(qrow0 + wm*16 + (lane >> 2)) * D_;
    #pragma unroll
    for (int nb = 0; nb < 8; ++nb) {
        #pragma unroll
        for (int g = 0; g < 2; ++g) {
            const int c = wn*128 + nb*16 + g*8 + (lane & 3) * 2;
            #pragma unroll
            for (int h = 0; h < 2; ++h) {
                uint32_t ph = pack_h2(oacc[nb][g][h*2], oacc[nb][g][h*2+1]);
                *(uint32_t*)(g_rf + rrow + (size_t)h * 8 * D_ + c) = ph;
            }
        }
    }
}

// ================= launch =================
#define GEMM_SMEM (NSTAGE*GSTG)

extern "C" void kernel_launch(void* const* d_in, const int* in_sizes, int n_in,
                              void* d_out, int out_size)
{
    const float* x  = (const float*)d_in[0];
    const float* wq = (const float*)d_in[1];
    const float* wk = (const float*)d_in[2];
    const float* wv = (const float*)d_in[3];
    const float* wo = (const float*)d_in[4];
    const float* dl = (const float*)d_in[5];
    const float* os = (const float*)d_in[6];
    float* out = (float*)d_out;

    cudaFuncSetAttribute(hmma_qkv_kernel, cudaFuncAttributeMaxDynamicSharedMemorySize, GEMM_SMEM);
    cudaFuncSetAttribute(hmma_out_kernel, cudaFuncAttributeMaxDynamicSharedMemorySize, GEMM_SMEM);
    cudaFuncSetAttribute(attn_hmma_kernel, cudaFuncAttributeMaxDynamicSharedMemorySize, ATT_SMEM);

    cvt_all_kernel<<<XBLKS + 4*WBLKS, 256>>>(x, wq, wk, wv, wo);

    hmma_qkv_kernel<<<dim3(2, 64, 6), 256, GEMM_SMEM>>>();

    reduce_qkv_kernel<<<3*2048, 256>>>();

    attn_hmma_kernel<<<dim3(T_/64, B_), 256, ATT_SMEM>>>(dl);

    hmma_out_kernel<<<dim3(64, 64), 256, GEMM_SMEM>>>(os, out);
}

// round 15
// speedup vs baseline: 3.1736x; 1.0036x over previous
#include <cuda_runtime.h>
#include <cuda_bf16.h>
#include <cuda_fp16.h>
#include <cstdint>

#define B_ 4
#define T_ 2048
#define V_ 8192
#define D_ 256
#define M_ (B_*T_)   // 8192 rows of (b,t)

// ---------------- scratch (device globals; no allocs allowed) ----------------
__device__ __half g_xf[(size_t)M_*V_];      // single fp16 x
__device__ __half g_wf[3*(size_t)D_*V_];
__device__ __half g_wof[(size_t)V_*D_];
__device__ __half g_rf[(size_t)M_*D_];      // single fp16 r

// split-K fp32 partials for qkv: 6 slabs of M_*D_ (z = w*2 + khalf)
__device__ float g_part[6*(size_t)M_*D_];

// bf16 hi/lo q,k,v (attention stays 3-pass bf16)
__device__ __nv_bfloat16 g_qbh[(size_t)M_*D_];
__device__ __nv_bfloat16 g_qbl[(size_t)M_*D_];
__device__ __nv_bfloat16 g_kbh[(size_t)M_*D_];
__device__ __nv_bfloat16 g_kbl[(size_t)M_*D_];
__device__ __nv_bfloat16 g_vbh[(size_t)M_*D_];
__device__ __nv_bfloat16 g_vbl[(size_t)M_*D_];

// ---------------- helpers ----------------
__device__ __forceinline__ uint32_t smem_u32(const void* p){
    uint32_t a;
    asm("{ .reg .u64 t; cvta.to.shared.u64 t, %1; cvt.u32.u64 %0, t; }" : "=r"(a) : "l"(p));
    return a;
}
#define CP16(smem, gptr) \
    asm volatile("cp.async.cg.shared.global [%0], [%1], 16;" :: "r"(smem), "l"(gptr))
#define CP_COMMIT() asm volatile("cp.async.commit_group;" ::: "memory")
#define CP_WAIT2()  asm volatile("cp.async.wait_group 2;" ::: "memory")
#define CP_WAIT1()  asm volatile("cp.async.wait_group 1;" ::: "memory")
#define CP_WAIT0()  asm volatile("cp.async.wait_group 0;" ::: "memory")

__device__ __forceinline__ void ldsm_x4(uint32_t (&r)[4], uint32_t addr){
    asm volatile("ldmatrix.sync.aligned.m8n8.x4.shared.b16 {%0,%1,%2,%3}, [%4];"
        : "=r"(r[0]), "=r"(r[1]), "=r"(r[2]), "=r"(r[3]) : "r"(addr));
}
__device__ __forceinline__ void ldsm_x4_t(uint32_t (&r)[4], uint32_t addr){
    asm volatile("ldmatrix.sync.aligned.m8n8.x4.trans.shared.b16 {%0,%1,%2,%3}, [%4];"
        : "=r"(r[0]), "=r"(r[1]), "=r"(r[2]), "=r"(r[3]) : "r"(addr));
}
// bf16 mma (attention)
__device__ __forceinline__ void mma16816(float (&d)[4], const uint32_t (&a)[4],
                                         uint32_t b0, uint32_t b1){
    asm volatile("mma.sync.aligned.m16n8k16.row.col.f32.bf16.bf16.f32 "
        "{%0,%1,%2,%3}, {%4,%5,%6,%7}, {%8,%9}, {%0,%1,%2,%3};"
        : "+f"(d[0]), "+f"(d[1]), "+f"(d[2]), "+f"(d[3])
        : "r"(a[0]), "r"(a[1]), "r"(a[2]), "r"(a[3]), "r"(b0), "r"(b1));
}
// fp16 mma (projection GEMMs)
__device__ __forceinline__ void mma16816h(float (&d)[4], const uint32_t (&a)[4],
                                          uint32_t b0, uint32_t b1){
    asm volatile("mma.sync.aligned.m16n8k16.row.col.f32.f16.f16.f32 "
        "{%0,%1,%2,%3}, {%4,%5,%6,%7}, {%8,%9}, {%0,%1,%2,%3};"
        : "+f"(d[0]), "+f"(d[1]), "+f"(d[2]), "+f"(d[3])
        : "r"(a[0]), "r"(a[1]), "r"(a[2]), "r"(a[3]), "r"(b0), "r"(b1));
}
__device__ __forceinline__ uint32_t pack_hilo_b(float a, float c,
                                                __nv_bfloat16& ra, __nv_bfloat16& rc){
    ra = __float2bfloat16(a);
    rc = __float2bfloat16(c);
    return (uint32_t)*(uint16_t*)&ra | ((uint32_t)*(uint16_t*)&rc << 16);
}
__device__ __forceinline__ uint32_t pack_h2(float a, float c){
    __half ra = __float2half_rn(a);
    __half rc = __float2half_rn(c);
    return (uint32_t)*(uint16_t*)&ra | ((uint32_t)*(uint16_t*)&rc << 16);
}

// ================= merged conversion kernel: x + all weights -> fp16 =================
#define XBLKS ((int)(((size_t)M_*V_)/4096))      // 16384
#define WBLKS 512

__global__ void __launch_bounds__(256)
cvt_all_kernel(const float* __restrict__ x,
               const float* __restrict__ wq, const float* __restrict__ wk,
               const float* __restrict__ wv, const float* __restrict__ wo)
{
    const float* in;
    __half* outp;
    int blk;
    if (blockIdx.x < XBLKS) {
        in = x; outp = g_xf; blk = blockIdx.x;
    } else {
        const int wb = blockIdx.x - XBLKS;
        const int sel = wb >> 9;
        blk = wb & (WBLKS - 1);
        switch (sel) {
            case 0: in = wq; outp = g_wf;                 break;
            case 1: in = wk; outp = g_wf + (size_t)D_*V_;   break;
            case 2: in = wv; outp = g_wf + 2*(size_t)D_*V_; break;
            default: in = wo; outp = g_wof;               break;
        }
    }
    const size_t base = (size_t)blk * 4096 + threadIdx.x * 4;
    float4 v[4];
    #pragma unroll
    for (int j = 0; j < 4; ++j) v[j] = *(const float4*)(in + base + j * 1024);
    #pragma unroll
    for (int j = 0; j < 4; ++j) {
        const size_t i = base + j * 1024;
        float f[4] = {v[j].x, v[j].y, v[j].z, v[j].w};
        union { __half b[4]; uint2 u; } H;
        #pragma unroll
        for (int e = 0; e < 4; ++e) H.b[e] = __float2half_rn(f[e]);
        *(uint2*)(outp + i) = H.u;
    }
}

// ================= split-K reduce: partials -> bf16 hi/lo q/k/v =================
__global__ void __launch_bounds__(256)
reduce_qkv_kernel()
{
    const int w   = blockIdx.x >> 11;
    const int blk = blockIdx.x & 2047;
    const size_t base = (size_t)blk * 1024 + threadIdx.x * 4;
    const float* p0 = g_part + (size_t)(2*w)   * ((size_t)M_*D_);
    const float* p1 = g_part + (size_t)(2*w+1) * ((size_t)M_*D_);
    __nv_bfloat16* hi = (w==0) ? g_qbh : (w==1) ? g_kbh : g_vbh;
    __nv_bfloat16* lo = (w==0) ? g_qbl : (w==1) ? g_kbl : g_vbl;
    float4 a = *(const float4*)(p0 + base);
    float4 b = *(const float4*)(p1 + base);
    float f[4] = {a.x+b.x, a.y+b.y, a.z+b.z, a.w+b.w};
    union { __nv_bfloat16 b[4]; uint2 u; } H, L;
    #pragma unroll
    for (int e = 0; e < 4; ++e) {
        __nv_bfloat16 h = __float2bfloat16(f[e]);
        float r = f[e] - __bfloat162float(h);
        H.b[e] = h;
        L.b[e] = __float2bfloat16(r);
    }
    *(uint2*)(hi + base) = H.u;
    *(uint2*)(lo + base) = L.u;
}

// ================= fp16 1-pass NT GEMM, BK=64, 3-stage cp.async ring =================
#define LDS_B 144
#define GSTG  36864
#define GT_B  18432
#define NSTAGE 3

__device__ __forceinline__ void hmma_gemm_body(
    const __half* __restrict__ Ag, const __half* __restrict__ Bg,
    float* __restrict__ Cf,
    int K, int ldAB, int ldC, float scale, int row0, int col0)
{
    extern __shared__ __align__(128) char sm[];
    const int tid  = threadIdx.x;
    const int lane = tid & 31;
    const int wid  = tid >> 5;
    const int wm   = wid >> 2;
    const int wn   = wid & 3;
    const uint32_t sbase = smem_u32(sm);

    float acc[4][4][4];
    #pragma unroll
    for (int a = 0; a < 4; ++a)
        #pragma unroll
        for (int b = 0; b < 4; ++b)
            #pragma unroll
            for (int c = 0; c < 4; ++c) acc[a][b][c] = 0.f;

    auto load_stage = [&](int c, int s){
        const uint32_t sb = sbase + s * GSTG;
        #pragma unroll
        for (int q = 0; q < 4; ++q) {
            const int idx = tid + q * 256;
            const int r = idx >> 3, seg = idx & 7;
            const size_t k0 = (size_t)c * 64 + seg * 8;
            const uint32_t soff = r * LDS_B + seg * 16;
            CP16(sb + soff,        Ag + (size_t)(row0 + r) * ldAB + k0);
            CP16(sb + GT_B + soff, Bg + (size_t)(col0 + r) * ldAB + k0);
        }
    };

    const uint32_t offA = (lane & 15) * LDS_B + (lane >> 4) * 16;
    const uint32_t offB = ((lane & 7) + ((lane >> 4) & 1) * 8) * LDS_B
                        + ((lane >> 3) & 1) * 16;

    const int NC = K / 64;

    load_stage(0, 0); CP_COMMIT();
    if (NC > 1) { load_stage(1, 1); CP_COMMIT(); }

    int sidx = 0;
    for (int c = 0; c < NC; ++c) {
        if (c + 1 < NC) CP_WAIT1();
        else            CP_WAIT0();
        __syncthreads();

        const uint32_t sb = sbase + sidx * GSTG;
        #pragma unroll
        for (int kk = 0; kk < 4; ++kk) {
            const uint32_t kb = kk * 32;
            uint32_t ah[4][4], bb[2][4];
            #pragma unroll
            for (int mf = 0; mf < 4; ++mf)
                ldsm_x4(ah[mf], sb + (wm*64 + mf*16) * LDS_B + kb + offA);
            #pragma unroll
            for (int g = 0; g < 2; ++g)
                ldsm_x4(bb[g], sb + GT_B + (wn*32 + g*16) * LDS_B + kb + offB);
            #pragma unroll
            for (int mf = 0; mf < 4; ++mf)
                #pragma unroll
                for (int nf = 0; nf < 4; ++nf)
                    mma16816h(acc[mf][nf], ah[mf], bb[nf>>1][(nf&1)*2], bb[nf>>1][(nf&1)*2+1]);
        }

        if (c + 2 < NC) {
            int s2 = sidx + 2; if (s2 >= NSTAGE) s2 -= NSTAGE;
            load_stage(c + 2, s2);
            CP_COMMIT();
        }
        if (++sidx == NSTAGE) sidx = 0;
    }

    #pragma unroll
    for (int mf = 0; mf < 4; ++mf) {
        const int r0 = row0 + wm*64 + mf*16 + (lane >> 2);
        #pragma unroll
        for (int nf = 0; nf < 4; ++nf) {
            const int cc = col0 + wn*32 + nf*8 + (lane & 3) * 2;
            float2 v0 = { acc[mf][nf][0] * scale, acc[mf][nf][1] * scale };
            float2 v1 = { acc[mf][nf][2] * scale, acc[mf][nf][3] * scale };
            *(float2*)(Cf + (size_t)r0 * ldC + cc)       = v0;
            *(float2*)(Cf + (size_t)(r0 + 8) * ldC + cc) = v1;
        }
    }
}

// ---- QKV split-K: grid (2 Ntiles, 64 Mtiles, 6 = weight*2 + khalf) ----
__global__ void __launch_bounds__(256, 2)
hmma_qkv_kernel()
{
    const int z = blockIdx.z;
    const int w = z >> 1, kh = z & 1;
    const size_t koff = (size_t)kh * 4096;
    const __half* Bg = g_wf + (size_t)w * D_ * V_ + koff;
    float* Cf = g_part + (size_t)z * ((size_t)M_*D_);
    hmma_gemm_body(g_xf + koff, Bg, Cf,
                   4096, V_, D_, 1.0f, blockIdx.y * 128, blockIdx.x * 128);
}

// ---- OUT: grid (64 Ntiles, 64 Mtiles) ----
__global__ void __launch_bounds__(256, 2)
hmma_out_kernel(const float* __restrict__ out_scale, float* __restrict__ out)
{
    hmma_gemm_body(g_rf, g_wof, out,
                   D_, D_, V_, out_scale[0], blockIdx.y * 128, blockIdx.x * 128);
}

// ================= HMMA attention (bf16 3-pass, K/V ring-prefetched) =================
#define AT_STRIDE 528
#define SW_STRIDE 144
#define SM_QH 0
#define SM_QL 33792
#define SM_KH 67584
#define SM_KL 101376
#define SM_VH 135168
#define SM_VL 168960
#define SM_SWH 202752
#define SM_SWL 211968
#define ATT_SMEM 221184

__global__ void __launch_bounds__(256, 1)
attn_hmma_kernel(const float* __restrict__ dlp)
{
    extern __shared__ __align__(128) char shm[];
    const int tid = threadIdx.x, lane = tid & 31, wid = tid >> 5;
    const int wm = wid >> 1, wn = wid & 1;
    const int ib = blockIdx.x, b = blockIdx.y;
    const uint32_t sb = smem_u32(shm);

    const float logit = dlp[0];
    const float decay = 1.f / (1.f + expf(-logit));
    const float l2d   = log2f(decay);

    const int qrow0 = b * T_ + ib * 64;

    // ---- loop extent (identical arithmetic to old per-iter break) ----
    int nblk = 1;
    while (ib + nblk < T_/64) {
        int emin = nblk * 64 - 64;
        if (emin > 0 && l2d * (float)emin < -15.f) break;
        ++nblk;
    }
    const int jb_end = ib + nblk;

    auto load_k = [&](int jb){
        const int krow0 = b * T_ + jb * 64;
        #pragma unroll
        for (int it = 0; it < 8; ++it) {
            int idx = it * 256 + tid;
            int r = idx >> 5, s = idx & 31;
            uint32_t soff = r * AT_STRIDE + s * 16;
            size_t gb = ((size_t)(krow0 + r) * D_) * 2 + s * 16;
            CP16(sb + SM_KH + soff, (const char*)g_kbh + gb);
            CP16(sb + SM_KL + soff, (const char*)g_kbl + gb);
        }
    };
    auto load_v = [&](int jb){
        const int krow0 = b * T_ + jb * 64;
        #pragma unroll
        for (int it = 0; it < 8; ++it) {
            int idx = it * 256 + tid;
            int r = idx >> 5, s = idx & 31;
            uint32_t soff = r * AT_STRIDE + s * 16;
            size_t gb = ((size_t)(krow0 + r) * D_) * 2 + s * 16;
            CP16(sb + SM_VH + soff, (const char*)g_vbh + gb);
            CP16(sb + SM_VL + soff, (const char*)g_vbl + gb);
        }
    };

    // ---- prologue: Q, K(ib), V(ib) ----
    #pragma unroll
    for (int it = 0; it < 8; ++it) {
        int idx = it * 256 + tid;
        int r = idx >> 5, s = idx & 31;
        uint32_t soff = r * AT_STRIDE + s * 16;
        size_t gb = ((size_t)(qrow0 + r) * D_) * 2 + s * 16;
        CP16(sb + SM_QH + soff, (const char*)g_qbh + gb);
        CP16(sb + SM_QL + soff, (const char*)g_qbl + gb);
    }
    CP_COMMIT();
    load_k(ib); CP_COMMIT();
    load_v(ib); CP_COMMIT();

    float oacc[8][2][4];
    #pragma unroll
    for (int a = 0; a < 8; ++a)
        #pragma unroll
        for (int g = 0; g < 2; ++g)
            #pragma unroll
            for (int e = 0; e < 4; ++e) oacc[a][g][e] = 0.f;

    const uint32_t offA  = (lane & 15) * AT_STRIDE + (lane >> 4) * 16;
    const uint32_t offB  = ((lane & 7) + ((lane >> 4) & 1) * 8) * AT_STRIDE
                         + ((lane >> 3) & 1) * 16;
    const uint32_t offAs = (lane & 15) * SW_STRIDE + (lane >> 4) * 16;
    const uint32_t offV  = ((lane & 7) + ((lane >> 3) & 1) * 8) * AT_STRIDE
                         + (lane >> 4) * 16;

    const int rl0 = wm * 16 + (lane >> 2);
    const float er0 = exp2f(-l2d * (float)rl0);
    const float er1 = er0 * exp2f(-l2d * 8.f);

    CP_WAIT2();        // Q ready (K/V may be in flight)
    __syncthreads();

    for (int jb = ib; jb < jb_end; ++jb) {
        const bool pre = (jb + 1 < jb_end);

        CP_WAIT1();    // K(jb) ready (V(jb) in flight)
        __syncthreads();

        // ---- phase A: S = Q K^T, 3-pass bf16 ----
        float sacc[4][4];
        #pragma unroll
        for (int nf = 0; nf < 4; ++nf)
            #pragma unroll
            for (int e = 0; e < 4; ++e) sacc[nf][e] = 0.f;

        #pragma unroll 4
        for (int kf = 0; kf < 16; ++kf) {
            const uint32_t kb = kf * 32;
            uint32_t qh[4], ql[4], kh[2][4], kl[2][4];
            ldsm_x4(qh, sb + SM_QH + (wm*16) * AT_STRIDE + kb + offA);
            ldsm_x4(ql, sb + SM_QL + (wm*16) * AT_STRIDE + kb + offA);
            ldsm_x4(kh[0], sb + SM_KH + (wn*32)      * AT_STRIDE + kb + offB);
            ldsm_x4(kh[1], sb + SM_KH + (wn*32 + 16) * AT_STRIDE + kb + offB);
            ldsm_x4(kl[0], sb + SM_KL + (wn*32)      * AT_STRIDE + kb + offB);
            ldsm_x4(kl[1], sb + SM_KL + (wn*32 + 16) * AT_STRIDE + kb + offB);
            #pragma unroll
            for (int nf = 0; nf < 4; ++nf) {
                mma16816(sacc[nf], qh, kh[nf>>1][(nf&1)*2], kh[nf>>1][(nf&1)*2+1]);
                mma16816(sacc[nf], qh, kl[nf>>1][(nf&1)*2], kl[nf>>1][(nf&1)*2+1]);
                mma16816(sacc[nf], ql, kh[nf>>1][(nf&1)*2], kh[nf>>1][(nf&1)*2+1]);
            }
        }

        __syncthreads();                 // all warps done reading K(jb)
        if (pre) { load_k(jb + 1); CP_COMMIT(); }   // K(jb+1) hidden behind weights + phase B

        // ---- weight + split hi/lo into Sw staging ----
        const float wbase = exp2f(l2d * (float)((jb - ib) * 64 - 1));
        const bool diag = (jb == ib);
        #pragma unroll
        for (int nf = 0; nf < 4; ++nf) {
            const int cl = wn*32 + nf*8 + (lane & 3)*2;
            float ec0 = exp2f(l2d * (float)cl);
            float ec1 = ec0 * decay;
            float w00 = wbase*ec0*er0, w01 = wbase*ec1*er0;
            float w10 = wbase*ec0*er1, w11 = wbase*ec1*er1;
            if (diag) {
                if (cl     <= rl0)     w00 = 0.f;
                if (cl + 1 <= rl0)     w01 = 0.f;
                if (cl     <= rl0 + 8) w10 = 0.f;
                if (cl + 1 <= rl0 + 8) w11 = 0.f;
            }
            float v00 = sacc[nf][0]*w00, v01 = sacc[nf][1]*w01;
            float v10 = sacc[nf][2]*w10, v11 = sacc[nf][3]*w11;

            #pragma unroll
            for (int h = 0; h < 2; ++h) {
                float a = h ? v10 : v00, c = h ? v11 : v01;
                __nv_bfloat16 ha, hc;
                uint32_t ph = pack_hilo_b(a, c, ha, hc);
                float ra = a - __bfloat162float(ha), rc = c - __bfloat162float(hc);
                __nv_bfloat16 t0, t1;
                uint32_t pl = pack_hilo_b(ra, rc, t0, t1);
                uint32_t off = (rl0 + h*8) * SW_STRIDE + cl * 2;
                *(uint32_t*)(shm + SM_SWH + off) = ph;
                *(uint32_t*)(shm + SM_SWL + off) = pl;
            }
        }

        if (pre) CP_WAIT1();             // V(jb) ready (K(jb+1) in flight)
        else     CP_WAIT0();
        __syncthreads();                 // Sw visible; V ready

        // ---- phase B: out += Sw @ V ----
        uint32_t sh4[4][4], sl4[4][4];
        #pragma unroll
        for (int kf = 0; kf < 4; ++kf) {
            ldsm_x4(sh4[kf], sb + SM_SWH + (wm*16) * SW_STRIDE + kf*32 + offAs);
            ldsm_x4(sl4[kf], sb + SM_SWL + (wm*16) * SW_STRIDE + kf*32 + offAs);
        }
        #pragma unroll
        for (int nb = 0; nb < 8; ++nb) {
            const uint32_t d0b = (uint32_t)(wn*128 + nb*16) * 2;
            #pragma unroll
            for (int kf = 0; kf < 4; ++kf) {
                uint32_t vh[4], vl[4];
                const uint32_t va = sb + (kf*16) * AT_STRIDE + d0b + offV;
                ldsm_x4_t(vh, va + SM_VH);
                ldsm_x4_t(vl, va + SM_VL);
                mma16816(oacc[nb][0], sh4[kf], vh[0], vh[1]);
                mma16816(oacc[nb][1], sh4[kf], vh[2], vh[3]);
                mma16816(oacc[nb][0], sh4[kf], vl[0], vl[1]);
                mma16816(oacc[nb][1], sh4[kf], vl[2], vl[3]);
                mma16816(oacc[nb][0], sl4[kf], vh[0], vh[1]);
                mma16816(oacc[nb][1], sl4[kf], vh[2], vh[3]);
            }
        }
        __syncthreads();                 // all warps done reading V(jb) / Sw
        if (pre) { load_v(jb + 1); CP_COMMIT(); }   // V(jb+1) hidden behind next phase A
    }

    // ---- fused epilogue: write r as single fp16 ----
    const size_t rrow = (size_t)(qrow0 + wm*16 + (lane >> 2)) * D_;
    #pragma unroll
    for (int nb = 0; nb < 8; ++nb) {
        #pragma unroll
        for (int g = 0; g < 2; ++g) {
            const int c = wn*128 + nb*16 + g*8 + (lane & 3) * 2;
            #pragma unroll
            for (int h = 0; h < 2; ++h) {
                uint32_t ph = pack_h2(oacc[nb][g][h*2], oacc[nb][g][h*2+1]);
                *(uint32_t*)(g_rf + rrow + (size_t)h * 8 * D_ + c) = ph;
            }
        }
    }
}

// ================= launch =================
#define GEMM_SMEM (NSTAGE*GSTG)

extern "C" void kernel_launch(void* const* d_in, const int* in_sizes, int n_in,
                              void* d_out, int out_size)
{
    const float* x  = (const float*)d_in[0];
    const float* wq = (const float*)d_in[1];
    const float* wk = (const float*)d_in[2];
    const float* wv = (const float*)d_in[3];
    const float* wo = (const float*)d_in[4];
    const float* dl = (const float*)d_in[5];
    const float* os = (const float*)d_in[6];
    float* out = (float*)d_out;

    cudaFuncSetAttribute(hmma_qkv_kernel, cudaFuncAttributeMaxDynamicSharedMemorySize, GEMM_SMEM);
    cudaFuncSetAttribute(hmma_out_kernel, cudaFuncAttributeMaxDynamicSharedMemorySize, GEMM_SMEM);
    cudaFuncSetAttribute(attn_hmma_kernel, cudaFuncAttributeMaxDynamicSharedMemorySize, ATT_SMEM);

    cvt_all_kernel<<<XBLKS + 4*WBLKS, 256>>>(x, wq, wk, wv, wo);

    hmma_qkv_kernel<<<dim3(2, 64, 6), 256, GEMM_SMEM>>>();

    reduce_qkv_kernel<<<3*2048, 256>>>();

    attn_hmma_kernel<<<dim3(T_/64, B_), 256, ATT_SMEM>>>(dl);

    hmma_out_kernel<<<dim3(64, 64), 256, GEMM_SMEM>>>(os, out);
}

// round 16
// speedup vs baseline: 3.2022x; 1.0090x over previous
#include <cuda_runtime.h>
#include <cuda_bf16.h>
#include <cuda_fp16.h>
#include <cstdint>

#define B_ 4
#define T_ 2048
#define V_ 8192
#define D_ 256
#define M_ (B_*T_)   // 8192 rows of (b,t)

// ---------------- scratch (device globals; no allocs allowed) ----------------
__device__ __half g_xf[(size_t)M_*V_];      // single fp16 x
__device__ __half g_wf[3*(size_t)D_*V_];
__device__ __half g_wof[(size_t)V_*D_];
__device__ __half g_rf[(size_t)M_*D_];      // single fp16 r

// split-K fp32 partials for qkv: 6 slabs of M_*D_ (z = w*2 + khalf)
__device__ float g_part[6*(size_t)M_*D_];

// bf16 hi/lo q,k,v (attention stays 3-pass bf16)
__device__ __nv_bfloat16 g_qbh[(size_t)M_*D_];
__device__ __nv_bfloat16 g_qbl[(size_t)M_*D_];
__device__ __nv_bfloat16 g_kbh[(size_t)M_*D_];
__device__ __nv_bfloat16 g_kbl[(size_t)M_*D_];
__device__ __nv_bfloat16 g_vbh[(size_t)M_*D_];
__device__ __nv_bfloat16 g_vbl[(size_t)M_*D_];

// ---------------- helpers ----------------
__device__ __forceinline__ uint32_t smem_u32(const void* p){
    uint32_t a;
    asm("{ .reg .u64 t; cvta.to.shared.u64 t, %1; cvt.u32.u64 %0, t; }" : "=r"(a) : "l"(p));
    return a;
}
#define CP16(smem, gptr) \
    asm volatile("cp.async.cg.shared.global [%0], [%1], 16;" :: "r"(smem), "l"(gptr))
#define CP_COMMIT() asm volatile("cp.async.commit_group;" ::: "memory")
#define CP_WAIT2()  asm volatile("cp.async.wait_group 2;" ::: "memory")
#define CP_WAIT1()  asm volatile("cp.async.wait_group 1;" ::: "memory")
#define CP_WAIT0()  asm volatile("cp.async.wait_group 0;" ::: "memory")

__device__ __forceinline__ void ldsm_x4(uint32_t (&r)[4], uint32_t addr){
    asm volatile("ldmatrix.sync.aligned.m8n8.x4.shared.b16 {%0,%1,%2,%3}, [%4];"
        : "=r"(r[0]), "=r"(r[1]), "=r"(r[2]), "=r"(r[3]) : "r"(addr));
}
__device__ __forceinline__ void ldsm_x4_t(uint32_t (&r)[4], uint32_t addr){
    asm volatile("ldmatrix.sync.aligned.m8n8.x4.trans.shared.b16 {%0,%1,%2,%3}, [%4];"
        : "=r"(r[0]), "=r"(r[1]), "=r"(r[2]), "=r"(r[3]) : "r"(addr));
}
// bf16 mma (attention)
__device__ __forceinline__ void mma16816(float (&d)[4], const uint32_t (&a)[4],
                                         uint32_t b0, uint32_t b1){
    asm volatile("mma.sync.aligned.m16n8k16.row.col.f32.bf16.bf16.f32 "
        "{%0,%1,%2,%3}, {%4,%5,%6,%7}, {%8,%9}, {%0,%1,%2,%3};"
        : "+f"(d[0]), "+f"(d[1]), "+f"(d[2]), "+f"(d[3])
        : "r"(a[0]), "r"(a[1]), "r"(a[2]), "r"(a[3]), "r"(b0), "r"(b1));
}
// fp16 mma (projection GEMMs)
__device__ __forceinline__ void mma16816h(float (&d)[4], const uint32_t (&a)[4],
                                          uint32_t b0, uint32_t b1){
    asm volatile("mma.sync.aligned.m16n8k16.row.col.f32.f16.f16.f32 "
        "{%0,%1,%2,%3}, {%4,%5,%6,%7}, {%8,%9}, {%0,%1,%2,%3};"
        : "+f"(d[0]), "+f"(d[1]), "+f"(d[2]), "+f"(d[3])
        : "r"(a[0]), "r"(a[1]), "r"(a[2]), "r"(a[3]), "r"(b0), "r"(b1));
}
__device__ __forceinline__ uint32_t pack_hilo_b(float a, float c,
                                                __nv_bfloat16& ra, __nv_bfloat16& rc){
    ra = __float2bfloat16(a);
    rc = __float2bfloat16(c);
    return (uint32_t)*(uint16_t*)&ra | ((uint32_t)*(uint16_t*)&rc << 16);
}
__device__ __forceinline__ uint32_t pack_h2(float a, float c){
    __half ra = __float2half_rn(a);
    __half rc = __float2half_rn(c);
    return (uint32_t)*(uint16_t*)&ra | ((uint32_t)*(uint16_t*)&rc << 16);
}

// ================= merged conversion kernel: x + all weights -> fp16 =================
#define XBLKS ((int)(((size_t)M_*V_)/4096))      // 16384
#define WBLKS 512

__global__ void __launch_bounds__(256)
cvt_all_kernel(const float* __restrict__ x,
               const float* __restrict__ wq, const float* __restrict__ wk,
               const float* __restrict__ wv, const float* __restrict__ wo)
{
    const float* in;
    __half* outp;
    int blk;
    if (blockIdx.x < XBLKS) {
        in = x; outp = g_xf; blk = blockIdx.x;
    } else {
        const int wb = blockIdx.x - XBLKS;
        const int sel = wb >> 9;
        blk = wb & (WBLKS - 1);
        switch (sel) {
            case 0: in = wq; outp = g_wf;                 break;
            case 1: in = wk; outp = g_wf + (size_t)D_*V_;   break;
            case 2: in = wv; outp = g_wf + 2*(size_t)D_*V_; break;
            default: in = wo; outp = g_wof;               break;
        }
    }
    const size_t base = (size_t)blk * 4096 + threadIdx.x * 4;
    float4 v[4];
    #pragma unroll
    for (int j = 0; j < 4; ++j) v[j] = *(const float4*)(in + base + j * 1024);
    #pragma unroll
    for (int j = 0; j < 4; ++j) {
        const size_t i = base + j * 1024;
        float f[4] = {v[j].x, v[j].y, v[j].z, v[j].w};
        union { __half b[4]; uint2 u; } H;
        #pragma unroll
        for (int e = 0; e < 4; ++e) H.b[e] = __float2half_rn(f[e]);
        *(uint2*)(outp + i) = H.u;
    }
}

// ================= split-K reduce: partials -> bf16 hi/lo q/k/v =================
__global__ void __launch_bounds__(256)
reduce_qkv_kernel()
{
    const int w   = blockIdx.x >> 11;
    const int blk = blockIdx.x & 2047;
    const size_t base = (size_t)blk * 1024 + threadIdx.x * 4;
    const float* p0 = g_part + (size_t)(2*w)   * ((size_t)M_*D_);
    const float* p1 = g_part + (size_t)(2*w+1) * ((size_t)M_*D_);
    __nv_bfloat16* hi = (w==0) ? g_qbh : (w==1) ? g_kbh : g_vbh;
    __nv_bfloat16* lo = (w==0) ? g_qbl : (w==1) ? g_kbl : g_vbl;
    float4 a = *(const float4*)(p0 + base);
    float4 b = *(const float4*)(p1 + base);
    float f[4] = {a.x+b.x, a.y+b.y, a.z+b.z, a.w+b.w};
    union { __nv_bfloat16 b[4]; uint2 u; } H, L;
    #pragma unroll
    for (int e = 0; e < 4; ++e) {
        __nv_bfloat16 h = __float2bfloat16(f[e]);
        float r = f[e] - __bfloat162float(h);
        H.b[e] = h;
        L.b[e] = __float2bfloat16(r);
    }
    *(uint2*)(hi + base) = H.u;
    *(uint2*)(lo + base) = L.u;
}

// ================= fp16 1-pass NT GEMM, BK=64, 3-stage cp.async ring =================
#define LDS_B 144
#define GSTG  36864
#define GT_B  18432
#define NSTAGE 3

__device__ __forceinline__ void hmma_gemm_body(
    const __half* __restrict__ Ag, const __half* __restrict__ Bg,
    float* __restrict__ Cf,
    int K, int ldAB, int ldC, float scale, int row0, int col0)
{
    extern __shared__ __align__(128) char sm[];
    const int tid  = threadIdx.x;
    const int lane = tid & 31;
    const int wid  = tid >> 5;
    const int wm   = wid >> 2;
    const int wn   = wid & 3;
    const uint32_t sbase = smem_u32(sm);

    float acc[4][4][4];
    #pragma unroll
    for (int a = 0; a < 4; ++a)
        #pragma unroll
        for (int b = 0; b < 4; ++b)
            #pragma unroll
            for (int c = 0; c < 4; ++c) acc[a][b][c] = 0.f;

    auto load_stage = [&](int c, int s){
        const uint32_t sb = sbase + s * GSTG;
        #pragma unroll
        for (int q = 0; q < 4; ++q) {
            const int idx = tid + q * 256;
            const int r = idx >> 3, seg = idx & 7;
            const size_t k0 = (size_t)c * 64 + seg * 8;
            const uint32_t soff = r * LDS_B + seg * 16;
            CP16(sb + soff,        Ag + (size_t)(row0 + r) * ldAB + k0);
            CP16(sb + GT_B + soff, Bg + (size_t)(col0 + r) * ldAB + k0);
        }
    };

    const uint32_t offA = (lane & 15) * LDS_B + (lane >> 4) * 16;
    const uint32_t offB = ((lane & 7) + ((lane >> 4) & 1) * 8) * LDS_B
                        + ((lane >> 3) & 1) * 16;

    const int NC = K / 64;

    load_stage(0, 0); CP_COMMIT();
    if (NC > 1) { load_stage(1, 1); CP_COMMIT(); }

    int sidx = 0;
    for (int c = 0; c < NC; ++c) {
        if (c + 1 < NC) CP_WAIT1();
        else            CP_WAIT0();
        __syncthreads();

        const uint32_t sb = sbase + sidx * GSTG;
        #pragma unroll
        for (int kk = 0; kk < 4; ++kk) {
            const uint32_t kb = kk * 32;
            uint32_t ah[4][4], bb[2][4];
            #pragma unroll
            for (int mf = 0; mf < 4; ++mf)
                ldsm_x4(ah[mf], sb + (wm*64 + mf*16) * LDS_B + kb + offA);
            #pragma unroll
            for (int g = 0; g < 2; ++g)
                ldsm_x4(bb[g], sb + GT_B + (wn*32 + g*16) * LDS_B + kb + offB);
            #pragma unroll
            for (int mf = 0; mf < 4; ++mf)
                #pragma unroll
                for (int nf = 0; nf < 4; ++nf)
                    mma16816h(acc[mf][nf], ah[mf], bb[nf>>1][(nf&1)*2], bb[nf>>1][(nf&1)*2+1]);
        }

        if (c + 2 < NC) {
            int s2 = sidx + 2; if (s2 >= NSTAGE) s2 -= NSTAGE;
            load_stage(c + 2, s2);
            CP_COMMIT();
        }
        if (++sidx == NSTAGE) sidx = 0;
    }

    #pragma unroll
    for (int mf = 0; mf < 4; ++mf) {
        const int r0 = row0 + wm*64 + mf*16 + (lane >> 2);
        #pragma unroll
        for (int nf = 0; nf < 4; ++nf) {
            const int cc = col0 + wn*32 + nf*8 + (lane & 3) * 2;
            float2 v0 = { acc[mf][nf][0] * scale, acc[mf][nf][1] * scale };
            float2 v1 = { acc[mf][nf][2] * scale, acc[mf][nf][3] * scale };
            *(float2*)(Cf + (size_t)r0 * ldC + cc)       = v0;
            *(float2*)(Cf + (size_t)(r0 + 8) * ldC + cc) = v1;
        }
    }
}

// ---- QKV split-K: grid (2 Ntiles, 64 Mtiles, 6 = weight*2 + khalf) ----
__global__ void __launch_bounds__(256, 2)
hmma_qkv_kernel()
{
    const int z = blockIdx.z;
    const int w = z >> 1, kh = z & 1;
    const size_t koff = (size_t)kh * 4096;
    const __half* Bg = g_wf + (size_t)w * D_ * V_ + koff;
    float* Cf = g_part + (size_t)z * ((size_t)M_*D_);
    hmma_gemm_body(g_xf + koff, Bg, Cf,
                   4096, V_, D_, 1.0f, blockIdx.y * 128, blockIdx.x * 128);
}

// ---- OUT: grid (64 Ntiles, 64 Mtiles) ----
__global__ void __launch_bounds__(256, 2)
hmma_out_kernel(const float* __restrict__ out_scale, float* __restrict__ out)
{
    hmma_gemm_body(g_rf, g_wof, out,
                   D_, D_, V_, out_scale[0], blockIdx.y * 128, blockIdx.x * 128);
}

// ================= HMMA attention (bf16 3-pass, K/V ring-prefetched) =================
#define AT_STRIDE 528
#define SW_STRIDE 144
#define SM_QH 0
#define SM_QL 33792
#define SM_KH 67584
#define SM_KL 101376
#define SM_VH 135168
#define SM_VL 168960
#define SM_SWH 202752
#define SM_SWL 211968
#define ATT_SMEM 221184

__global__ void __launch_bounds__(256, 1)
attn_hmma_kernel(const float* __restrict__ dlp)
{
    extern __shared__ __align__(128) char shm[];
    const int tid = threadIdx.x, lane = tid & 31, wid = tid >> 5;
    const int wm = wid >> 1, wn = wid & 1;
    const int ib = blockIdx.x, b = blockIdx.y;
    const uint32_t sb = smem_u32(shm);

    const float logit = dlp[0];
    const float decay = 1.f / (1.f + expf(-logit));
    const float l2d   = log2f(decay);

    const int qrow0 = b * T_ + ib * 64;

    // ---- loop extent ----
    int nblk = 1;
    while (ib + nblk < T_/64) {
        int emin = nblk * 64 - 64;
        if (emin > 0 && l2d * (float)emin < -13.f) break;
        ++nblk;
    }
    const int jb_end = ib + nblk;

    auto load_k = [&](int jb){
        const int krow0 = b * T_ + jb * 64;
        #pragma unroll
        for (int it = 0; it < 8; ++it) {
            int idx = it * 256 + tid;
            int r = idx >> 5, s = idx & 31;
            uint32_t soff = r * AT_STRIDE + s * 16;
            size_t gb = ((size_t)(krow0 + r) * D_) * 2 + s * 16;
            CP16(sb + SM_KH + soff, (const char*)g_kbh + gb);
            CP16(sb + SM_KL + soff, (const char*)g_kbl + gb);
        }
    };
    auto load_v = [&](int jb){
        const int krow0 = b * T_ + jb * 64;
        #pragma unroll
        for (int it = 0; it < 8; ++it) {
            int idx = it * 256 + tid;
            int r = idx >> 5, s = idx & 31;
            uint32_t soff = r * AT_STRIDE + s * 16;
            size_t gb = ((size_t)(krow0 + r) * D_) * 2 + s * 16;
            CP16(sb + SM_VH + soff, (const char*)g_vbh + gb);
            CP16(sb + SM_VL + soff, (const char*)g_vbl + gb);
        }
    };

    // ---- prologue: Q, K(ib), V(ib) ----
    #pragma unroll
    for (int it = 0; it < 8; ++it) {
        int idx = it * 256 + tid;
        int r = idx >> 5, s = idx & 31;
        uint32_t soff = r * AT_STRIDE + s * 16;
        size_t gb = ((size_t)(qrow0 + r) * D_) * 2 + s * 16;
        CP16(sb + SM_QH + soff, (const char*)g_qbh + gb);
        CP16(sb + SM_QL + soff, (const char*)g_qbl + gb);
    }
    CP_COMMIT();
    load_k(ib); CP_COMMIT();
    load_v(ib); CP_COMMIT();

    float oacc[8][2][4];
    #pragma unroll
    for (int a = 0; a < 8; ++a)
        #pragma unroll
        for (int g = 0; g < 2; ++g)
            #pragma unroll
            for (int e = 0; e < 4; ++e) oacc[a][g][e] = 0.f;

    const uint32_t offA  = (lane & 15) * AT_STRIDE + (lane >> 4) * 16;
    const uint32_t offB  = ((lane & 7) + ((lane >> 4) & 1) * 8) * AT_STRIDE
                         + ((lane >> 3) & 1) * 16;
    const uint32_t offAs = (lane & 15) * SW_STRIDE + (lane >> 4) * 16;
    const uint32_t offV  = ((lane & 7) + ((lane >> 3) & 1) * 8) * AT_STRIDE
                         + (lane >> 4) * 16;

    const int rl0 = wm * 16 + (lane >> 2);
    const float er0 = exp2f(-l2d * (float)rl0);
    const float er1 = er0 * exp2f(-l2d * 8.f);

    CP_WAIT2();        // Q ready (K/V may be in flight)
    __syncthreads();

    for (int jb = ib; jb < jb_end; ++jb) {
        const bool pre = (jb + 1 < jb_end);

        CP_WAIT1();    // K(jb) ready (V(jb) in flight)
        __syncthreads();

        // ---- phase A: S = Q K^T, 3-pass bf16 ----
        float sacc[4][4];
        #pragma unroll
        for (int nf = 0; nf < 4; ++nf)
            #pragma unroll
            for (int e = 0; e < 4; ++e) sacc[nf][e] = 0.f;

        #pragma unroll 4
        for (int kf = 0; kf < 16; ++kf) {
            const uint32_t kb = kf * 32;
            uint32_t qh[4], ql[4], kh[2][4], kl[2][4];
            ldsm_x4(qh, sb + SM_QH + (wm*16) * AT_STRIDE + kb + offA);
            ldsm_x4(ql, sb + SM_QL + (wm*16) * AT_STRIDE + kb + offA);
            ldsm_x4(kh[0], sb + SM_KH + (wn*32)      * AT_STRIDE + kb + offB);
            ldsm_x4(kh[1], sb + SM_KH + (wn*32 + 16) * AT_STRIDE + kb + offB);
            ldsm_x4(kl[0], sb + SM_KL + (wn*32)      * AT_STRIDE + kb + offB);
            ldsm_x4(kl[1], sb + SM_KL + (wn*32 + 16) * AT_STRIDE + kb + offB);
            #pragma unroll
            for (int nf = 0; nf < 4; ++nf) {
                mma16816(sacc[nf], qh, kh[nf>>1][(nf&1)*2], kh[nf>>1][(nf&1)*2+1]);
                mma16816(sacc[nf], qh, kl[nf>>1][(nf&1)*2], kl[nf>>1][(nf&1)*2+1]);
                mma16816(sacc[nf], ql, kh[nf>>1][(nf&1)*2], kh[nf>>1][(nf&1)*2+1]);
            }
        }

        __syncthreads();                 // all warps done reading K(jb)
        if (pre) { load_k(jb + 1); CP_COMMIT(); }

        // ---- weight + split hi/lo into Sw staging ----
        const float wbase = exp2f(l2d * (float)((jb - ib) * 64 - 1));
        const bool diag = (jb == ib);
        #pragma unroll
        for (int nf = 0; nf < 4; ++nf) {
            const int cl = wn*32 + nf*8 + (lane & 3)*2;
            float ec0 = exp2f(l2d * (float)cl);
            float ec1 = ec0 * decay;
            float w00 = wbase*ec0*er0, w01 = wbase*ec1*er0;
            float w10 = wbase*ec0*er1, w11 = wbase*ec1*er1;
            if (diag) {
                if (cl     <= rl0)     w00 = 0.f;
                if (cl + 1 <= rl0)     w01 = 0.f;
                if (cl     <= rl0 + 8) w10 = 0.f;
                if (cl + 1 <= rl0 + 8) w11 = 0.f;
            }
            float v00 = sacc[nf][0]*w00, v01 = sacc[nf][1]*w01;
            float v10 = sacc[nf][2]*w10, v11 = sacc[nf][3]*w11;

            #pragma unroll
            for (int h = 0; h < 2; ++h) {
                float a = h ? v10 : v00, c = h ? v11 : v01;
                __nv_bfloat16 ha, hc;
                uint32_t ph = pack_hilo_b(a, c, ha, hc);
                float ra = a - __bfloat162float(ha), rc = c - __bfloat162float(hc);
                __nv_bfloat16 t0, t1;
                uint32_t pl = pack_hilo_b(ra, rc, t0, t1);
                uint32_t off = (rl0 + h*8) * SW_STRIDE + cl * 2;
                *(uint32_t*)(shm + SM_SWH + off) = ph;
                *(uint32_t*)(shm + SM_SWL + off) = pl;
            }
        }

        if (pre) CP_WAIT1();             // V(jb) ready (K(jb+1) in flight)
        else     CP_WAIT0();
        __syncthreads();                 // Sw visible; V ready

        // ---- phase B: out += Sw @ V ----
        uint32_t sh4[4][4], sl4[4][4];
        #pragma unroll
        for (int kf = 0; kf < 4; ++kf) {
            ldsm_x4(sh4[kf], sb + SM_SWH + (wm*16) * SW_STRIDE + kf*32 + offAs);
            ldsm_x4(sl4[kf], sb + SM_SWL + (wm*16) * SW_STRIDE + kf*32 + offAs);
        }
        #pragma unroll
        for (int nb = 0; nb < 8; ++nb) {
            const uint32_t d0b = (uint32_t)(wn*128 + nb*16) * 2;
            #pragma unroll
            for (int kf = 0; kf < 4; ++kf) {
                uint32_t vh[4], vl[4];
                const uint32_t va = sb + (kf*16) * AT_STRIDE + d0b + offV;
                ldsm_x4_t(vh, va + SM_VH);
                ldsm_x4_t(vl, va + SM_VL);
                mma16816(oacc[nb][0], sh4[kf], vh[0], vh[1]);
                mma16816(oacc[nb][1], sh4[kf], vh[2], vh[3]);
                mma16816(oacc[nb][0], sh4[kf], vl[0], vl[1]);
                mma16816(oacc[nb][1], sh4[kf], vl[2], vl[3]);
                mma16816(oacc[nb][0], sl4[kf], vh[0], vh[1]);
                mma16816(oacc[nb][1], sl4[kf], vh[2], vh[3]);
            }
        }
        __syncthreads();                 // all warps done reading V(jb) / Sw
        if (pre) { load_v(jb + 1); CP_COMMIT(); }
    }

    // ---- fused epilogue: write r as single fp16 ----
    const size_t rrow = (size_t)(qrow0 + wm*16 + (lane >> 2)) * D_;
    #pragma unroll
    for (int nb = 0; nb < 8; ++nb) {
        #pragma unroll
        for (int g = 0; g < 2; ++g) {
            const int c = wn*128 + nb*16 + g*8 + (lane & 3) * 2;
            #pragma unroll
            for (int h = 0; h < 2; ++h) {
                uint32_t ph = pack_h2(oacc[nb][g][h*2], oacc[nb][g][h*2+1]);
                *(uint32_t*)(g_rf + rrow + (size_t)h * 8 * D_ + c) = ph;
            }
        }
    }
}

// ================= launch =================
#define GEMM_SMEM (NSTAGE*GSTG)

extern "C" void kernel_launch(void* const* d_in, const int* in_sizes, int n_in,
                              void* d_out, int out_size)
{
    const float* x  = (const float*)d_in[0];
    const float* wq = (const float*)d_in[1];
    const float* wk = (const float*)d_in[2];
    const float* wv = (const float*)d_in[3];
    const float* wo = (const float*)d_in[4];
    const float* dl = (const float*)d_in[5];
    const float* os = (const float*)d_in[6];
    float* out = (float*)d_out;

    cudaFuncSetAttribute(hmma_qkv_kernel, cudaFuncAttributeMaxDynamicSharedMemorySize, GEMM_SMEM);
    cudaFuncSetAttribute(hmma_out_kernel, cudaFuncAttributeMaxDynamicSharedMemorySize, GEMM_SMEM);
    cudaFuncSetAttribute(attn_hmma_kernel, cudaFuncAttributeMaxDynamicSharedMemorySize, ATT_SMEM);

    cvt_all_kernel<<<XBLKS + 4*WBLKS, 256>>>(x, wq, wk, wv, wo);

    hmma_qkv_kernel<<<dim3(2, 64, 6), 256, GEMM_SMEM>>>();

    reduce_qkv_kernel<<<3*2048, 256>>>();

    attn_hmma_kernel<<<dim3(T_/64, B_), 256, ATT_SMEM>>>(dl);

    hmma_out_kernel<<<dim3(64, 64), 256, GEMM_SMEM>>>(os, out);
}

// round 17
// speedup vs baseline: 3.2675x; 1.0204x over previous
#include <cuda_runtime.h>
#include <cuda_bf16.h>
#include <cuda_fp16.h>
#include <cstdint>

#define B_ 4
#define T_ 2048
#define V_ 8192
#define D_ 256
#define M_ (B_*T_)   // 8192 rows of (b,t)

// ---------------- scratch (device globals; no allocs allowed) ----------------
__device__ __half g_xf[(size_t)M_*V_];      // single fp16 x
__device__ __half g_wf[3*(size_t)D_*V_];
__device__ __half g_wof[(size_t)V_*D_];
__device__ __half g_rf[(size_t)M_*D_];      // single fp16 r

// split-K fp32 partials for qkv: 9 slabs of M_*D_ (z = w*3 + ks)
__device__ float g_part[9*(size_t)M_*D_];

// bf16 hi/lo q,k,v (attention stays 3-pass bf16)
__device__ __nv_bfloat16 g_qbh[(size_t)M_*D_];
__device__ __nv_bfloat16 g_qbl[(size_t)M_*D_];
__device__ __nv_bfloat16 g_kbh[(size_t)M_*D_];
__device__ __nv_bfloat16 g_kbl[(size_t)M_*D_];
__device__ __nv_bfloat16 g_vbh[(size_t)M_*D_];
__device__ __nv_bfloat16 g_vbl[(size_t)M_*D_];

// ---------------- helpers ----------------
__device__ __forceinline__ uint32_t smem_u32(const void* p){
    uint32_t a;
    asm("{ .reg .u64 t; cvta.to.shared.u64 t, %1; cvt.u32.u64 %0, t; }" : "=r"(a) : "l"(p));
    return a;
}
#define CP16(smem, gptr) \
    asm volatile("cp.async.cg.shared.global [%0], [%1], 16;" :: "r"(smem), "l"(gptr))
#define CP_COMMIT() asm volatile("cp.async.commit_group;" ::: "memory")
#define CP_WAIT2()  asm volatile("cp.async.wait_group 2;" ::: "memory")
#define CP_WAIT1()  asm volatile("cp.async.wait_group 1;" ::: "memory")
#define CP_WAIT0()  asm volatile("cp.async.wait_group 0;" ::: "memory")

__device__ __forceinline__ void ldsm_x4(uint32_t (&r)[4], uint32_t addr){
    asm volatile("ldmatrix.sync.aligned.m8n8.x4.shared.b16 {%0,%1,%2,%3}, [%4];"
        : "=r"(r[0]), "=r"(r[1]), "=r"(r[2]), "=r"(r[3]) : "r"(addr));
}
__device__ __forceinline__ void ldsm_x4_t(uint32_t (&r)[4], uint32_t addr){
    asm volatile("ldmatrix.sync.aligned.m8n8.x4.trans.shared.b16 {%0,%1,%2,%3}, [%4];"
        : "=r"(r[0]), "=r"(r[1]), "=r"(r[2]), "=r"(r[3]) : "r"(addr));
}
// bf16 mma (attention)
__device__ __forceinline__ void mma16816(float (&d)[4], const uint32_t (&a)[4],
                                         uint32_t b0, uint32_t b1){
    asm volatile("mma.sync.aligned.m16n8k16.row.col.f32.bf16.bf16.f32 "
        "{%0,%1,%2,%3}, {%4,%5,%6,%7}, {%8,%9}, {%0,%1,%2,%3};"
        : "+f"(d[0]), "+f"(d[1]), "+f"(d[2]), "+f"(d[3])
        : "r"(a[0]), "r"(a[1]), "r"(a[2]), "r"(a[3]), "r"(b0), "r"(b1));
}
// fp16 mma (projection GEMMs)
__device__ __forceinline__ void mma16816h(float (&d)[4], const uint32_t (&a)[4],
                                          uint32_t b0, uint32_t b1){
    asm volatile("mma.sync.aligned.m16n8k16.row.col.f32.f16.f16.f32 "
        "{%0,%1,%2,%3}, {%4,%5,%6,%7}, {%8,%9}, {%0,%1,%2,%3};"
        : "+f"(d[0]), "+f"(d[1]), "+f"(d[2]), "+f"(d[3])
        : "r"(a[0]), "r"(a[1]), "r"(a[2]), "r"(a[3]), "r"(b0), "r"(b1));
}
__device__ __forceinline__ uint32_t pack_hilo_b(float a, float c,
                                                __nv_bfloat16& ra, __nv_bfloat16& rc){
    ra = __float2bfloat16(a);
    rc = __float2bfloat16(c);
    return (uint32_t)*(uint16_t*)&ra | ((uint32_t)*(uint16_t*)&rc << 16);
}
__device__ __forceinline__ uint32_t pack_h2(float a, float c){
    __half ra = __float2half_rn(a);
    __half rc = __float2half_rn(c);
    return (uint32_t)*(uint16_t*)&ra | ((uint32_t)*(uint16_t*)&rc << 16);
}

// ================= merged conversion kernel: x + all weights -> fp16 =================
#define XBLKS ((int)(((size_t)M_*V_)/4096))      // 16384
#define WBLKS 512

__global__ void __launch_bounds__(256)
cvt_all_kernel(const float* __restrict__ x,
               const float* __restrict__ wq, const float* __restrict__ wk,
               const float* __restrict__ wv, const float* __restrict__ wo)
{
    const float* in;
    __half* outp;
    int blk;
    if (blockIdx.x < XBLKS) {
        in = x; outp = g_xf; blk = blockIdx.x;
    } else {
        const int wb = blockIdx.x - XBLKS;
        const int sel = wb >> 9;
        blk = wb & (WBLKS - 1);
        switch (sel) {
            case 0: in = wq; outp = g_wf;                 break;
            case 1: in = wk; outp = g_wf + (size_t)D_*V_;   break;
            case 2: in = wv; outp = g_wf + 2*(size_t)D_*V_; break;
            default: in = wo; outp = g_wof;               break;
        }
    }
    const size_t base = (size_t)blk * 4096 + threadIdx.x * 4;
    float4 v[4];
    #pragma unroll
    for (int j = 0; j < 4; ++j) v[j] = *(const float4*)(in + base + j * 1024);
    #pragma unroll
    for (int j = 0; j < 4; ++j) {
        const size_t i = base + j * 1024;
        float f[4] = {v[j].x, v[j].y, v[j].z, v[j].w};
        union { __half b[4]; uint2 u; } H;
        #pragma unroll
        for (int e = 0; e < 4; ++e) H.b[e] = __float2half_rn(f[e]);
        *(uint2*)(outp + i) = H.u;
    }
}

// ================= split-K reduce (3-way): partials -> bf16 hi/lo q/k/v =================
__global__ void __launch_bounds__(256)
reduce_qkv_kernel()
{
    const int w   = blockIdx.x >> 11;
    const int blk = blockIdx.x & 2047;
    const size_t base = (size_t)blk * 1024 + threadIdx.x * 4;
    const float* p0 = g_part + (size_t)(3*w)   * ((size_t)M_*D_);
    const float* p1 = g_part + (size_t)(3*w+1) * ((size_t)M_*D_);
    const float* p2 = g_part + (size_t)(3*w+2) * ((size_t)M_*D_);
    __nv_bfloat16* hi = (w==0) ? g_qbh : (w==1) ? g_kbh : g_vbh;
    __nv_bfloat16* lo = (w==0) ? g_qbl : (w==1) ? g_kbl : g_vbl;
    float4 a = *(const float4*)(p0 + base);
    float4 b = *(const float4*)(p1 + base);
    float4 c = *(const float4*)(p2 + base);
    float f[4] = {a.x+b.x+c.x, a.y+b.y+c.y, a.z+b.z+c.z, a.w+b.w+c.w};
    union { __nv_bfloat16 b[4]; uint2 u; } H, L;
    #pragma unroll
    for (int e = 0; e < 4; ++e) {
        __nv_bfloat16 h = __float2bfloat16(f[e]);
        float r = f[e] - __bfloat162float(h);
        H.b[e] = h;
        L.b[e] = __float2bfloat16(r);
    }
    *(uint2*)(hi + base) = H.u;
    *(uint2*)(lo + base) = L.u;
}

// ================= fp16 1-pass NT GEMM, BK=64, 3-stage cp.async ring =================
#define LDS_B 144
#define GSTG  36864
#define GT_B  18432
#define NSTAGE 3

__device__ __forceinline__ void hmma_gemm_body(
    const __half* __restrict__ Ag, const __half* __restrict__ Bg,
    float* __restrict__ Cf,
    int K, int ldAB, int ldC, float scale, int row0, int col0)
{
    extern __shared__ __align__(128) char sm[];
    const int tid  = threadIdx.x;
    const int lane = tid & 31;
    const int wid  = tid >> 5;
    const int wm   = wid >> 2;
    const int wn   = wid & 3;
    const uint32_t sbase = smem_u32(sm);

    float acc[4][4][4];
    #pragma unroll
    for (int a = 0; a < 4; ++a)
        #pragma unroll
        for (int b = 0; b < 4; ++b)
            #pragma unroll
            for (int c = 0; c < 4; ++c) acc[a][b][c] = 0.f;

    auto load_stage = [&](int c, int s){
        const uint32_t sb = sbase + s * GSTG;
        #pragma unroll
        for (int q = 0; q < 4; ++q) {
            const int idx = tid + q * 256;
            const int r = idx >> 3, seg = idx & 7;
            const size_t k0 = (size_t)c * 64 + seg * 8;
            const uint32_t soff = r * LDS_B + seg * 16;
            CP16(sb + soff,        Ag + (size_t)(row0 + r) * ldAB + k0);
            CP16(sb + GT_B + soff, Bg + (size_t)(col0 + r) * ldAB + k0);
        }
    };

    const uint32_t offA = (lane & 15) * LDS_B + (lane >> 4) * 16;
    const uint32_t offB = ((lane & 7) + ((lane >> 4) & 1) * 8) * LDS_B
                        + ((lane >> 3) & 1) * 16;

    const int NC = K / 64;

    load_stage(0, 0); CP_COMMIT();
    if (NC > 1) { load_stage(1, 1); CP_COMMIT(); }

    int sidx = 0;
    for (int c = 0; c < NC; ++c) {
        if (c + 1 < NC) CP_WAIT1();
        else            CP_WAIT0();
        __syncthreads();

        const uint32_t sb = sbase + sidx * GSTG;
        #pragma unroll
        for (int kk = 0; kk < 4; ++kk) {
            const uint32_t kb = kk * 32;
            uint32_t ah[4][4], bb[2][4];
            #pragma unroll
            for (int mf = 0; mf < 4; ++mf)
                ldsm_x4(ah[mf], sb + (wm*64 + mf*16) * LDS_B + kb + offA);
            #pragma unroll
            for (int g = 0; g < 2; ++g)
                ldsm_x4(bb[g], sb + GT_B + (wn*32 + g*16) * LDS_B + kb + offB);
            #pragma unroll
            for (int mf = 0; mf < 4; ++mf)
                #pragma unroll
                for (int nf = 0; nf < 4; ++nf)
                    mma16816h(acc[mf][nf], ah[mf], bb[nf>>1][(nf&1)*2], bb[nf>>1][(nf&1)*2+1]);
        }

        if (c + 2 < NC) {
            int s2 = sidx + 2; if (s2 >= NSTAGE) s2 -= NSTAGE;
            load_stage(c + 2, s2);
            CP_COMMIT();
        }
        if (++sidx == NSTAGE) sidx = 0;
    }

    #pragma unroll
    for (int mf = 0; mf < 4; ++mf) {
        const int r0 = row0 + wm*64 + mf*16 + (lane >> 2);
        #pragma unroll
        for (int nf = 0; nf < 4; ++nf) {
            const int cc = col0 + wn*32 + nf*8 + (lane & 3) * 2;
            float2 v0 = { acc[mf][nf][0] * scale, acc[mf][nf][1] * scale };
            float2 v1 = { acc[mf][nf][2] * scale, acc[mf][nf][3] * scale };
            *(float2*)(Cf + (size_t)r0 * ldC + cc)       = v0;
            *(float2*)(Cf + (size_t)(r0 + 8) * ldC + cc) = v1;
        }
    }
}

// ---- QKV split-K=3: grid (2 Ntiles, 64 Mtiles, 9 = weight*3 + ks) ----
// K splits (chunks of 64): ks=0 -> 43, ks=1 -> 43, ks=2 -> 42  (total 128 = 8192)
__global__ void __launch_bounds__(256, 2)
hmma_qkv_kernel()
{
    const int z = blockIdx.z;
    const int w = z / 3, ks = z % 3;
    const size_t koff = (size_t)ks * 2752;            // 43*64
    const int Kslice = (ks == 2) ? 2688 : 2752;       // 42*64 : 43*64
    const __half* Bg = g_wf + (size_t)w * D_ * V_ + koff;
    float* Cf = g_part + (size_t)z * ((size_t)M_*D_);
    hmma_gemm_body(g_xf + koff, Bg, Cf,
                   Kslice, V_, D_, 1.0f, blockIdx.y * 128, blockIdx.x * 128);
}

// ---- OUT: grid (64 Ntiles, 64 Mtiles) ----
__global__ void __launch_bounds__(256, 2)
hmma_out_kernel(const float* __restrict__ out_scale, float* __restrict__ out)
{
    hmma_gemm_body(g_rf, g_wof, out,
                   D_, D_, V_, out_scale[0], blockIdx.y * 128, blockIdx.x * 128);
}

// ================= HMMA attention (bf16 3-pass, K/V ring-prefetched) =================
#define AT_STRIDE 528
#define SW_STRIDE 144
#define SM_QH 0
#define SM_QL 33792
#define SM_KH 67584
#define SM_KL 101376
#define SM_VH 135168
#define SM_VL 168960
#define SM_SWH 202752
#define SM_SWL 211968
#define ATT_SMEM 221184

__global__ void __launch_bounds__(256, 1)
attn_hmma_kernel(const float* __restrict__ dlp)
{
    extern __shared__ __align__(128) char shm[];
    const int tid = threadIdx.x, lane = tid & 31, wid = tid >> 5;
    const int wm = wid >> 1, wn = wid & 1;
    const int ib = blockIdx.x, b = blockIdx.y;
    const uint32_t sb = smem_u32(shm);

    const float logit = dlp[0];
    const float decay = 1.f / (1.f + expf(-logit));
    const float l2d   = log2f(decay);

    const int qrow0 = b * T_ + ib * 64;

    // ---- loop extent ----
    int nblk = 1;
    while (ib + nblk < T_/64) {
        int emin = nblk * 64 - 64;
        if (emin > 0 && l2d * (float)emin < -13.f) break;
        ++nblk;
    }
    const int jb_end = ib + nblk;

    auto load_k = [&](int jb){
        const int krow0 = b * T_ + jb * 64;
        #pragma unroll
        for (int it = 0; it < 8; ++it) {
            int idx = it * 256 + tid;
            int r = idx >> 5, s = idx & 31;
            uint32_t soff = r * AT_STRIDE + s * 16;
            size_t gb = ((size_t)(krow0 + r) * D_) * 2 + s * 16;
            CP16(sb + SM_KH + soff, (const char*)g_kbh + gb);
            CP16(sb + SM_KL + soff, (const char*)g_kbl + gb);
        }
    };
    auto load_v = [&](int jb){
        const int krow0 = b * T_ + jb * 64;
        #pragma unroll
        for (int it = 0; it < 8; ++it) {
            int idx = it * 256 + tid;
            int r = idx >> 5, s = idx & 31;
            uint32_t soff = r * AT_STRIDE + s * 16;
            size_t gb = ((size_t)(krow0 + r) * D_) * 2 + s * 16;
            CP16(sb + SM_VH + soff, (const char*)g_vbh + gb);
            CP16(sb + SM_VL + soff, (const char*)g_vbl + gb);
        }
    };

    // ---- prologue: Q, K(ib), V(ib) ----
    #pragma unroll
    for (int it = 0; it < 8; ++it) {
        int idx = it * 256 + tid;
        int r = idx >> 5, s = idx & 31;
        uint32_t soff = r * AT_STRIDE + s * 16;
        size_t gb = ((size_t)(qrow0 + r) * D_) * 2 + s * 16;
        CP16(sb + SM_QH + soff, (const char*)g_qbh + gb);
        CP16(sb + SM_QL + soff, (const char*)g_qbl + gb);
    }
    CP_COMMIT();
    load_k(ib); CP_COMMIT();
    load_v(ib); CP_COMMIT();

    float oacc[8][2][4];
    #pragma unroll
    for (int a = 0; a < 8; ++a)
        #pragma unroll
        for (int g = 0; g < 2; ++g)
            #pragma unroll
            for (int e = 0; e < 4; ++e) oacc[a][g][e] = 0.f;

    const uint32_t offA  = (lane & 15) * AT_STRIDE + (lane >> 4) * 16;
    const uint32_t offB  = ((lane & 7) + ((lane >> 4) & 1) * 8) * AT_STRIDE
                         + ((lane >> 3) & 1) * 16;
    const uint32_t offAs = (lane & 15) * SW_STRIDE + (lane >> 4) * 16;
    const uint32_t offV  = ((lane & 7) + ((lane >> 3) & 1) * 8) * AT_STRIDE
                         + (lane >> 4) * 16;

    const int rl0 = wm * 16 + (lane >> 2);
    const float er0 = exp2f(-l2d * (float)rl0);
    const float er1 = er0 * exp2f(-l2d * 8.f);

    CP_WAIT2();        // Q ready (K/V may be in flight)
    __syncthreads();

    for (int jb = ib; jb < jb_end; ++jb) {
        const bool pre = (jb + 1 < jb_end);

        CP_WAIT1();    // K(jb) ready (V(jb) in flight)
        __syncthreads();

        // ---- phase A: S = Q K^T, 3-pass bf16 ----
        float sacc[4][4];
        #pragma unroll
        for (int nf = 0; nf < 4; ++nf)
            #pragma unroll
            for (int e = 0; e < 4; ++e) sacc[nf][e] = 0.f;

        #pragma unroll 4
        for (int kf = 0; kf < 16; ++kf) {
            const uint32_t kb = kf * 32;
            uint32_t qh[4], ql[4], kh[2][4], kl[2][4];
            ldsm_x4(qh, sb + SM_QH + (wm*16) * AT_STRIDE + kb + offA);
            ldsm_x4(ql, sb + SM_QL + (wm*16) * AT_STRIDE + kb + offA);
            ldsm_x4(kh[0], sb + SM_KH + (wn*32)      * AT_STRIDE + kb + offB);
            ldsm_x4(kh[1], sb + SM_KH + (wn*32 + 16) * AT_STRIDE + kb + offB);
            ldsm_x4(kl[0], sb + SM_KL + (wn*32)      * AT_STRIDE + kb + offB);
            ldsm_x4(kl[1], sb + SM_KL + (wn*32 + 16) * AT_STRIDE + kb + offB);
            #pragma unroll
            for (int nf = 0; nf < 4; ++nf) {
                mma16816(sacc[nf], qh, kh[nf>>1][(nf&1)*2], kh[nf>>1][(nf&1)*2+1]);
                mma16816(sacc[nf], qh, kl[nf>>1][(nf&1)*2], kl[nf>>1][(nf&1)*2+1]);
                mma16816(sacc[nf], ql, kh[nf>>1][(nf&1)*2], kh[nf>>1][(nf&1)*2+1]);
            }
        }

        __syncthreads();                 // all warps done reading K(jb)
        if (pre) { load_k(jb + 1); CP_COMMIT(); }

        // ---- weight + split hi/lo into Sw staging ----
        const float wbase = exp2f(l2d * (float)((jb - ib) * 64 - 1));
        const bool diag = (jb == ib);
        #pragma unroll
        for (int nf = 0; nf < 4; ++nf) {
            const int cl = wn*32 + nf*8 + (lane & 3)*2;
            float ec0 = exp2f(l2d * (float)cl);
            float ec1 = ec0 * decay;
            float w00 = wbase*ec0*er0, w01 = wbase*ec1*er0;
            float w10 = wbase*ec0*er1, w11 = wbase*ec1*er1;
            if (diag) {
                if (cl     <= rl0)     w00 = 0.f;
                if (cl + 1 <= rl0)     w01 = 0.f;
                if (cl     <= rl0 + 8) w10 = 0.f;
                if (cl + 1 <= rl0 + 8) w11 = 0.f;
            }
            float v00 = sacc[nf][0]*w00, v01 = sacc[nf][1]*w01;
            float v10 = sacc[nf][2]*w10, v11 = sacc[nf][3]*w11;

            #pragma unroll
            for (int h = 0; h < 2; ++h) {
                float a = h ? v10 : v00, c = h ? v11 : v01;
                __nv_bfloat16 ha, hc;
                uint32_t ph = pack_hilo_b(a, c, ha, hc);
                float ra = a - __bfloat162float(ha), rc = c - __bfloat162float(hc);
                __nv_bfloat16 t0, t1;
                uint32_t pl = pack_hilo_b(ra, rc, t0, t1);
                uint32_t off = (rl0 + h*8) * SW_STRIDE + cl * 2;
                *(uint32_t*)(shm + SM_SWH + off) = ph;
                *(uint32_t*)(shm + SM_SWL + off) = pl;
            }
        }

        if (pre) CP_WAIT1();             // V(jb) ready (K(jb+1) in flight)
        else     CP_WAIT0();
        __syncthreads();                 // Sw visible; V ready

        // ---- phase B: out += Sw @ V ----
        uint32_t sh4[4][4], sl4[4][4];
        #pragma unroll
        for (int kf = 0; kf < 4; ++kf) {
            ldsm_x4(sh4[kf], sb + SM_SWH + (wm*16) * SW_STRIDE + kf*32 + offAs);
            ldsm_x4(sl4[kf], sb + SM_SWL + (wm*16) * SW_STRIDE + kf*32 + offAs);
        }
        #pragma unroll
        for (int nb = 0; nb < 8; ++nb) {
            const uint32_t d0b = (uint32_t)(wn*128 + nb*16) * 2;
            #pragma unroll
            for (int kf = 0; kf < 4; ++kf) {
                uint32_t vh[4], vl[4];
                const uint32_t va = sb + (kf*16) * AT_STRIDE + d0b + offV;
                ldsm_x4_t(vh, va + SM_VH);
                ldsm_x4_t(vl, va + SM_VL);
                mma16816(oacc[nb][0], sh4[kf], vh[0], vh[1]);
                mma16816(oacc[nb][1], sh4[kf], vh[2], vh[3]);
                mma16816(oacc[nb][0], sh4[kf], vl[0], vl[1]);
                mma16816(oacc[nb][1], sh4[kf], vl[2], vl[3]);
                mma16816(oacc[nb][0], sl4[kf], vh[0], vh[1]);
                mma16816(oacc[nb][1], sl4[kf], vh[2], vh[3]);
            }
        }
        __syncthreads();                 // all warps done reading V(jb) / Sw
        if (pre) { load_v(jb + 1); CP_COMMIT(); }
    }

    // ---- fused epilogue: write r as single fp16 ----
    const size_t rrow = (size_t)(qrow0 + wm*16 + (lane >> 2)) * D_;
    #pragma unroll
    for (int nb = 0; nb < 8; ++nb) {
        #pragma unroll
        for (int g = 0; g < 2; ++g) {
            const int c = wn*128 + nb*16 + g*8 + (lane & 3) * 2;
            #pragma unroll
            for (int h = 0; h < 2; ++h) {
                uint32_t ph = pack_h2(oacc[nb][g][h*2], oacc[nb][g][h*2+1]);
                *(uint32_t*)(g_rf + rrow + (size_t)h * 8 * D_ + c) = ph;
            }
        }
    }
}

// ================= launch =================
#define GEMM_SMEM (NSTAGE*GSTG)

extern "C" void kernel_launch(void* const* d_in, const int* in_sizes, int n_in,
                              void* d_out, int out_size)
{
    const float* x  = (const float*)d_in[0];
    const float* wq = (const float*)d_in[1];
    const float* wk = (const float*)d_in[2];
    const float* wv = (const float*)d_in[3];
    const float* wo = (const float*)d_in[4];
    const float* dl = (const float*)d_in[5];
    const float* os = (const float*)d_in[6];
    float* out = (float*)d_out;

    cudaFuncSetAttribute(hmma_qkv_kernel, cudaFuncAttributeMaxDynamicSharedMemorySize, GEMM_SMEM);
    cudaFuncSetAttribute(hmma_out_kernel, cudaFuncAttributeMaxDynamicSharedMemorySize, GEMM_SMEM);
    cudaFuncSetAttribute(attn_hmma_kernel, cudaFuncAttributeMaxDynamicSharedMemorySize, ATT_SMEM);

    cvt_all_kernel<<<XBLKS + 4*WBLKS, 256>>>(x, wq, wk, wv, wo);

    hmma_qkv_kernel<<<dim3(2, 64, 9), 256, GEMM_SMEM>>>();

    reduce_qkv_kernel<<<3*2048, 256>>>();

    attn_hmma_kernel<<<dim3(T_/64, B_), 256, ATT_SMEM>>>(dl);

    hmma_out_kernel<<<dim3(64, 64), 256, GEMM_SMEM>>>(os, out);
}